// round 3
// baseline (speedup 1.0000x reference)
#include <cuda_runtime.h>
#include <math.h>

// ---------------------------------------------------------------------------
// Problem constants
// ---------------------------------------------------------------------------
#define BB 8
#define SS 1024
#define DD 1024
#define HH 16
#define HD 64
#define DFF 4096
#define BH (BB*HH)          // 128
#define NREL 33             // 2*16+1

// ---------------------------------------------------------------------------
// Scratch
// ---------------------------------------------------------------------------
#define OFF_Q     0ull
#define OFF_K     8388608ull
#define OFF_V     16777216ull
#define OFF_QREL  25165824ull
#define OFF_P     29491200ull
#define OFF_ASUM  163708928ull
#define OFF_O     168034304ull
#define OFF_T1    176422912ull
#define OFF_X1    184811520ull
#define OFF_FFH   193200128ull
#define OFF_T2    226754560ull
#define SCRATCH_TOTAL 235143168ull

__device__ float g_scratch[SCRATCH_TOTAL];

// ---------------------------------------------------------------------------
// tf32 helpers
// ---------------------------------------------------------------------------
__device__ __forceinline__ unsigned f2tf(float f) {
    unsigned u;
    asm("cvt.rna.tf32.f32 %0, %1;" : "=r"(u) : "f"(f));
    return u;
}

__device__ __forceinline__ void mma8(float* c, const unsigned* a, const unsigned* b) {
    asm volatile(
        "mma.sync.aligned.m16n8k8.row.col.f32.tf32.tf32.f32 "
        "{%0,%1,%2,%3}, {%4,%5,%6,%7}, {%8,%9}, {%0,%1,%2,%3};"
        : "+f"(c[0]), "+f"(c[1]), "+f"(c[2]), "+f"(c[3])
        : "r"(a[0]), "r"(a[1]), "r"(a[2]), "r"(a[3]), "r"(b[0]), "r"(b[1]));
}

#define PADA 20
#define PADB 136
#define PADV 72

// ---------------------------------------------------------------------------
// Block reductions (256 threads)
// ---------------------------------------------------------------------------
__device__ __forceinline__ float blockReduceSum256(float v, float* sh) {
    #pragma unroll
    for (int o = 16; o; o >>= 1) v += __shfl_xor_sync(0xffffffffu, v, o);
    int warp = threadIdx.x >> 5, lane = threadIdx.x & 31;
    if (lane == 0) sh[warp] = v;
    __syncthreads();
    if (warp == 0) {
        v = (lane < 8) ? sh[lane] : 0.f;
        #pragma unroll
        for (int o = 4; o; o >>= 1) v += __shfl_xor_sync(0xffffffffu, v, o);
        if (lane == 0) sh[0] = v;
    }
    __syncthreads();
    float r = sh[0];
    __syncthreads();
    return r;
}

__device__ __forceinline__ float blockReduceMax256(float v, float* sh) {
    #pragma unroll
    for (int o = 16; o; o >>= 1) v = fmaxf(v, __shfl_xor_sync(0xffffffffu, v, o));
    int warp = threadIdx.x >> 5, lane = threadIdx.x & 31;
    if (lane == 0) sh[warp] = v;
    __syncthreads();
    if (warp == 0) {
        v = (lane < 8) ? sh[lane] : -INFINITY;
        #pragma unroll
        for (int o = 4; o; o >>= 1) v = fmaxf(v, __shfl_xor_sync(0xffffffffu, v, o));
        if (lane == 0) sh[0] = v;
    }
    __syncthreads();
    float r = sh[0];
    __syncthreads();
    return r;
}

// ---------------------------------------------------------------------------
// Pipelined tf32 GEMM: C[M,N] = A[M,K] @ B[K,N] (+bias, epilogue mode)
//   mode 0: +bias   1: relu   2: +bias+resid   3: head-scatter
// Block 128x128, K-step 16, double-buffered smem + register prefetch.
// ---------------------------------------------------------------------------
__global__ __launch_bounds__(256)
void gemm_tf32(const float* __restrict__ A, const float* __restrict__ B,
               const float* __restrict__ bias, const float* __restrict__ resid,
               float* __restrict__ C, int M, int N, int K, int mode)
{
    __shared__ unsigned As[2][128 * PADA];
    __shared__ unsigned Bs[2][16 * PADB];
    const int tid = threadIdx.x, lane = tid & 31, warp = tid >> 5;
    const int gid = lane >> 2, tig = lane & 3;
    const int m0 = blockIdx.y * 128, n0 = blockIdx.x * 128;
    const int wm = warp & 1, wn = warp >> 1;

    const int ra = tid >> 2, ca = (tid & 3) * 4;   // A rows (p: +64), cols
    const int rb = tid >> 5, cb = (tid & 31) * 4;  // B rows (p: +8),  cols

    float4 pa[2], pb[2];
    #pragma unroll
    for (int p = 0; p < 2; p++) {
        pa[p] = *(const float4*)(A + (size_t)(m0 + ra + p * 64) * K + ca);
        pb[p] = *(const float4*)(B + (size_t)(rb + p * 8) * N + n0 + cb);
    }
    #pragma unroll
    for (int p = 0; p < 2; p++) {
        unsigned* d = &As[0][(ra + p * 64) * PADA + ca];
        d[0] = f2tf(pa[p].x); d[1] = f2tf(pa[p].y); d[2] = f2tf(pa[p].z); d[3] = f2tf(pa[p].w);
        unsigned* e = &Bs[0][(rb + p * 8) * PADB + cb];
        e[0] = f2tf(pb[p].x); e[1] = f2tf(pb[p].y); e[2] = f2tf(pb[p].z); e[3] = f2tf(pb[p].w);
    }
    __syncthreads();

    float acc[4][4][4];
    #pragma unroll
    for (int i = 0; i < 4; i++)
        #pragma unroll
        for (int j = 0; j < 4; j++)
            #pragma unroll
            for (int t = 0; t < 4; t++) acc[i][j][t] = 0.f;

    int buf = 0;
    for (int k0 = 0; k0 < K; k0 += 16) {
        const bool nxt = (k0 + 16) < K;
        if (nxt) {
            #pragma unroll
            for (int p = 0; p < 2; p++) {
                pa[p] = *(const float4*)(A + (size_t)(m0 + ra + p * 64) * K + (k0 + 16) + ca);
                pb[p] = *(const float4*)(B + (size_t)(k0 + 16 + rb + p * 8) * N + n0 + cb);
            }
        }
        const unsigned* Ac = As[buf];
        const unsigned* Bc = Bs[buf];
        #pragma unroll
        for (int ks = 0; ks < 16; ks += 8) {
            unsigned af[4][4], bf[4][2];
            #pragma unroll
            for (int mt = 0; mt < 4; mt++) {
                int mrow = (wm * 64 + mt * 16 + gid) * PADA;
                af[mt][0] = Ac[mrow + ks + tig];
                af[mt][1] = Ac[mrow + 8 * PADA + ks + tig];
                af[mt][2] = Ac[mrow + ks + tig + 4];
                af[mt][3] = Ac[mrow + 8 * PADA + ks + tig + 4];
            }
            #pragma unroll
            for (int nt = 0; nt < 4; nt++) {
                int nc = wn * 32 + nt * 8 + gid;
                bf[nt][0] = Bc[(ks + tig) * PADB + nc];
                bf[nt][1] = Bc[(ks + tig + 4) * PADB + nc];
            }
            #pragma unroll
            for (int mt = 0; mt < 4; mt++)
                #pragma unroll
                for (int nt = 0; nt < 4; nt++)
                    mma8(acc[mt][nt], af[mt], bf[nt]);
        }
        if (nxt) {
            #pragma unroll
            for (int p = 0; p < 2; p++) {
                unsigned* d = &As[buf ^ 1][(ra + p * 64) * PADA + ca];
                d[0] = f2tf(pa[p].x); d[1] = f2tf(pa[p].y); d[2] = f2tf(pa[p].z); d[3] = f2tf(pa[p].w);
                unsigned* e = &Bs[buf ^ 1][(rb + p * 8) * PADB + cb];
                e[0] = f2tf(pb[p].x); e[1] = f2tf(pb[p].y); e[2] = f2tf(pb[p].z); e[3] = f2tf(pb[p].w);
            }
        }
        __syncthreads();
        buf ^= 1;
    }

    #pragma unroll
    for (int mt = 0; mt < 4; mt++) {
        #pragma unroll
        for (int nt = 0; nt < 4; nt++) {
            int n_ = n0 + wn * 32 + nt * 8 + 2 * tig;
            #pragma unroll
            for (int h = 0; h < 2; h++) {
                int m = m0 + wm * 64 + mt * 16 + gid + h * 8;
                float v0 = acc[mt][nt][h * 2 + 0] + bias[n_];
                float v1 = acc[mt][nt][h * 2 + 1] + bias[n_ + 1];
                if (mode == 1) { v0 = fmaxf(v0, 0.f); v1 = fmaxf(v1, 0.f); }
                if (mode == 2) {
                    v0 += resid[(size_t)m * N + n_];
                    v1 += resid[(size_t)m * N + n_ + 1];
                }
                if (mode == 3) {
                    int b_ = m >> 10, s_ = m & 1023;
                    int h0 = n_ >> 6, hd0 = n_ & 63;
                    C[(((size_t)(b_ * 16 + h0) * 1024 + s_) << 6) + hd0] = v0;
                    int h1 = (n_ + 1) >> 6, hd1 = (n_ + 1) & 63;
                    C[(((size_t)(b_ * 16 + h1) * 1024 + s_) << 6) + hd1] = v1;
                } else {
                    *(float2*)(C + (size_t)m * N + n_) = make_float2(v0, v1);
                }
            }
        }
    }
}

// ---------------------------------------------------------------------------
// qrel[b,h,q,r] = Q[b,h,q,:] . rel_k[r,:]  (tiled, 64 rows/block)
// ---------------------------------------------------------------------------
__global__ __launch_bounds__(256)
void qrel_kernel(const float* __restrict__ Q, const float* __restrict__ relk,
                 float* __restrict__ out)
{
    __shared__ float rk[NREL * 65];
    __shared__ float qs[64 * 65];
    const int tid = threadIdx.x;
    const int row0 = blockIdx.x * 64;

    for (int i = tid; i < NREL * HD; i += 256) {
        int r = i >> 6, d = i & 63;
        rk[r * 65 + d] = relk[i];
    }
    #pragma unroll
    for (int p = 0; p < 4; p++) {
        int f = tid + p * 256;
        int r = f >> 4, c = f & 15;
        float4 v = *(const float4*)(Q + (size_t)(row0 + r) * HD + c * 4);
        float* d = &qs[r * 65 + c * 4];
        d[0] = v.x; d[1] = v.y; d[2] = v.z; d[3] = v.w;
    }
    __syncthreads();

    for (int i = tid; i < 64 * NREL; i += 256) {
        int q = i / NREL, r = i - q * NREL;
        float s = 0.f;
        #pragma unroll
        for (int d = 0; d < HD; d++)
            s = fmaf(qs[q * 65 + d], rk[r * 65 + d], s);
        out[(size_t)(row0 + q) * NREL + r] = s;
    }
}

// ---------------------------------------------------------------------------
// scores: P[bh,q,k] = (Q.K^T + qrel gather) / 8  — pipelined tf32 mma
// ---------------------------------------------------------------------------
__global__ __launch_bounds__(256)
void scores_tf32(const float* __restrict__ Q, const float* __restrict__ Kh,
                 const float* __restrict__ qrel, float* __restrict__ P)
{
    __shared__ unsigned As[2][128 * PADA];
    __shared__ unsigned Bs[2][16 * PADB];
    const int tid = threadIdx.x, lane = tid & 31, warp = tid >> 5;
    const int gid = lane >> 2, tig = lane & 3;
    const int bh = blockIdx.z;
    const int q0 = blockIdx.y * 128, k0b = blockIdx.x * 128;
    const int wm = warp & 1, wn = warp >> 1;

    const float* Qb = Q + (size_t)bh * SS * HD;
    const float* Kb = Kh + (size_t)bh * SS * HD;

    const int ra = tid >> 2, ca = (tid & 3) * 4;

    float4 pa[2], pw[2];
    #pragma unroll
    for (int p = 0; p < 2; p++) {
        pa[p] = *(const float4*)(Qb + (size_t)(q0 + ra + p * 64) * HD + ca);
        pw[p] = *(const float4*)(Kb + (size_t)(k0b + ra + p * 64) * HD + ca);
    }
    #pragma unroll
    for (int p = 0; p < 2; p++) {
        int r = ra + p * 64;
        unsigned* d = &As[0][r * PADA + ca];
        d[0] = f2tf(pa[p].x); d[1] = f2tf(pa[p].y); d[2] = f2tf(pa[p].z); d[3] = f2tf(pa[p].w);
        Bs[0][(ca + 0) * PADB + r] = f2tf(pw[p].x);
        Bs[0][(ca + 1) * PADB + r] = f2tf(pw[p].y);
        Bs[0][(ca + 2) * PADB + r] = f2tf(pw[p].z);
        Bs[0][(ca + 3) * PADB + r] = f2tf(pw[p].w);
    }
    __syncthreads();

    float acc[4][4][4];
    #pragma unroll
    for (int i = 0; i < 4; i++)
        #pragma unroll
        for (int j = 0; j < 4; j++)
            #pragma unroll
            for (int t = 0; t < 4; t++) acc[i][j][t] = 0.f;

    int buf = 0;
    for (int kc = 0; kc < HD; kc += 16) {
        const bool nxt = (kc + 16) < HD;
        if (nxt) {
            #pragma unroll
            for (int p = 0; p < 2; p++) {
                pa[p] = *(const float4*)(Qb + (size_t)(q0 + ra + p * 64) * HD + kc + 16 + ca);
                pw[p] = *(const float4*)(Kb + (size_t)(k0b + ra + p * 64) * HD + kc + 16 + ca);
            }
        }
        const unsigned* Ac = As[buf];
        const unsigned* Bc = Bs[buf];
        #pragma unroll
        for (int ks = 0; ks < 16; ks += 8) {
            unsigned af[4][4], bf[4][2];
            #pragma unroll
            for (int mt = 0; mt < 4; mt++) {
                int mrow = (wm * 64 + mt * 16 + gid) * PADA;
                af[mt][0] = Ac[mrow + ks + tig];
                af[mt][1] = Ac[mrow + 8 * PADA + ks + tig];
                af[mt][2] = Ac[mrow + ks + tig + 4];
                af[mt][3] = Ac[mrow + 8 * PADA + ks + tig + 4];
            }
            #pragma unroll
            for (int nt = 0; nt < 4; nt++) {
                int nc = wn * 32 + nt * 8 + gid;
                bf[nt][0] = Bc[(ks + tig) * PADB + nc];
                bf[nt][1] = Bc[(ks + tig + 4) * PADB + nc];
            }
            #pragma unroll
            for (int mt = 0; mt < 4; mt++)
                #pragma unroll
                for (int nt = 0; nt < 4; nt++)
                    mma8(acc[mt][nt], af[mt], bf[nt]);
        }
        if (nxt) {
            #pragma unroll
            for (int p = 0; p < 2; p++) {
                int r = ra + p * 64;
                unsigned* d = &As[buf ^ 1][r * PADA + ca];
                d[0] = f2tf(pa[p].x); d[1] = f2tf(pa[p].y); d[2] = f2tf(pa[p].z); d[3] = f2tf(pa[p].w);
                Bs[buf ^ 1][(ca + 0) * PADB + r] = f2tf(pw[p].x);
                Bs[buf ^ 1][(ca + 1) * PADB + r] = f2tf(pw[p].y);
                Bs[buf ^ 1][(ca + 2) * PADB + r] = f2tf(pw[p].z);
                Bs[buf ^ 1][(ca + 3) * PADB + r] = f2tf(pw[p].w);
            }
        }
        __syncthreads();
        buf ^= 1;
    }

    // load qrel table into reused smem
    float* qr = (float*)&As[0][0];
    for (int i = tid; i < 128 * NREL; i += 256) {
        int r = i / NREL, c = i - r * NREL;
        qr[i] = qrel[((size_t)bh * SS + q0 + r) * NREL + c];
    }
    __syncthreads();

    float* Pb = P + (size_t)bh * SS * SS;
    #pragma unroll
    for (int mt = 0; mt < 4; mt++) {
        #pragma unroll
        for (int nt = 0; nt < 4; nt++) {
            int n_ = k0b + wn * 32 + nt * 8 + 2 * tig;
            #pragma unroll
            for (int h = 0; h < 2; h++) {
                int ql = wm * 64 + mt * 16 + gid + h * 8;
                int q = q0 + ql;
                int d0 = n_ - q;     d0 = d0 < -16 ? -16 : (d0 > 16 ? 16 : d0);
                int d1 = n_ + 1 - q; d1 = d1 < -16 ? -16 : (d1 > 16 ? 16 : d1);
                float v0 = (acc[mt][nt][h * 2 + 0] + qr[ql * NREL + d0 + 16]) * 0.125f;
                float v1 = (acc[mt][nt][h * 2 + 1] + qr[ql * NREL + d1 + 16]) * 0.125f;
                *(float2*)(Pb + (size_t)q * SS + n_) = make_float2(v0, v1);
            }
        }
    }
}

// ---------------------------------------------------------------------------
// softmax over k + relative bucket sums asum[row, 0..32]
// ---------------------------------------------------------------------------
__global__ __launch_bounds__(256)
void softmax_kernel(float* __restrict__ P, float* __restrict__ asum)
{
    __shared__ float red[32];
    const int row = blockIdx.x;
    const int q = row & (SS - 1);
    const int tid = threadIdx.x;
    float* p = P + (size_t)row * SS;

    if (tid < NREL) asum[(size_t)row * NREL + tid] = 0.f;

    float4 v = *(const float4*)(p + tid * 4);
    float mx = fmaxf(fmaxf(v.x, v.y), fmaxf(v.z, v.w));
    mx = blockReduceMax256(mx, red);

    float e0 = __expf(v.x - mx), e1 = __expf(v.y - mx);
    float e2 = __expf(v.z - mx), e3 = __expf(v.w - mx);
    float s = blockReduceSum256(e0 + e1 + e2 + e3, red);
    float inv = 1.f / s;
    float p0 = e0 * inv, p1 = e1 * inv, p2 = e2 * inv, p3 = e3 * inv;

    float4 o; o.x = p0; o.y = p1; o.z = p2; o.w = p3;
    *(float4*)(p + tid * 4) = o;

    float b0 = 0.f, b32 = 0.f;
    float pv[4] = {p0, p1, p2, p3};
    const int kbase = tid * 4;
    #pragma unroll
    for (int t = 0; t < 4; t++) {
        int k = kbase + t;
        int d = k - q;
        if (d <= -16)      b0  += pv[t];
        else if (d >= 16)  b32 += pv[t];
        else               asum[(size_t)row * NREL + d + 16] = pv[t];
    }
    b0  = blockReduceSum256(b0,  red);
    b32 = blockReduceSum256(b32, red);
    if (tid == 0) {
        asum[(size_t)row * NREL + 0]  = b0;
        asum[(size_t)row * NREL + 32] = b32;
    }
}

// ---------------------------------------------------------------------------
// attn@V (pipelined tf32 mma) + relative-V epilogue, writes [B,S,D]
// Block tile 128x64. 8 warps: 4(M) x 2(N).
// ---------------------------------------------------------------------------
__global__ __launch_bounds__(256)
void attnv_tf32(const float* __restrict__ P, const float* __restrict__ V,
                const float* __restrict__ asum, const float* __restrict__ relv,
                float* __restrict__ O)
{
    __shared__ unsigned As[2][128 * PADA];
    __shared__ unsigned Bs[2][16 * PADV];
    const int tid = threadIdx.x, lane = tid & 31, warp = tid >> 5;
    const int gid = lane >> 2, tig = lane & 3;
    const int bh = blockIdx.y, q0 = blockIdx.x * 128;
    const int wm = warp & 3, wn = warp >> 2;

    const float* Pb = P + (size_t)bh * SS * SS;
    const float* Vb = V + (size_t)bh * SS * HD;

    const int ra = tid >> 2, ca = (tid & 3) * 4;
    const int rv = tid >> 4, cv = (tid & 15) * 4;

    float4 pa[2], pv;
    #pragma unroll
    for (int p = 0; p < 2; p++)
        pa[p] = *(const float4*)(Pb + (size_t)(q0 + ra + p * 64) * SS + ca);
    pv = *(const float4*)(Vb + (size_t)rv * HD + cv);

    #pragma unroll
    for (int p = 0; p < 2; p++) {
        unsigned* d = &As[0][(ra + p * 64) * PADA + ca];
        d[0] = f2tf(pa[p].x); d[1] = f2tf(pa[p].y); d[2] = f2tf(pa[p].z); d[3] = f2tf(pa[p].w);
    }
    {
        unsigned* e = &Bs[0][rv * PADV + cv];
        e[0] = f2tf(pv.x); e[1] = f2tf(pv.y); e[2] = f2tf(pv.z); e[3] = f2tf(pv.w);
    }
    __syncthreads();

    float acc[2][4][4];
    #pragma unroll
    for (int i = 0; i < 2; i++)
        #pragma unroll
        for (int j = 0; j < 4; j++)
            #pragma unroll
            for (int t = 0; t < 4; t++) acc[i][j][t] = 0.f;

    int buf = 0;
    for (int k0 = 0; k0 < SS; k0 += 16) {
        const bool nxt = (k0 + 16) < SS;
        if (nxt) {
            #pragma unroll
            for (int p = 0; p < 2; p++)
                pa[p] = *(const float4*)(Pb + (size_t)(q0 + ra + p * 64) * SS + k0 + 16 + ca);
            pv = *(const float4*)(Vb + (size_t)(k0 + 16 + rv) * HD + cv);
        }
        const unsigned* Ac = As[buf];
        const unsigned* Bc = Bs[buf];
        #pragma unroll
        for (int ks = 0; ks < 16; ks += 8) {
            unsigned af[2][4], bf[4][2];
            #pragma unroll
            for (int mt = 0; mt < 2; mt++) {
                int mrow = (wm * 32 + mt * 16 + gid) * PADA;
                af[mt][0] = Ac[mrow + ks + tig];
                af[mt][1] = Ac[mrow + 8 * PADA + ks + tig];
                af[mt][2] = Ac[mrow + ks + tig + 4];
                af[mt][3] = Ac[mrow + 8 * PADA + ks + tig + 4];
            }
            #pragma unroll
            for (int nt = 0; nt < 4; nt++) {
                int nc = wn * 32 + nt * 8 + gid;
                bf[nt][0] = Bc[(ks + tig) * PADV + nc];
                bf[nt][1] = Bc[(ks + tig + 4) * PADV + nc];
            }
            #pragma unroll
            for (int mt = 0; mt < 2; mt++)
                #pragma unroll
                for (int nt = 0; nt < 4; nt++)
                    mma8(acc[mt][nt], af[mt], bf[nt]);
        }
        if (nxt) {
            #pragma unroll
            for (int p = 0; p < 2; p++) {
                unsigned* d = &As[buf ^ 1][(ra + p * 64) * PADA + ca];
                d[0] = f2tf(pa[p].x); d[1] = f2tf(pa[p].y); d[2] = f2tf(pa[p].z); d[3] = f2tf(pa[p].w);
            }
            unsigned* e = &Bs[buf ^ 1][rv * PADV + cv];
            e[0] = f2tf(pv.x); e[1] = f2tf(pv.y); e[2] = f2tf(pv.z); e[3] = f2tf(pv.w);
        }
        __syncthreads();
        buf ^= 1;
    }

    // relative-V epilogue: acc += asum[q,:] @ rel_v (smem reuse)
    float* Ss = (float*)&As[0][0];   // [128][33]
    float* Rs = (float*)&Bs[0][0];   // [33][65]
    for (int i = tid; i < 128 * NREL; i += 256) {
        int r = i / NREL, c = i - r * NREL;
        Ss[i] = asum[((size_t)bh * SS + q0 + r) * NREL + c];
    }
    for (int i = tid; i < NREL * HD; i += 256) {
        int r = i >> 6, c = i & 63;
        Rs[r * 65 + c] = relv[i];
    }
    __syncthreads();

    #pragma unroll 1
    for (int r = 0; r < NREL; r++) {
        float rvv[4][2];
        #pragma unroll
        for (int nt = 0; nt < 4; nt++) {
            int n = wn * 32 + nt * 8 + 2 * tig;
            rvv[nt][0] = Rs[r * 65 + n];
            rvv[nt][1] = Rs[r * 65 + n + 1];
        }
        #pragma unroll
        for (int mt = 0; mt < 2; mt++) {
            #pragma unroll
            for (int h = 0; h < 2; h++) {
                float sv = Ss[(wm * 32 + mt * 16 + gid + h * 8) * NREL + r];
                #pragma unroll
                for (int nt = 0; nt < 4; nt++) {
                    acc[mt][nt][h * 2 + 0] = fmaf(sv, rvv[nt][0], acc[mt][nt][h * 2 + 0]);
                    acc[mt][nt][h * 2 + 1] = fmaf(sv, rvv[nt][1], acc[mt][nt][h * 2 + 1]);
                }
            }
        }
    }

    const int b_ = bh >> 4, h_ = bh & 15;
    #pragma unroll
    for (int mt = 0; mt < 2; mt++) {
        #pragma unroll
        for (int nt = 0; nt < 4; nt++) {
            int n = wn * 32 + nt * 8 + 2 * tig;
            #pragma unroll
            for (int h = 0; h < 2; h++) {
                int q = q0 + wm * 32 + mt * 16 + gid + h * 8;
                *(float2*)(O + ((size_t)b_ * SS + q) * DD + h_ * HD + n) =
                    make_float2(acc[mt][nt][h * 2 + 0], acc[mt][nt][h * 2 + 1]);
            }
        }
    }
}

// ---------------------------------------------------------------------------
// LayerNorm over last dim
// ---------------------------------------------------------------------------
__global__ __launch_bounds__(256)
void ln_kernel(const float* __restrict__ X, const float* __restrict__ g,
               const float* __restrict__ bt, float* __restrict__ out)
{
    __shared__ float red[32];
    const int row = blockIdx.x;
    const int tid = threadIdx.x;
    const float* x = X + (size_t)row * DD;

    float4 v = *(const float4*)(x + tid * 4);
    float s  = v.x + v.y + v.z + v.w;
    float ss = v.x*v.x + v.y*v.y + v.z*v.z + v.w*v.w;
    s  = blockReduceSum256(s,  red);
    ss = blockReduceSum256(ss, red);
    const float mean = s * (1.f / DD);
    const float var  = ss * (1.f / DD) - mean * mean;
    const float rs   = rsqrtf(var + 1e-5f);

    float4 gg = *(const float4*)(g  + tid * 4);
    float4 bb = *(const float4*)(bt + tid * 4);
    float4 o;
    o.x = (v.x - mean) * rs * gg.x + bb.x;
    o.y = (v.y - mean) * rs * gg.y + bb.y;
    o.z = (v.z - mean) * rs * gg.z + bb.z;
    o.w = (v.w - mean) * rs * gg.w + bb.w;
    *(float4*)(out + (size_t)row * DD + tid * 4) = o;
}

// ---------------------------------------------------------------------------
// kernel_launch
// ---------------------------------------------------------------------------
extern "C" void kernel_launch(void* const* d_in, const int* in_sizes, int n_in,
                              void* d_out, int out_size)
{
    const float* x     = (const float*)d_in[0];
    const float* wq    = (const float*)d_in[2];
    const float* bq    = (const float*)d_in[3];
    const float* wk    = (const float*)d_in[4];
    const float* bk    = (const float*)d_in[5];
    const float* wv    = (const float*)d_in[6];
    const float* bv    = (const float*)d_in[7];
    const float* wo    = (const float*)d_in[8];
    const float* bo    = (const float*)d_in[9];
    const float* rel_k = (const float*)d_in[10];
    const float* rel_v = (const float*)d_in[11];
    const float* fc1_w = (const float*)d_in[12];
    const float* fc1_b = (const float*)d_in[13];
    const float* fc2_w = (const float*)d_in[14];
    const float* fc2_b = (const float*)d_in[15];
    const float* ln1_g = (const float*)d_in[16];
    const float* ln1_b = (const float*)d_in[17];
    const float* ln2_g = (const float*)d_in[18];
    const float* ln2_b = (const float*)d_in[19];

    float* scratch = nullptr;
    cudaGetSymbolAddress((void**)&scratch, g_scratch);
    float* Q    = scratch + OFF_Q;
    float* Kh   = scratch + OFF_K;
    float* V    = scratch + OFF_V;
    float* qrel = scratch + OFF_QREL;
    float* P    = scratch + OFF_P;
    float* as_  = scratch + OFF_ASUM;
    float* O    = scratch + OFF_O;
    float* t1   = scratch + OFF_T1;
    float* x1   = scratch + OFF_X1;
    float* ffh  = scratch + OFF_FFH;
    float* t2   = scratch + OFF_T2;

    const int M = BB * SS;                 // 8192

    dim3 gProj(DD / 128, M / 128);         // (8, 64)
    gemm_tf32<<<gProj, 256>>>(x, wq, bq, nullptr, Q,  M, DD, DD, 3);
    gemm_tf32<<<gProj, 256>>>(x, wk, bk, nullptr, Kh, M, DD, DD, 3);
    gemm_tf32<<<gProj, 256>>>(x, wv, bv, nullptr, V,  M, DD, DD, 3);

    qrel_kernel<<<BH * SS / 64, 256>>>(Q, rel_k, qrel);

    dim3 gSc(SS / 128, SS / 128, BH);      // (8, 8, 128)
    scores_tf32<<<gSc, 256>>>(Q, Kh, qrel, P);

    softmax_kernel<<<BH * SS, 256>>>(P, as_);

    dim3 gAV(SS / 128, BH);                // (8, 128)
    attnv_tf32<<<gAV, 256>>>(P, V, as_, rel_v, O);

    gemm_tf32<<<gProj, 256>>>(O, wo, bo, x, t1, M, DD, DD, 2);
    ln_kernel<<<M, 256>>>(t1, ln1_g, ln1_b, x1);

    dim3 gF1(DFF / 128, M / 128);          // (32, 64)
    gemm_tf32<<<gF1, 256>>>(x1, fc1_w, fc1_b, nullptr, ffh, M, DFF, DD, 1);

    gemm_tf32<<<gProj, 256>>>(ffh, fc2_w, fc2_b, x1, t2, M, DD, DFF, 2);
    ln_kernel<<<M, 256>>>(t2, ln2_g, ln2_b, (float*)d_out);
}

// round 4
// speedup vs baseline: 1.3491x; 1.3491x over previous
#include <cuda_runtime.h>
#include <math.h>

// ---------------------------------------------------------------------------
// Problem constants
// ---------------------------------------------------------------------------
#define BB 8
#define SS 1024
#define DD 1024
#define HH 16
#define HD 64
#define DFF 4096
#define BH (BB*HH)          // 128
#define NREL 33             // 2*16+1

// ---------------------------------------------------------------------------
// Scratch (floats)
// ---------------------------------------------------------------------------
#define OFF_Q     0ull
#define OFF_K     8388608ull
#define OFF_V     16777216ull
#define OFF_QREL  25165824ull
#define OFF_P     29491200ull
#define OFF_ASUM  163708928ull
#define OFF_O     168034304ull
#define OFF_T1    176422912ull
#define OFF_X1    184811520ull
#define OFF_FFH   193200128ull
#define OFF_T2    226754560ull
#define OFF_XT    235143168ull
#define OFF_X1T   243531776ull
#define OFF_WQT   251920384ull
#define OFF_WKT   252968960ull
#define OFF_WVT   254017536ull
#define OFF_WOT   255066112ull
#define OFF_F1T   256114688ull
#define OFF_F2T   260308992ull
#define SCRATCH_TOTAL 264503296ull

__device__ float g_scratch[SCRATCH_TOTAL];

// ---------------------------------------------------------------------------
// tf32 / cp.async helpers
// ---------------------------------------------------------------------------
__device__ __forceinline__ unsigned f2tf(float f) {
    unsigned u;
    asm("cvt.rna.tf32.f32 %0, %1;" : "=r"(u) : "f"(f));
    return u;
}

__device__ __forceinline__ void mma8(float* c, const unsigned* a, const unsigned* b) {
    asm volatile(
        "mma.sync.aligned.m16n8k8.row.col.f32.tf32.tf32.f32 "
        "{%0,%1,%2,%3}, {%4,%5,%6,%7}, {%8,%9}, {%0,%1,%2,%3};"
        : "+f"(c[0]), "+f"(c[1]), "+f"(c[2]), "+f"(c[3])
        : "r"(a[0]), "r"(a[1]), "r"(a[2]), "r"(a[3]), "r"(b[0]), "r"(b[1]));
}

__device__ __forceinline__ unsigned su32(const void* p) {
    return (unsigned)__cvta_generic_to_shared(p);
}
#define CP16(dst, src) \
    asm volatile("cp.async.cg.shared.global [%0], [%1], 16;" :: "r"(dst), "l"(src) : "memory")
#define CPCOMMIT() asm volatile("cp.async.commit_group;" ::: "memory")
#define CPWAIT(n)  asm volatile("cp.async.wait_group %0;" :: "n"(n) : "memory")

#define PADA 20
#define PADB 136
#define PADV 72

// ---------------------------------------------------------------------------
// Block reductions (256 threads)
// ---------------------------------------------------------------------------
__device__ __forceinline__ float blockReduceSum256(float v, float* sh) {
    #pragma unroll
    for (int o = 16; o; o >>= 1) v += __shfl_xor_sync(0xffffffffu, v, o);
    int warp = threadIdx.x >> 5, lane = threadIdx.x & 31;
    if (lane == 0) sh[warp] = v;
    __syncthreads();
    if (warp == 0) {
        v = (lane < 8) ? sh[lane] : 0.f;
        #pragma unroll
        for (int o = 4; o; o >>= 1) v += __shfl_xor_sync(0xffffffffu, v, o);
        if (lane == 0) sh[0] = v;
    }
    __syncthreads();
    float r = sh[0];
    __syncthreads();
    return r;
}

__device__ __forceinline__ float blockReduceMax256(float v, float* sh) {
    #pragma unroll
    for (int o = 16; o; o >>= 1) v = fmaxf(v, __shfl_xor_sync(0xffffffffu, v, o));
    int warp = threadIdx.x >> 5, lane = threadIdx.x & 31;
    if (lane == 0) sh[warp] = v;
    __syncthreads();
    if (warp == 0) {
        v = (lane < 8) ? sh[lane] : -INFINITY;
        #pragma unroll
        for (int o = 4; o; o >>= 1) v = fmaxf(v, __shfl_xor_sync(0xffffffffu, v, o));
        if (lane == 0) sh[0] = v;
    }
    __syncthreads();
    float r = sh[0];
    __syncthreads();
    return r;
}

// ---------------------------------------------------------------------------
// Elementwise tf32 conversion (store tf32 bit pattern as float)
// ---------------------------------------------------------------------------
__global__ __launch_bounds__(256)
void cvt_tf32_kernel(const float* __restrict__ in, float* __restrict__ out, int n)
{
    int i = (blockIdx.x * 256 + threadIdx.x) * 4;
    if (i < n) {
        float4 v = *(const float4*)(in + i);
        uint4 o;
        o.x = f2tf(v.x); o.y = f2tf(v.y); o.z = f2tf(v.z); o.w = f2tf(v.w);
        *(uint4*)(out + i) = o;
    }
}

// ---------------------------------------------------------------------------
// cp.async-pipelined tf32 GEMM. A,B are PRE-CONVERTED tf32 bits.
//   mode 1: relu, write tf32 bits   2: +bias+resid, write f32
//   3: head-scatter, write tf32 bits
// Block 128x128, K-step 16, 2-stage cp.async. 8 warps: 2(M) x 4(N).
// ---------------------------------------------------------------------------
__global__ __launch_bounds__(256)
void gemm_tf32(const float* __restrict__ A, const float* __restrict__ B,
               const float* __restrict__ bias, const float* __restrict__ resid,
               float* __restrict__ C, int M, int N, int K, int mode)
{
    __shared__ __align__(16) unsigned As[2][128 * PADA];
    __shared__ __align__(16) unsigned Bs[2][16 * PADB];
    const int tid = threadIdx.x, lane = tid & 31, warp = tid >> 5;
    const int gid = lane >> 2, tig = lane & 3;
    const int m0 = blockIdx.y * 128, n0 = blockIdx.x * 128;
    const int wm = warp & 1, wn = warp >> 1;

    const int rA = tid >> 2,  cA = (tid & 3) * 4;   // +64 for second chunk
    const int rB = tid >> 5,  cB = (tid & 31) * 4;  // +8 for second chunk

    #define G_ISSUE(bf, k0) do {                                               \
        unsigned da = su32(&As[bf][0]);                                         \
        CP16(da + (unsigned)((rA * PADA + cA) * 4),                             \
             A + (size_t)(m0 + rA) * K + (k0) + cA);                            \
        CP16(da + (unsigned)(((rA + 64) * PADA + cA) * 4),                      \
             A + (size_t)(m0 + rA + 64) * K + (k0) + cA);                       \
        unsigned db = su32(&Bs[bf][0]);                                         \
        CP16(db + (unsigned)((rB * PADB + cB) * 4),                             \
             B + (size_t)((k0) + rB) * N + n0 + cB);                            \
        CP16(db + (unsigned)(((rB + 8) * PADB + cB) * 4),                       \
             B + (size_t)((k0) + rB + 8) * N + n0 + cB);                        \
    } while (0)

    float acc[4][4][4];
    #pragma unroll
    for (int i = 0; i < 4; i++)
        #pragma unroll
        for (int j = 0; j < 4; j++)
            #pragma unroll
            for (int t = 0; t < 4; t++) acc[i][j][t] = 0.f;

    G_ISSUE(0, 0); CPCOMMIT();

    int buf = 0;
    for (int k0 = 0; k0 < K; k0 += 16) {
        if (k0 + 16 < K) { G_ISSUE(buf ^ 1, k0 + 16); CPCOMMIT(); CPWAIT(1); }
        else             { CPWAIT(0); }
        __syncthreads();
        const unsigned* Ac = As[buf];
        const unsigned* Bc = Bs[buf];
        #pragma unroll
        for (int ks = 0; ks < 16; ks += 8) {
            unsigned af[4][4], bf[4][2];
            #pragma unroll
            for (int mt = 0; mt < 4; mt++) {
                int mrow = (wm * 64 + mt * 16 + gid) * PADA;
                af[mt][0] = Ac[mrow + ks + tig];
                af[mt][1] = Ac[mrow + 8 * PADA + ks + tig];
                af[mt][2] = Ac[mrow + ks + tig + 4];
                af[mt][3] = Ac[mrow + 8 * PADA + ks + tig + 4];
            }
            #pragma unroll
            for (int nt = 0; nt < 4; nt++) {
                int nc = wn * 32 + nt * 8 + gid;
                bf[nt][0] = Bc[(ks + tig) * PADB + nc];
                bf[nt][1] = Bc[(ks + tig + 4) * PADB + nc];
            }
            #pragma unroll
            for (int mt = 0; mt < 4; mt++)
                #pragma unroll
                for (int nt = 0; nt < 4; nt++)
                    mma8(acc[mt][nt], af[mt], bf[nt]);
        }
        __syncthreads();
        buf ^= 1;
    }
    #undef G_ISSUE

    #pragma unroll
    for (int mt = 0; mt < 4; mt++) {
        #pragma unroll
        for (int nt = 0; nt < 4; nt++) {
            int n_ = n0 + wn * 32 + nt * 8 + 2 * tig;
            #pragma unroll
            for (int h = 0; h < 2; h++) {
                int m = m0 + wm * 64 + mt * 16 + gid + h * 8;
                float v0 = acc[mt][nt][h * 2 + 0] + bias[n_];
                float v1 = acc[mt][nt][h * 2 + 1] + bias[n_ + 1];
                if (mode == 1) {
                    v0 = __uint_as_float(f2tf(fmaxf(v0, 0.f)));
                    v1 = __uint_as_float(f2tf(fmaxf(v1, 0.f)));
                }
                if (mode == 2) {
                    v0 += resid[(size_t)m * N + n_];
                    v1 += resid[(size_t)m * N + n_ + 1];
                }
                if (mode == 3) {
                    int b_ = m >> 10, s_ = m & 1023;
                    int h0 = n_ >> 6, hd0 = n_ & 63;
                    C[(((size_t)(b_ * 16 + h0) * 1024 + s_) << 6) + hd0] = __uint_as_float(f2tf(v0));
                    int h1 = (n_ + 1) >> 6, hd1 = (n_ + 1) & 63;
                    C[(((size_t)(b_ * 16 + h1) * 1024 + s_) << 6) + hd1] = __uint_as_float(f2tf(v1));
                } else {
                    *(float2*)(C + (size_t)m * N + n_) = make_float2(v0, v1);
                }
            }
        }
    }
}

// ---------------------------------------------------------------------------
// qrel[b,h,q,r] = Q[b,h,q,:] . rel_k[r,:]  (tiled, 64 rows/block)
// ---------------------------------------------------------------------------
__global__ __launch_bounds__(256)
void qrel_kernel(const float* __restrict__ Q, const float* __restrict__ relk,
                 float* __restrict__ out)
{
    __shared__ float rk[NREL * 65];
    __shared__ float qs[64 * 65];
    const int tid = threadIdx.x;
    const int row0 = blockIdx.x * 64;

    for (int i = tid; i < NREL * HD; i += 256) {
        int r = i >> 6, d = i & 63;
        rk[r * 65 + d] = relk[i];
    }
    #pragma unroll
    for (int p = 0; p < 4; p++) {
        int f = tid + p * 256;
        int r = f >> 4, c = f & 15;
        float4 v = *(const float4*)(Q + (size_t)(row0 + r) * HD + c * 4);
        float* d = &qs[r * 65 + c * 4];
        d[0] = v.x; d[1] = v.y; d[2] = v.z; d[3] = v.w;
    }
    __syncthreads();

    for (int i = tid; i < 64 * NREL; i += 256) {
        int q = i / NREL, r = i - q * NREL;
        float s = 0.f;
        #pragma unroll
        for (int d = 0; d < HD; d++)
            s = fmaf(qs[q * 65 + d], rk[r * 65 + d], s);
        out[(size_t)(row0 + q) * NREL + r] = s;
    }
}

// ---------------------------------------------------------------------------
// scores: P[bh,q,k] = (Q.K^T + qrel gather) / 8
// Q,K pre-converted tf32 bits. Both tiles row-major [seq][hd], cp.async.
// ---------------------------------------------------------------------------
__global__ __launch_bounds__(256)
void scores_tf32(const float* __restrict__ Q, const float* __restrict__ Kh,
                 const float* __restrict__ qrel, float* __restrict__ P)
{
    __shared__ __align__(16) unsigned Qs[2][128 * PADA];
    __shared__ __align__(16) unsigned Ks[2][128 * PADA];
    const int tid = threadIdx.x, lane = tid & 31, warp = tid >> 5;
    const int gid = lane >> 2, tig = lane & 3;
    const int bh = blockIdx.z;
    const int q0 = blockIdx.y * 128, k0b = blockIdx.x * 128;
    const int wm = warp & 1, wn = warp >> 1;

    const float* Qb = Q + (size_t)bh * SS * HD;
    const float* Kb = Kh + (size_t)bh * SS * HD;

    const int rA = tid >> 2, cA = (tid & 3) * 4;

    #define S_ISSUE(bf, kc) do {                                                \
        unsigned dq = su32(&Qs[bf][0]);                                          \
        CP16(dq + (unsigned)((rA * PADA + cA) * 4),                              \
             Qb + (size_t)(q0 + rA) * HD + (kc) + cA);                           \
        CP16(dq + (unsigned)(((rA + 64) * PADA + cA) * 4),                       \
             Qb + (size_t)(q0 + rA + 64) * HD + (kc) + cA);                      \
        unsigned dk = su32(&Ks[bf][0]);                                          \
        CP16(dk + (unsigned)((rA * PADA + cA) * 4),                              \
             Kb + (size_t)(k0b + rA) * HD + (kc) + cA);                          \
        CP16(dk + (unsigned)(((rA + 64) * PADA + cA) * 4),                       \
             Kb + (size_t)(k0b + rA + 64) * HD + (kc) + cA);                     \
    } while (0)

    float acc[4][4][4];
    #pragma unroll
    for (int i = 0; i < 4; i++)
        #pragma unroll
        for (int j = 0; j < 4; j++)
            #pragma unroll
            for (int t = 0; t < 4; t++) acc[i][j][t] = 0.f;

    S_ISSUE(0, 0); CPCOMMIT();

    int buf = 0;
    for (int kc = 0; kc < HD; kc += 16) {
        if (kc + 16 < HD) { S_ISSUE(buf ^ 1, kc + 16); CPCOMMIT(); CPWAIT(1); }
        else              { CPWAIT(0); }
        __syncthreads();
        const unsigned* Ac = Qs[buf];
        const unsigned* Bc = Ks[buf];
        #pragma unroll
        for (int ks = 0; ks < 16; ks += 8) {
            unsigned af[4][4], bf[4][2];
            #pragma unroll
            for (int mt = 0; mt < 4; mt++) {
                int mrow = (wm * 64 + mt * 16 + gid) * PADA;
                af[mt][0] = Ac[mrow + ks + tig];
                af[mt][1] = Ac[mrow + 8 * PADA + ks + tig];
                af[mt][2] = Ac[mrow + ks + tig + 4];
                af[mt][3] = Ac[mrow + 8 * PADA + ks + tig + 4];
            }
            #pragma unroll
            for (int nt = 0; nt < 4; nt++) {
                int nrow = (wn * 32 + nt * 8 + gid) * PADA;
                bf[nt][0] = Bc[nrow + ks + tig];
                bf[nt][1] = Bc[nrow + ks + tig + 4];
            }
            #pragma unroll
            for (int mt = 0; mt < 4; mt++)
                #pragma unroll
                for (int nt = 0; nt < 4; nt++)
                    mma8(acc[mt][nt], af[mt], bf[nt]);
        }
        __syncthreads();
        buf ^= 1;
    }
    #undef S_ISSUE

    // qrel table into reused smem
    float* qr = (float*)&Qs[0][0];
    for (int i = tid; i < 128 * NREL; i += 256) {
        int r = i / NREL, c = i - r * NREL;
        qr[i] = qrel[((size_t)bh * SS + q0 + r) * NREL + c];
    }
    __syncthreads();

    float* Pb = P + (size_t)bh * SS * SS;
    #pragma unroll
    for (int mt = 0; mt < 4; mt++) {
        #pragma unroll
        for (int nt = 0; nt < 4; nt++) {
            int n_ = k0b + wn * 32 + nt * 8 + 2 * tig;
            #pragma unroll
            for (int h = 0; h < 2; h++) {
                int ql = wm * 64 + mt * 16 + gid + h * 8;
                int q = q0 + ql;
                int d0 = n_ - q;     d0 = d0 < -16 ? -16 : (d0 > 16 ? 16 : d0);
                int d1 = n_ + 1 - q; d1 = d1 < -16 ? -16 : (d1 > 16 ? 16 : d1);
                float v0 = (acc[mt][nt][h * 2 + 0] + qr[ql * NREL + d0 + 16]) * 0.125f;
                float v1 = (acc[mt][nt][h * 2 + 1] + qr[ql * NREL + d1 + 16]) * 0.125f;
                *(float2*)(Pb + (size_t)q * SS + n_) = make_float2(v0, v1);
            }
        }
    }
}

// ---------------------------------------------------------------------------
// softmax over k + bucket sums; writes P as tf32 bits
// ---------------------------------------------------------------------------
__global__ __launch_bounds__(256)
void softmax_kernel(float* __restrict__ P, float* __restrict__ asum)
{
    __shared__ float red[32];
    const int row = blockIdx.x;
    const int q = row & (SS - 1);
    const int tid = threadIdx.x;
    float* p = P + (size_t)row * SS;

    if (tid < NREL) asum[(size_t)row * NREL + tid] = 0.f;

    float4 v = *(const float4*)(p + tid * 4);
    float mx = fmaxf(fmaxf(v.x, v.y), fmaxf(v.z, v.w));
    mx = blockReduceMax256(mx, red);

    float e0 = __expf(v.x - mx), e1 = __expf(v.y - mx);
    float e2 = __expf(v.z - mx), e3 = __expf(v.w - mx);
    float s = blockReduceSum256(e0 + e1 + e2 + e3, red);
    float inv = 1.f / s;
    float p0 = e0 * inv, p1 = e1 * inv, p2 = e2 * inv, p3 = e3 * inv;

    uint4 o;
    o.x = f2tf(p0); o.y = f2tf(p1); o.z = f2tf(p2); o.w = f2tf(p3);
    *(uint4*)(p + tid * 4) = o;

    float b0 = 0.f, b32 = 0.f;
    float pv[4] = {p0, p1, p2, p3};
    const int kbase = tid * 4;
    #pragma unroll
    for (int t = 0; t < 4; t++) {
        int k = kbase + t;
        int d = k - q;
        if (d <= -16)      b0  += pv[t];
        else if (d >= 16)  b32 += pv[t];
        else               asum[(size_t)row * NREL + d + 16] = pv[t];
    }
    b0  = blockReduceSum256(b0,  red);
    b32 = blockReduceSum256(b32, red);
    if (tid == 0) {
        asum[(size_t)row * NREL + 0]  = b0;
        asum[(size_t)row * NREL + 32] = b32;
    }
}

// ---------------------------------------------------------------------------
// attn@V + relative-V epilogue; P,V pre-converted. Writes O as tf32 bits.
// Block 128x64, 8 warps: 4(M) x 2(N).
// ---------------------------------------------------------------------------
__global__ __launch_bounds__(256)
void attnv_tf32(const float* __restrict__ P, const float* __restrict__ V,
                const float* __restrict__ asum, const float* __restrict__ relv,
                float* __restrict__ O)
{
    __shared__ __align__(16) unsigned As[2][128 * PADA];
    __shared__ __align__(16) unsigned Bs[2][16 * PADV];
    const int tid = threadIdx.x, lane = tid & 31, warp = tid >> 5;
    const int gid = lane >> 2, tig = lane & 3;
    const int bh = blockIdx.y, q0 = blockIdx.x * 128;
    const int wm = warp & 3, wn = warp >> 2;

    const float* Pb = P + (size_t)bh * SS * SS;
    const float* Vb = V + (size_t)bh * SS * HD;

    const int rA = tid >> 2,  cA = (tid & 3) * 4;
    const int rV = tid >> 4,  cV = (tid & 15) * 4;

    #define AV_ISSUE(bf, k0) do {                                               \
        unsigned da = su32(&As[bf][0]);                                          \
        CP16(da + (unsigned)((rA * PADA + cA) * 4),                              \
             Pb + (size_t)(q0 + rA) * SS + (k0) + cA);                           \
        CP16(da + (unsigned)(((rA + 64) * PADA + cA) * 4),                       \
             Pb + (size_t)(q0 + rA + 64) * SS + (k0) + cA);                      \
        unsigned db = su32(&Bs[bf][0]);                                          \
        CP16(db + (unsigned)((rV * PADV + cV) * 4),                              \
             Vb + (size_t)((k0) + rV) * HD + cV);                                \
    } while (0)

    float acc[2][4][4];
    #pragma unroll
    for (int i = 0; i < 2; i++)
        #pragma unroll
        for (int j = 0; j < 4; j++)
            #pragma unroll
            for (int t = 0; t < 4; t++) acc[i][j][t] = 0.f;

    AV_ISSUE(0, 0); CPCOMMIT();

    int buf = 0;
    for (int k0 = 0; k0 < SS; k0 += 16) {
        if (k0 + 16 < SS) { AV_ISSUE(buf ^ 1, k0 + 16); CPCOMMIT(); CPWAIT(1); }
        else              { CPWAIT(0); }
        __syncthreads();
        const unsigned* Ac = As[buf];
        const unsigned* Bc = Bs[buf];
        #pragma unroll
        for (int ks = 0; ks < 16; ks += 8) {
            unsigned af[2][4], bf[4][2];
            #pragma unroll
            for (int mt = 0; mt < 2; mt++) {
                int mrow = (wm * 32 + mt * 16 + gid) * PADA;
                af[mt][0] = Ac[mrow + ks + tig];
                af[mt][1] = Ac[mrow + 8 * PADA + ks + tig];
                af[mt][2] = Ac[mrow + ks + tig + 4];
                af[mt][3] = Ac[mrow + 8 * PADA + ks + tig + 4];
            }
            #pragma unroll
            for (int nt = 0; nt < 4; nt++) {
                int nc = wn * 32 + nt * 8 + gid;
                bf[nt][0] = Bc[(ks + tig) * PADV + nc];
                bf[nt][1] = Bc[(ks + tig + 4) * PADV + nc];
            }
            #pragma unroll
            for (int mt = 0; mt < 2; mt++)
                #pragma unroll
                for (int nt = 0; nt < 4; nt++)
                    mma8(acc[mt][nt], af[mt], bf[nt]);
        }
        __syncthreads();
        buf ^= 1;
    }
    #undef AV_ISSUE

    // relative-V epilogue: acc += asum[q,:] @ rel_v (smem reuse)
    float* Ss = (float*)&As[0][0];   // [128][33]
    float* Rs = (float*)&Bs[0][0];   // [33][65]
    for (int i = tid; i < 128 * NREL; i += 256) {
        int r = i / NREL, c = i - r * NREL;
        Ss[i] = asum[((size_t)bh * SS + q0 + r) * NREL + c];
    }
    for (int i = tid; i < NREL * HD; i += 256) {
        int r = i >> 6, c = i & 63;
        Rs[r * 65 + c] = relv[i];
    }
    __syncthreads();

    #pragma unroll 1
    for (int r = 0; r < NREL; r++) {
        float rvv[4][2];
        #pragma unroll
        for (int nt = 0; nt < 4; nt++) {
            int n = wn * 32 + nt * 8 + 2 * tig;
            rvv[nt][0] = Rs[r * 65 + n];
            rvv[nt][1] = Rs[r * 65 + n + 1];
        }
        #pragma unroll
        for (int mt = 0; mt < 2; mt++) {
            #pragma unroll
            for (int h = 0; h < 2; h++) {
                float sv = Ss[(wm * 32 + mt * 16 + gid + h * 8) * NREL + r];
                #pragma unroll
                for (int nt = 0; nt < 4; nt++) {
                    acc[mt][nt][h * 2 + 0] = fmaf(sv, rvv[nt][0], acc[mt][nt][h * 2 + 0]);
                    acc[mt][nt][h * 2 + 1] = fmaf(sv, rvv[nt][1], acc[mt][nt][h * 2 + 1]);
                }
            }
        }
    }

    const int b_ = bh >> 4, h_ = bh & 15;
    #pragma unroll
    for (int mt = 0; mt < 2; mt++) {
        #pragma unroll
        for (int nt = 0; nt < 4; nt++) {
            int n = wn * 32 + nt * 8 + 2 * tig;
            #pragma unroll
            for (int h = 0; h < 2; h++) {
                int q = q0 + wm * 32 + mt * 16 + gid + h * 8;
                uint2 ob;
                ob.x = f2tf(acc[mt][nt][h * 2 + 0]);
                ob.y = f2tf(acc[mt][nt][h * 2 + 1]);
                *(uint2*)(O + ((size_t)b_ * SS + q) * DD + h_ * HD + n) = ob;
            }
        }
    }
}

// ---------------------------------------------------------------------------
// LayerNorm; optionally also writes tf32-converted copy
// ---------------------------------------------------------------------------
__global__ __launch_bounds__(256)
void ln_kernel(const float* __restrict__ X, const float* __restrict__ g,
               const float* __restrict__ bt, float* __restrict__ out,
               float* __restrict__ outt)
{
    __shared__ float red[32];
    const int row = blockIdx.x;
    const int tid = threadIdx.x;
    const float* x = X + (size_t)row * DD;

    float4 v = *(const float4*)(x + tid * 4);
    float s  = v.x + v.y + v.z + v.w;
    float ss = v.x*v.x + v.y*v.y + v.z*v.z + v.w*v.w;
    s  = blockReduceSum256(s,  red);
    ss = blockReduceSum256(ss, red);
    const float mean = s * (1.f / DD);
    const float var  = ss * (1.f / DD) - mean * mean;
    const float rs   = rsqrtf(var + 1e-5f);

    float4 gg = *(const float4*)(g  + tid * 4);
    float4 bb = *(const float4*)(bt + tid * 4);
    float4 o;
    o.x = (v.x - mean) * rs * gg.x + bb.x;
    o.y = (v.y - mean) * rs * gg.y + bb.y;
    o.z = (v.z - mean) * rs * gg.z + bb.z;
    o.w = (v.w - mean) * rs * gg.w + bb.w;
    *(float4*)(out + (size_t)row * DD + tid * 4) = o;
    if (outt) {
        uint4 ot;
        ot.x = f2tf(o.x); ot.y = f2tf(o.y); ot.z = f2tf(o.z); ot.w = f2tf(o.w);
        *(uint4*)(outt + (size_t)row * DD + tid * 4) = ot;
    }
}

// ---------------------------------------------------------------------------
// kernel_launch
// ---------------------------------------------------------------------------
extern "C" void kernel_launch(void* const* d_in, const int* in_sizes, int n_in,
                              void* d_out, int out_size)
{
    const float* x     = (const float*)d_in[0];
    const float* wq    = (const float*)d_in[2];
    const float* bq    = (const float*)d_in[3];
    const float* wk    = (const float*)d_in[4];
    const float* bk    = (const float*)d_in[5];
    const float* wv    = (const float*)d_in[6];
    const float* bv    = (const float*)d_in[7];
    const float* wo    = (const float*)d_in[8];
    const float* bo    = (const float*)d_in[9];
    const float* rel_k = (const float*)d_in[10];
    const float* rel_v = (const float*)d_in[11];
    const float* fc1_w = (const float*)d_in[12];
    const float* fc1_b = (const float*)d_in[13];
    const float* fc2_w = (const float*)d_in[14];
    const float* fc2_b = (const float*)d_in[15];
    const float* ln1_g = (const float*)d_in[16];
    const float* ln1_b = (const float*)d_in[17];
    const float* ln2_g = (const float*)d_in[18];
    const float* ln2_b = (const float*)d_in[19];

    float* scratch = nullptr;
    cudaGetSymbolAddress((void**)&scratch, g_scratch);
    float* Q    = scratch + OFF_Q;
    float* Kh   = scratch + OFF_K;
    float* V    = scratch + OFF_V;
    float* qrel = scratch + OFF_QREL;
    float* P    = scratch + OFF_P;
    float* as_  = scratch + OFF_ASUM;
    float* O    = scratch + OFF_O;
    float* t1   = scratch + OFF_T1;
    float* x1   = scratch + OFF_X1;
    float* ffh  = scratch + OFF_FFH;
    float* t2   = scratch + OFF_T2;
    float* xt   = scratch + OFF_XT;
    float* x1t  = scratch + OFF_X1T;
    float* wqt  = scratch + OFF_WQT;
    float* wkt  = scratch + OFF_WKT;
    float* wvt  = scratch + OFF_WVT;
    float* wot  = scratch + OFF_WOT;
    float* f1t  = scratch + OFF_F1T;
    float* f2t  = scratch + OFF_F2T;

    const int M = BB * SS;                 // 8192

    // Pre-convert GEMM operands to tf32 bits
    cvt_tf32_kernel<<<(M * DD / 4 + 255) / 256, 256>>>(x, xt, M * DD);
    cvt_tf32_kernel<<<(DD * DD / 4 + 255) / 256, 256>>>(wq, wqt, DD * DD);
    cvt_tf32_kernel<<<(DD * DD / 4 + 255) / 256, 256>>>(wk, wkt, DD * DD);
    cvt_tf32_kernel<<<(DD * DD / 4 + 255) / 256, 256>>>(wv, wvt, DD * DD);
    cvt_tf32_kernel<<<(DD * DD / 4 + 255) / 256, 256>>>(wo, wot, DD * DD);
    cvt_tf32_kernel<<<(DD * DFF / 4 + 255) / 256, 256>>>(fc1_w, f1t, DD * DFF);
    cvt_tf32_kernel<<<(DFF * DD / 4 + 255) / 256, 256>>>(fc2_w, f2t, DFF * DD);

    dim3 gProj(DD / 128, M / 128);         // (8, 64)
    gemm_tf32<<<gProj, 256>>>(xt, wqt, bq, nullptr, Q,  M, DD, DD, 3);
    gemm_tf32<<<gProj, 256>>>(xt, wkt, bk, nullptr, Kh, M, DD, DD, 3);
    gemm_tf32<<<gProj, 256>>>(xt, wvt, bv, nullptr, V,  M, DD, DD, 3);

    qrel_kernel<<<BH * SS / 64, 256>>>(Q, rel_k, qrel);

    dim3 gSc(SS / 128, SS / 128, BH);      // (8, 8, 128)
    scores_tf32<<<gSc, 256>>>(Q, Kh, qrel, P);

    softmax_kernel<<<BH * SS, 256>>>(P, as_);

    dim3 gAV(SS / 128, BH);                // (8, 128)
    attnv_tf32<<<gAV, 256>>>(P, V, as_, rel_v, O);

    gemm_tf32<<<gProj, 256>>>(O, wot, bo, x, t1, M, DD, DD, 2);
    ln_kernel<<<M, 256>>>(t1, ln1_g, ln1_b, x1, x1t);

    dim3 gF1(DFF / 128, M / 128);          // (32, 64)
    gemm_tf32<<<gF1, 256>>>(x1t, f1t, fc1_b, nullptr, ffh, M, DFF, DD, 1);

    gemm_tf32<<<gProj, 256>>>(ffh, f2t, fc2_b, x1, t2, M, DD, DFF, 2);
    ln_kernel<<<M, 256>>>(t2, ln2_g, ln2_b, (float*)d_out, nullptr);
}

// round 5
// speedup vs baseline: 1.5682x; 1.1624x over previous
#include <cuda_runtime.h>
#include <math.h>

// ---------------------------------------------------------------------------
// Problem constants
// ---------------------------------------------------------------------------
#define BB 8
#define SS 1024
#define DD 1024
#define HH 16
#define HD 64
#define DFF 4096
#define BH (BB*HH)          // 128
#define NREL 33             // 2*16+1

// ---------------------------------------------------------------------------
// Scratch (floats)
// ---------------------------------------------------------------------------
#define OFF_Q     0ull
#define OFF_K     8388608ull
#define OFF_V     16777216ull
#define OFF_QREL  25165824ull
#define OFF_O     29491200ull
#define OFF_T1    37879808ull
#define OFF_X1    46268416ull
#define OFF_FFH   54657024ull
#define OFF_T2    88211456ull
#define OFF_XT    96600064ull
#define OFF_X1T   104988672ull
#define OFF_WQT   113377280ull
#define OFF_WKT   114425856ull
#define OFF_WVT   115474432ull
#define OFF_WOT   116523008ull
#define OFF_F1T   117571584ull
#define OFF_F2T   121765888ull
#define SCRATCH_TOTAL 125960192ull

__device__ float g_scratch[SCRATCH_TOTAL];

// ---------------------------------------------------------------------------
// tf32 / cp.async helpers
// ---------------------------------------------------------------------------
__device__ __forceinline__ unsigned f2tf(float f) {
    unsigned u;
    asm("cvt.rna.tf32.f32 %0, %1;" : "=r"(u) : "f"(f));
    return u;
}

__device__ __forceinline__ void mma8(float* c, const unsigned* a, const unsigned* b) {
    asm volatile(
        "mma.sync.aligned.m16n8k8.row.col.f32.tf32.tf32.f32 "
        "{%0,%1,%2,%3}, {%4,%5,%6,%7}, {%8,%9}, {%0,%1,%2,%3};"
        : "+f"(c[0]), "+f"(c[1]), "+f"(c[2]), "+f"(c[3])
        : "r"(a[0]), "r"(a[1]), "r"(a[2]), "r"(a[3]), "r"(b[0]), "r"(b[1]));
}

__device__ __forceinline__ unsigned su32(const void* p) {
    return (unsigned)__cvta_generic_to_shared(p);
}
#define CP16(dst, src) \
    asm volatile("cp.async.cg.shared.global [%0], [%1], 16;" :: "r"(dst), "l"(src) : "memory")
#define CPCOMMIT() asm volatile("cp.async.commit_group;" ::: "memory")
#define CPWAIT(n)  asm volatile("cp.async.wait_group %0;" :: "n"(n) : "memory")

#define PADA 20
#define PADB 136

// flash smem strides
#define QSTR 68
#define KSTR 68
#define VSTR 72
#define TKF  64

// ---------------------------------------------------------------------------
// Block reductions (256 threads)
// ---------------------------------------------------------------------------
__device__ __forceinline__ float blockReduceSum256(float v, float* sh) {
    #pragma unroll
    for (int o = 16; o; o >>= 1) v += __shfl_xor_sync(0xffffffffu, v, o);
    int warp = threadIdx.x >> 5, lane = threadIdx.x & 31;
    if (lane == 0) sh[warp] = v;
    __syncthreads();
    if (warp == 0) {
        v = (lane < 8) ? sh[lane] : 0.f;
        #pragma unroll
        for (int o = 4; o; o >>= 1) v += __shfl_xor_sync(0xffffffffu, v, o);
        if (lane == 0) sh[0] = v;
    }
    __syncthreads();
    float r = sh[0];
    __syncthreads();
    return r;
}

// ---------------------------------------------------------------------------
// Elementwise tf32 conversion
// ---------------------------------------------------------------------------
__global__ __launch_bounds__(256)
void cvt_tf32_kernel(const float* __restrict__ in, float* __restrict__ out, int n)
{
    int i = (blockIdx.x * 256 + threadIdx.x) * 4;
    if (i < n) {
        float4 v = *(const float4*)(in + i);
        uint4 o;
        o.x = f2tf(v.x); o.y = f2tf(v.y); o.z = f2tf(v.z); o.w = f2tf(v.w);
        *(uint4*)(out + i) = o;
    }
}

// ---------------------------------------------------------------------------
// cp.async-pipelined tf32 GEMM (unchanged from R4)
// ---------------------------------------------------------------------------
__global__ __launch_bounds__(256)
void gemm_tf32(const float* __restrict__ A, const float* __restrict__ B,
               const float* __restrict__ bias, const float* __restrict__ resid,
               float* __restrict__ C, int M, int N, int K, int mode)
{
    __shared__ __align__(16) unsigned As[2][128 * PADA];
    __shared__ __align__(16) unsigned Bs[2][16 * PADB];
    const int tid = threadIdx.x, lane = tid & 31, warp = tid >> 5;
    const int gid = lane >> 2, tig = lane & 3;
    const int m0 = blockIdx.y * 128, n0 = blockIdx.x * 128;
    const int wm = warp & 1, wn = warp >> 1;

    const int rA = tid >> 2,  cA = (tid & 3) * 4;
    const int rB = tid >> 5,  cB = (tid & 31) * 4;

    #define G_ISSUE(bf, k0) do {                                               \
        unsigned da = su32(&As[bf][0]);                                         \
        CP16(da + (unsigned)((rA * PADA + cA) * 4),                             \
             A + (size_t)(m0 + rA) * K + (k0) + cA);                            \
        CP16(da + (unsigned)(((rA + 64) * PADA + cA) * 4),                      \
             A + (size_t)(m0 + rA + 64) * K + (k0) + cA);                       \
        unsigned db = su32(&Bs[bf][0]);                                         \
        CP16(db + (unsigned)((rB * PADB + cB) * 4),                             \
             B + (size_t)((k0) + rB) * N + n0 + cB);                            \
        CP16(db + (unsigned)(((rB + 8) * PADB + cB) * 4),                       \
             B + (size_t)((k0) + rB + 8) * N + n0 + cB);                        \
    } while (0)

    float acc[4][4][4];
    #pragma unroll
    for (int i = 0; i < 4; i++)
        #pragma unroll
        for (int j = 0; j < 4; j++)
            #pragma unroll
            for (int t = 0; t < 4; t++) acc[i][j][t] = 0.f;

    G_ISSUE(0, 0); CPCOMMIT();

    int buf = 0;
    for (int k0 = 0; k0 < K; k0 += 16) {
        if (k0 + 16 < K) { G_ISSUE(buf ^ 1, k0 + 16); CPCOMMIT(); CPWAIT(1); }
        else             { CPWAIT(0); }
        __syncthreads();
        const unsigned* Ac = As[buf];
        const unsigned* Bc = Bs[buf];
        #pragma unroll
        for (int ks = 0; ks < 16; ks += 8) {
            unsigned af[4][4], bf[4][2];
            #pragma unroll
            for (int mt = 0; mt < 4; mt++) {
                int mrow = (wm * 64 + mt * 16 + gid) * PADA;
                af[mt][0] = Ac[mrow + ks + tig];
                af[mt][1] = Ac[mrow + 8 * PADA + ks + tig];
                af[mt][2] = Ac[mrow + ks + tig + 4];
                af[mt][3] = Ac[mrow + 8 * PADA + ks + tig + 4];
            }
            #pragma unroll
            for (int nt = 0; nt < 4; nt++) {
                int nc = wn * 32 + nt * 8 + gid;
                bf[nt][0] = Bc[(ks + tig) * PADB + nc];
                bf[nt][1] = Bc[(ks + tig + 4) * PADB + nc];
            }
            #pragma unroll
            for (int mt = 0; mt < 4; mt++)
                #pragma unroll
                for (int nt = 0; nt < 4; nt++)
                    mma8(acc[mt][nt], af[mt], bf[nt]);
        }
        __syncthreads();
        buf ^= 1;
    }
    #undef G_ISSUE

    #pragma unroll
    for (int mt = 0; mt < 4; mt++) {
        #pragma unroll
        for (int nt = 0; nt < 4; nt++) {
            int n_ = n0 + wn * 32 + nt * 8 + 2 * tig;
            #pragma unroll
            for (int h = 0; h < 2; h++) {
                int m = m0 + wm * 64 + mt * 16 + gid + h * 8;
                float v0 = acc[mt][nt][h * 2 + 0] + bias[n_];
                float v1 = acc[mt][nt][h * 2 + 1] + bias[n_ + 1];
                if (mode == 1) {
                    v0 = __uint_as_float(f2tf(fmaxf(v0, 0.f)));
                    v1 = __uint_as_float(f2tf(fmaxf(v1, 0.f)));
                }
                if (mode == 2) {
                    v0 += resid[(size_t)m * N + n_];
                    v1 += resid[(size_t)m * N + n_ + 1];
                }
                if (mode == 3) {
                    int b_ = m >> 10, s_ = m & 1023;
                    int h0 = n_ >> 6, hd0 = n_ & 63;
                    C[(((size_t)(b_ * 16 + h0) * 1024 + s_) << 6) + hd0] = __uint_as_float(f2tf(v0));
                    int h1 = (n_ + 1) >> 6, hd1 = (n_ + 1) & 63;
                    C[(((size_t)(b_ * 16 + h1) * 1024 + s_) << 6) + hd1] = __uint_as_float(f2tf(v1));
                } else {
                    *(float2*)(C + (size_t)m * N + n_) = make_float2(v0, v1);
                }
            }
        }
    }
}

// ---------------------------------------------------------------------------
// qrel[b,h,q,r] = Q[b,h,q,:] . rel_k[r,:]  (tiled, 64 rows/block)
// ---------------------------------------------------------------------------
__global__ __launch_bounds__(256)
void qrel_kernel(const float* __restrict__ Q, const float* __restrict__ relk,
                 float* __restrict__ out)
{
    __shared__ float rk[NREL * 65];
    __shared__ float qs[64 * 65];
    const int tid = threadIdx.x;
    const int row0 = blockIdx.x * 64;

    for (int i = tid; i < NREL * HD; i += 256) {
        int r = i >> 6, d = i & 63;
        rk[r * 65 + d] = relk[i];
    }
    #pragma unroll
    for (int p = 0; p < 4; p++) {
        int f = tid + p * 256;
        int r = f >> 4, c = f & 15;
        float4 v = *(const float4*)(Q + (size_t)(row0 + r) * HD + c * 4);
        float* d = &qs[r * 65 + c * 4];
        d[0] = v.x; d[1] = v.y; d[2] = v.z; d[3] = v.w;
    }
    __syncthreads();

    for (int i = tid; i < 64 * NREL; i += 256) {
        int q = i / NREL, r = i - q * NREL;
        float s = 0.f;
        #pragma unroll
        for (int d = 0; d < HD; d++)
            s = fmaf(qs[q * 65 + d], rk[r * 65 + d], s);
        out[(size_t)(row0 + q) * NREL + r] = s;
    }
}

// ---------------------------------------------------------------------------
// FUSED flash attention: scores (+qrel bias) -> online softmax -> P@V
// + online relative-V bucket accumulation. Q,K,V are tf32 bits.
// grid (SS/128, BH), 256 threads; warp w owns q-rows [16w, 16w+16).
// Writes O in [B,S,D] layout as tf32 bits.
// ---------------------------------------------------------------------------
__global__ __launch_bounds__(256, 2)
void flash_attn(const float* __restrict__ Q, const float* __restrict__ Kh,
                const float* __restrict__ V, const float* __restrict__ qrel,
                const float* __restrict__ relv, float* __restrict__ O)
{
    extern __shared__ __align__(16) unsigned fsm[];
    unsigned* Qs = fsm;                          // 128*68
    unsigned* Ks = Qs + 128 * QSTR;              // 64*68
    unsigned* Vs = Ks + TKF * KSTR;              // 64*72
    float* qr = (float*)(Vs + TKF * VSTR);       // 128*34
    float* bk = qr + 128 * 34;                   // 128*34

    const int tid = threadIdx.x, lane = tid & 31, warp = tid >> 5;
    const int gid = lane >> 2, tig = lane & 3;
    const int bh = blockIdx.y, q0 = blockIdx.x * 128;
    const float* Qb = Q  + (size_t)bh * SS * HD;
    const float* Kb = Kh + (size_t)bh * SS * HD;
    const float* Vb = V  + (size_t)bh * SS * HD;

    const int rl0 = warp * 16 + gid;        // local q row (and +8)
    const int qg0 = q0 + rl0;

    // --- load Q tile (cp.async) ---
    {
        int rq = tid >> 4, cq = (tid & 15) * 4;
        unsigned dq = su32(Qs);
        #pragma unroll
        for (int p = 0; p < 8; p++) {
            int r = rq + p * 16;
            CP16(dq + (unsigned)((r * QSTR + cq) * 4), Qb + (size_t)(q0 + r) * HD + cq);
        }
        CPCOMMIT();
    }
    // --- load qrel table, zero buckets ---
    for (int i = tid; i < 128 * NREL; i += 256) {
        int r = i / NREL, c = i - r * NREL;
        qr[r * 34 + c] = qrel[((size_t)bh * SS + q0 + r) * NREL + c];
    }
    for (int i = tid; i < 128 * 34; i += 256) bk[i] = 0.f;

    float oacc[8][4];
    #pragma unroll
    for (int i = 0; i < 8; i++)
        #pragma unroll
        for (int t = 0; t < 4; t++) oacc[i][t] = 0.f;
    float m0 = -1e30f, m1 = -1e30f, l0 = 0.f, l1 = 0.f;

    const int rk_ = tid >> 4, ck_ = (tid & 15) * 4;

    for (int kt = 0; kt < SS / TKF; kt++) {
        const int k0 = kt * TKF;
        // issue K,V tile
        {
            unsigned dk = su32(Ks), dv = su32(Vs);
            #pragma unroll
            for (int p = 0; p < 4; p++) {
                int r = rk_ + p * 16;
                CP16(dk + (unsigned)((r * KSTR + ck_) * 4), Kb + (size_t)(k0 + r) * HD + ck_);
                CP16(dv + (unsigned)((r * VSTR + ck_) * 4), Vb + (size_t)(k0 + r) * HD + ck_);
            }
            CPCOMMIT(); CPWAIT(0);
        }
        __syncthreads();

        // --- S = Q @ K^T (16x64 per warp) ---
        float sacc[8][4];
        #pragma unroll
        for (int i = 0; i < 8; i++)
            #pragma unroll
            for (int t = 0; t < 4; t++) sacc[i][t] = 0.f;

        #pragma unroll
        for (int ks = 0; ks < 8; ks++) {
            unsigned af[4];
            int arow = rl0 * QSTR + ks * 8 + tig;
            af[0] = Qs[arow];
            af[1] = Qs[arow + 8 * QSTR];
            af[2] = Qs[arow + 4];
            af[3] = Qs[arow + 4 + 8 * QSTR];
            #pragma unroll
            for (int nt = 0; nt < 8; nt++) {
                unsigned bf[2];
                int brow = (nt * 8 + gid) * KSTR + ks * 8 + tig;
                bf[0] = Ks[brow];
                bf[1] = Ks[brow + 4];
                mma8(sacc[nt], af, bf);
            }
        }

        // --- bias + scale, row max ---
        float mx0 = -1e30f, mx1 = -1e30f;
        #pragma unroll
        for (int nt = 0; nt < 8; nt++) {
            int kc = k0 + nt * 8 + 2 * tig;
            int d00 = kc - qg0;           d00 = d00 < -16 ? -16 : (d00 > 16 ? 16 : d00);
            int d01 = kc + 1 - qg0;       d01 = d01 < -16 ? -16 : (d01 > 16 ? 16 : d01);
            int d10 = kc - qg0 - 8;       d10 = d10 < -16 ? -16 : (d10 > 16 ? 16 : d10);
            int d11 = kc + 1 - qg0 - 8;   d11 = d11 < -16 ? -16 : (d11 > 16 ? 16 : d11);
            sacc[nt][0] = (sacc[nt][0] + qr[rl0 * 34 + d00 + 16]) * 0.125f;
            sacc[nt][1] = (sacc[nt][1] + qr[rl0 * 34 + d01 + 16]) * 0.125f;
            sacc[nt][2] = (sacc[nt][2] + qr[(rl0 + 8) * 34 + d10 + 16]) * 0.125f;
            sacc[nt][3] = (sacc[nt][3] + qr[(rl0 + 8) * 34 + d11 + 16]) * 0.125f;
            mx0 = fmaxf(mx0, fmaxf(sacc[nt][0], sacc[nt][1]));
            mx1 = fmaxf(mx1, fmaxf(sacc[nt][2], sacc[nt][3]));
        }
        mx0 = fmaxf(mx0, __shfl_xor_sync(0xffffffffu, mx0, 1));
        mx0 = fmaxf(mx0, __shfl_xor_sync(0xffffffffu, mx0, 2));
        mx1 = fmaxf(mx1, __shfl_xor_sync(0xffffffffu, mx1, 1));
        mx1 = fmaxf(mx1, __shfl_xor_sync(0xffffffffu, mx1, 2));

        float m0n = fmaxf(m0, mx0), m1n = fmaxf(m1, mx1);
        float corr0 = __expf(m0 - m0n), corr1 = __expf(m1 - m1n);
        m0 = m0n; m1 = m1n;

        // --- exponentials, rescale O, sums ---
        float sum0 = 0.f, sum1 = 0.f;
        #pragma unroll
        for (int nt = 0; nt < 8; nt++) {
            float p0 = __expf(sacc[nt][0] - m0);
            float p1 = __expf(sacc[nt][1] - m0);
            float p2 = __expf(sacc[nt][2] - m1);
            float p3 = __expf(sacc[nt][3] - m1);
            sacc[nt][0] = p0; sacc[nt][1] = p1; sacc[nt][2] = p2; sacc[nt][3] = p3;
            sum0 += p0 + p1; sum1 += p2 + p3;
            oacc[nt][0] *= corr0; oacc[nt][1] *= corr0;
            oacc[nt][2] *= corr1; oacc[nt][3] *= corr1;
        }
        sum0 += __shfl_xor_sync(0xffffffffu, sum0, 1);
        sum0 += __shfl_xor_sync(0xffffffffu, sum0, 2);
        sum1 += __shfl_xor_sync(0xffffffffu, sum1, 1);
        sum1 += __shfl_xor_sync(0xffffffffu, sum1, 2);
        l0 = l0 * corr0 + sum0;
        l1 = l1 * corr1 + sum1;

        // --- buckets: rescale then add ---
        {
            int st = tig * 9, en = st + 9 > NREL ? NREL : st + 9;
            float* b0p = &bk[rl0 * 34];
            float* b1p = &bk[(rl0 + 8) * 34];
            for (int d = st; d < en; d++) { b0p[d] *= corr0; b1p[d] *= corr1; }
        }
        __syncwarp();
        {
            float ba0r0 = 0.f, ba32r0 = 0.f, ba0r1 = 0.f, ba32r1 = 0.f;
            #pragma unroll
            for (int nt = 0; nt < 8; nt++) {
                int kc = k0 + nt * 8 + 2 * tig;
                int d0 = kc - qg0, d1 = kc + 1 - qg0;
                int e0 = kc - qg0 - 8, e1 = kc + 1 - qg0 - 8;
                if (d0 <= -16) ba0r0 += sacc[nt][0];
                else if (d0 >= 16) ba32r0 += sacc[nt][0];
                else bk[rl0 * 34 + d0 + 16] += sacc[nt][0];
                if (d1 <= -16) ba0r0 += sacc[nt][1];
                else if (d1 >= 16) ba32r0 += sacc[nt][1];
                else bk[rl0 * 34 + d1 + 16] += sacc[nt][1];
                if (e0 <= -16) ba0r1 += sacc[nt][2];
                else if (e0 >= 16) ba32r1 += sacc[nt][2];
                else bk[(rl0 + 8) * 34 + e0 + 16] += sacc[nt][2];
                if (e1 <= -16) ba0r1 += sacc[nt][3];
                else if (e1 >= 16) ba32r1 += sacc[nt][3];
                else bk[(rl0 + 8) * 34 + e1 + 16] += sacc[nt][3];
            }
            ba0r0  += __shfl_xor_sync(0xffffffffu, ba0r0, 1);
            ba0r0  += __shfl_xor_sync(0xffffffffu, ba0r0, 2);
            ba32r0 += __shfl_xor_sync(0xffffffffu, ba32r0, 1);
            ba32r0 += __shfl_xor_sync(0xffffffffu, ba32r0, 2);
            ba0r1  += __shfl_xor_sync(0xffffffffu, ba0r1, 1);
            ba0r1  += __shfl_xor_sync(0xffffffffu, ba0r1, 2);
            ba32r1 += __shfl_xor_sync(0xffffffffu, ba32r1, 1);
            ba32r1 += __shfl_xor_sync(0xffffffffu, ba32r1, 2);
            if (tig == 0) {
                bk[rl0 * 34 + 0]        += ba0r0;
                bk[rl0 * 34 + 32]       += ba32r0;
                bk[(rl0 + 8) * 34 + 0]  += ba0r1;
                bk[(rl0 + 8) * 34 + 32] += ba32r1;
            }
        }

        // --- P @ V: build A-frags via quad shuffles ---
        #pragma unroll
        for (int ks = 0; ks < 8; ks++) {
            const float* pf = sacc[ks];
            int s0 = (lane & 28) | (tig >> 1);
            int s1 = s0 + 2;
            float w00 = __shfl_sync(0xffffffffu, pf[0], s0);
            float w01 = __shfl_sync(0xffffffffu, pf[1], s0);
            float w20 = __shfl_sync(0xffffffffu, pf[2], s0);
            float w21 = __shfl_sync(0xffffffffu, pf[3], s0);
            float x00 = __shfl_sync(0xffffffffu, pf[0], s1);
            float x01 = __shfl_sync(0xffffffffu, pf[1], s1);
            float x20 = __shfl_sync(0xffffffffu, pf[2], s1);
            float x21 = __shfl_sync(0xffffffffu, pf[3], s1);
            bool odd = tig & 1;
            unsigned a[4];
            a[0] = f2tf(odd ? w01 : w00);
            a[1] = f2tf(odd ? w21 : w20);
            a[2] = f2tf(odd ? x01 : x00);
            a[3] = f2tf(odd ? x21 : x20);
            #pragma unroll
            for (int nt = 0; nt < 8; nt++) {
                unsigned bf[2];
                int vb = (ks * 8 + tig) * VSTR + nt * 8 + gid;
                bf[0] = Vs[vb];
                bf[1] = Vs[vb + 4 * VSTR];
                mma8(oacc[nt], a, bf);
            }
        }
        __syncthreads();
    }

    // --- epilogue: + buckets @ rel_v, normalize, write ---
    float* rv = (float*)Ks;   // reuse (33 x 64, stride 68)
    for (int i = tid; i < NREL * HD; i += 256) {
        int r = i >> 6, c = i & 63;
        rv[r * 68 + c] = relv[i];
    }
    __syncthreads();

    float inv0 = 1.f / l0, inv1 = 1.f / l1;

    #pragma unroll 1
    for (int r = 0; r < NREL; r++) {
        float br0 = bk[rl0 * 34 + r];
        float br1 = bk[(rl0 + 8) * 34 + r];
        #pragma unroll
        for (int nt = 0; nt < 8; nt++) {
            float r0 = rv[r * 68 + nt * 8 + 2 * tig];
            float r1 = rv[r * 68 + nt * 8 + 2 * tig + 1];
            oacc[nt][0] += br0 * r0; oacc[nt][1] += br0 * r1;
            oacc[nt][2] += br1 * r0; oacc[nt][3] += br1 * r1;
        }
    }

    const int b_ = bh >> 4, h_ = bh & 15;
    #pragma unroll
    for (int nt = 0; nt < 8; nt++) {
        int col = h_ * 64 + nt * 8 + 2 * tig;
        uint2 o0, o1;
        o0.x = f2tf(oacc[nt][0] * inv0); o0.y = f2tf(oacc[nt][1] * inv0);
        o1.x = f2tf(oacc[nt][2] * inv1); o1.y = f2tf(oacc[nt][3] * inv1);
        *(uint2*)(O + ((size_t)b_ * SS + q0 + rl0) * DD + col) = o0;
        *(uint2*)(O + ((size_t)b_ * SS + q0 + rl0 + 8) * DD + col) = o1;
    }
}

// ---------------------------------------------------------------------------
// LayerNorm; optionally also writes tf32-converted copy
// ---------------------------------------------------------------------------
__global__ __launch_bounds__(256)
void ln_kernel(const float* __restrict__ X, const float* __restrict__ g,
               const float* __restrict__ bt, float* __restrict__ out,
               float* __restrict__ outt)
{
    __shared__ float red[32];
    const int row = blockIdx.x;
    const int tid = threadIdx.x;
    const float* x = X + (size_t)row * DD;

    float4 v = *(const float4*)(x + tid * 4);
    float s  = v.x + v.y + v.z + v.w;
    float ss = v.x*v.x + v.y*v.y + v.z*v.z + v.w*v.w;
    s  = blockReduceSum256(s,  red);
    ss = blockReduceSum256(ss, red);
    const float mean = s * (1.f / DD);
    const float var  = ss * (1.f / DD) - mean * mean;
    const float rs   = rsqrtf(var + 1e-5f);

    float4 gg = *(const float4*)(g  + tid * 4);
    float4 bb = *(const float4*)(bt + tid * 4);
    float4 o;
    o.x = (v.x - mean) * rs * gg.x + bb.x;
    o.y = (v.y - mean) * rs * gg.y + bb.y;
    o.z = (v.z - mean) * rs * gg.z + bb.z;
    o.w = (v.w - mean) * rs * gg.w + bb.w;
    *(float4*)(out + (size_t)row * DD + tid * 4) = o;
    if (outt) {
        uint4 ot;
        ot.x = f2tf(o.x); ot.y = f2tf(o.y); ot.z = f2tf(o.z); ot.w = f2tf(o.w);
        *(uint4*)(outt + (size_t)row * DD + tid * 4) = ot;
    }
}

// ---------------------------------------------------------------------------
// kernel_launch
// ---------------------------------------------------------------------------
extern "C" void kernel_launch(void* const* d_in, const int* in_sizes, int n_in,
                              void* d_out, int out_size)
{
    const float* x     = (const float*)d_in[0];
    const float* wq    = (const float*)d_in[2];
    const float* bq    = (const float*)d_in[3];
    const float* wk    = (const float*)d_in[4];
    const float* bk_   = (const float*)d_in[5];
    const float* wv    = (const float*)d_in[6];
    const float* bv    = (const float*)d_in[7];
    const float* wo    = (const float*)d_in[8];
    const float* bo    = (const float*)d_in[9];
    const float* rel_k = (const float*)d_in[10];
    const float* rel_v = (const float*)d_in[11];
    const float* fc1_w = (const float*)d_in[12];
    const float* fc1_b = (const float*)d_in[13];
    const float* fc2_w = (const float*)d_in[14];
    const float* fc2_b = (const float*)d_in[15];
    const float* ln1_g = (const float*)d_in[16];
    const float* ln1_b = (const float*)d_in[17];
    const float* ln2_g = (const float*)d_in[18];
    const float* ln2_b = (const float*)d_in[19];

    float* scratch = nullptr;
    cudaGetSymbolAddress((void**)&scratch, g_scratch);
    float* Q    = scratch + OFF_Q;
    float* Kh   = scratch + OFF_K;
    float* V    = scratch + OFF_V;
    float* qrel = scratch + OFF_QREL;
    float* O    = scratch + OFF_O;
    float* t1   = scratch + OFF_T1;
    float* x1   = scratch + OFF_X1;
    float* ffh  = scratch + OFF_FFH;
    float* t2   = scratch + OFF_T2;
    float* xt   = scratch + OFF_XT;
    float* x1t  = scratch + OFF_X1T;
    float* wqt  = scratch + OFF_WQT;
    float* wkt  = scratch + OFF_WKT;
    float* wvt  = scratch + OFF_WVT;
    float* wot  = scratch + OFF_WOT;
    float* f1t  = scratch + OFF_F1T;
    float* f2t  = scratch + OFF_F2T;

    const int M = BB * SS;                 // 8192
    const int FLASH_SMEM = (128 * QSTR + TKF * KSTR + TKF * VSTR + 128 * 34 + 128 * 34) * 4;

    cudaFuncSetAttribute(flash_attn, cudaFuncAttributeMaxDynamicSharedMemorySize, FLASH_SMEM);

    // Pre-convert GEMM operands to tf32 bits
    cvt_tf32_kernel<<<(M * DD / 4 + 255) / 256, 256>>>(x, xt, M * DD);
    cvt_tf32_kernel<<<(DD * DD / 4 + 255) / 256, 256>>>(wq, wqt, DD * DD);
    cvt_tf32_kernel<<<(DD * DD / 4 + 255) / 256, 256>>>(wk, wkt, DD * DD);
    cvt_tf32_kernel<<<(DD * DD / 4 + 255) / 256, 256>>>(wv, wvt, DD * DD);
    cvt_tf32_kernel<<<(DD * DD / 4 + 255) / 256, 256>>>(wo, wot, DD * DD);
    cvt_tf32_kernel<<<(DD * DFF / 4 + 255) / 256, 256>>>(fc1_w, f1t, DD * DFF);
    cvt_tf32_kernel<<<(DFF * DD / 4 + 255) / 256, 256>>>(fc2_w, f2t, DFF * DD);

    dim3 gProj(DD / 128, M / 128);         // (8, 64)
    gemm_tf32<<<gProj, 256>>>(xt, wqt, bq,  nullptr, Q,  M, DD, DD, 3);
    gemm_tf32<<<gProj, 256>>>(xt, wkt, bk_, nullptr, Kh, M, DD, DD, 3);
    gemm_tf32<<<gProj, 256>>>(xt, wvt, bv,  nullptr, V,  M, DD, DD, 3);

    qrel_kernel<<<BH * SS / 64, 256>>>(Q, rel_k, qrel);

    dim3 gFA(SS / 128, BH);                // (8, 128)
    flash_attn<<<gFA, 256, FLASH_SMEM>>>(Q, Kh, V, qrel, rel_v, O);

    gemm_tf32<<<gProj, 256>>>(O, wot, bo, x, t1, M, DD, DD, 2);
    ln_kernel<<<M, 256>>>(t1, ln1_g, ln1_b, x1, x1t);

    dim3 gF1(DFF / 128, M / 128);          // (32, 64)
    gemm_tf32<<<gF1, 256>>>(x1t, f1t, fc1_b, nullptr, ffh, M, DFF, DD, 1);

    gemm_tf32<<<gProj, 256>>>(ffh, f2t, fc2_b, x1, t2, M, DD, DFF, 2);
    ln_kernel<<<M, 256>>>(t2, ln2_g, ln2_b, (float*)d_out, nullptr);
}

// round 7
// speedup vs baseline: 2.4813x; 1.5823x over previous
#include <cuda_runtime.h>
#include <cuda_fp16.h>
#include <math.h>
#include <stdint.h>

// ---------------------------------------------------------------------------
// Problem constants
// ---------------------------------------------------------------------------
#define BB 8
#define SS 1024
#define DD 1024
#define HH 16
#define HD 64
#define DFF 4096
#define BH 128
#define NREL 33

// ---------------------------------------------------------------------------
// Scratch (float units; fp16 regions reinterpreted)
// ---------------------------------------------------------------------------
#define OFF_Q     0ull          // Q fp16 [bh][s][hd]   (uses 4.2M floats)
#define OFF_K     8388608ull    // K fp16 [bh][s][hd]
#define OFF_V     16777216ull   // V fp16 TRANSPOSED [bh][hd][s]
#define OFF_QREL  25165824ull   // fp32 [bh*s][33]
#define OFF_O     29491200ull   // O fp16 [b][s][d]
#define OFF_T1    37879808ull   // fp32
#define OFF_X1    46268416ull   // fp32
#define OFF_FFH   54657024ull   // ffh fp16 [M][DFF]
#define OFF_T2    88211456ull   // fp32
#define OFF_XT    96600064ull   // x fp16
#define OFF_X1T   104988672ull  // x1 fp16
#define OFF_WQT   113377280ull  // wqkv^T fp16 [3072][1024]
#define OFF_WOT   116523008ull  // wo^T fp16
#define OFF_F1T   117571584ull  // fc1^T fp16 [4096][1024]
#define OFF_F2T   121765888ull  // fc2^T fp16 [1024][4096]
#define SCRATCH_TOTAL 125960192ull

__device__ float g_scratch[SCRATCH_TOTAL];

// ---------------------------------------------------------------------------
// helpers
// ---------------------------------------------------------------------------
__device__ __forceinline__ unsigned f2h2(float a, float b) {
    __half2 h = __floats2half2_rn(a, b);
    return *(unsigned*)&h;
}

// D += A(16x16 row) * B(16x8 col), fp16 in, fp32 accum
__device__ __forceinline__ void mmaf16(float* c, const unsigned* a, const unsigned* b) {
    asm volatile(
        "mma.sync.aligned.m16n8k16.row.col.f32.f16.f16.f32 "
        "{%0,%1,%2,%3}, {%4,%5,%6,%7}, {%8,%9}, {%0,%1,%2,%3};"
        : "+f"(c[0]), "+f"(c[1]), "+f"(c[2]), "+f"(c[3])
        : "r"(a[0]), "r"(a[1]), "r"(a[2]), "r"(a[3]), "r"(b[0]), "r"(b[1]));
}

__device__ __forceinline__ unsigned su32(const void* p) {
    return (unsigned)__cvta_generic_to_shared(p);
}
#define CP16(dst, src) \
    asm volatile("cp.async.cg.shared.global [%0], [%1], 16;" :: "r"(dst), "l"(src) : "memory")
#define CPCOMMIT() asm volatile("cp.async.commit_group;" ::: "memory")
#define CPWAIT(n)  asm volatile("cp.async.wait_group %0;" :: "n"(n) : "memory")

#define PADP 20   // gemm pair stride
#define FSTR 36   // flash pair stride

// ---------------------------------------------------------------------------
// Block reductions
// ---------------------------------------------------------------------------
__device__ __forceinline__ float blockReduceSum256(float v, float* sh) {
    #pragma unroll
    for (int o = 16; o; o >>= 1) v += __shfl_xor_sync(0xffffffffu, v, o);
    int warp = threadIdx.x >> 5, lane = threadIdx.x & 31;
    if (lane == 0) sh[warp] = v;
    __syncthreads();
    if (warp == 0) {
        v = (lane < 8) ? sh[lane] : 0.f;
        #pragma unroll
        for (int o = 4; o; o >>= 1) v += __shfl_xor_sync(0xffffffffu, v, o);
        if (lane == 0) sh[0] = v;
    }
    __syncthreads();
    float r = sh[0];
    __syncthreads();
    return r;
}

// ---------------------------------------------------------------------------
// fp32 -> fp16 elementwise (8/thread)
// ---------------------------------------------------------------------------
__global__ __launch_bounds__(256)
void cvt_h_kernel(const float* __restrict__ in, __half* __restrict__ out, int n)
{
    int i = (blockIdx.x * 256 + threadIdx.x) * 8;
    if (i < n) {
        float4 a = *(const float4*)(in + i);
        float4 b = *(const float4*)(in + i + 4);
        uint4 o;
        o.x = f2h2(a.x, a.y); o.y = f2h2(a.z, a.w);
        o.z = f2h2(b.x, b.y); o.w = f2h2(b.z, b.w);
        *(uint4*)(out + i) = o;
    }
}

// ---------------------------------------------------------------------------
// Transpose + fp16: in [K,N] fp32 -> out [N,K] fp16
// ---------------------------------------------------------------------------
__global__ __launch_bounds__(256)
void cvt_t_kernel(const float* __restrict__ in, __half* __restrict__ out, int K, int N)
{
    __shared__ float t[32][33];
    const int lx = threadIdx.x & 31, ly = threadIdx.x >> 5;
    const int n = blockIdx.x * 32 + lx, k0 = blockIdx.y * 32;
    #pragma unroll
    for (int p = 0; p < 32; p += 8)
        t[ly + p][lx] = in[(size_t)(k0 + ly + p) * N + n];
    __syncthreads();
    const int k = k0 + lx, n2 = blockIdx.x * 32;
    #pragma unroll
    for (int p = 0; p < 32; p += 8)
        out[(size_t)(n2 + ly + p) * K + k] = __float2half(t[lx][ly + p]);
}

// ---------------------------------------------------------------------------
// fp16 tensor-core GEMM: C = A[M,K] @ Bt[N,K]^T  (both fp16 K-major)
//   mode 1: relu -> fp16          mode 2: +bias+resid -> fp32
//   mode 3: QKV scatter: Q,K fp16 [bh][s][hd]; V fp16 transposed [bh][hd][s]
// Block 128x128, K-tile 32 halves, double-buffered cp.async.
// 8 warps: 2(M) x 4(N), warp tile 64x32.
// ---------------------------------------------------------------------------
__global__ __launch_bounds__(256)
void gemm_f16(const __half* __restrict__ A, const __half* __restrict__ Bt,
              const float* __restrict__ b1, const float* __restrict__ b2,
              const float* __restrict__ b3, const float* __restrict__ resid,
              void* __restrict__ C, int M, int N, int K, int mode)
{
    __shared__ __align__(16) unsigned As[2][128 * PADP];
    __shared__ __align__(16) unsigned Bs[2][128 * PADP];
    const int tid = threadIdx.x, lane = tid & 31, warp = tid >> 5;
    const int gid = lane >> 2, tig = lane & 3;
    const int m0 = blockIdx.y * 128, n0 = blockIdx.x * 128;
    const int wm = warp & 1, wn = warp >> 1;

    #define G_ISSUE(bf, k0) do {                                                \
        unsigned da = su32(&As[bf][0]);                                          \
        unsigned db = su32(&Bs[bf][0]);                                          \
        _Pragma("unroll")                                                        \
        for (int p_ = 0; p_ < 2; p_++) {                                         \
            int f_ = tid + p_ * 256;                                             \
            int r_ = f_ >> 2, c_ = f_ & 3;                                       \
            CP16(da + (unsigned)((r_ * PADP + c_ * 4) * 4),                      \
                 A + (size_t)(m0 + r_) * K + (k0) + c_ * 8);                     \
            CP16(db + (unsigned)((r_ * PADP + c_ * 4) * 4),                      \
                 Bt + (size_t)(n0 + r_) * K + (k0) + c_ * 8);                    \
        }                                                                        \
        CPCOMMIT();                                                              \
    } while (0)

    float acc[4][4][4];
    #pragma unroll
    for (int i = 0; i < 4; i++)
        #pragma unroll
        for (int j = 0; j < 4; j++)
            #pragma unroll
            for (int t = 0; t < 4; t++) acc[i][j][t] = 0.f;

    G_ISSUE(0, 0);

    int buf = 0;
    for (int k0 = 0; k0 < K; k0 += 32) {
        if (k0 + 32 < K) { G_ISSUE(buf ^ 1, k0 + 32); CPWAIT(1); }
        else             { CPWAIT(0); }
        __syncthreads();
        const unsigned* Ac = As[buf];
        const unsigned* Bc = Bs[buf];
        #pragma unroll
        for (int ks = 0; ks < 2; ks++) {
            const int pb = ks * 8;
            unsigned af[4][4], bf[4][2];
            #pragma unroll
            for (int mt = 0; mt < 4; mt++) {
                int r = (wm * 64 + mt * 16 + gid) * PADP;
                af[mt][0] = Ac[r + pb + tig];
                af[mt][1] = Ac[r + 8 * PADP + pb + tig];
                af[mt][2] = Ac[r + pb + tig + 4];
                af[mt][3] = Ac[r + 8 * PADP + pb + tig + 4];
            }
            #pragma unroll
            for (int nt = 0; nt < 4; nt++) {
                int r = (wn * 32 + nt * 8 + gid) * PADP;
                bf[nt][0] = Bc[r + pb + tig];
                bf[nt][1] = Bc[r + pb + tig + 4];
            }
            #pragma unroll
            for (int mt = 0; mt < 4; mt++)
                #pragma unroll
                for (int nt = 0; nt < 4; nt++)
                    mmaf16(acc[mt][nt], af[mt], bf[nt]);
        }
        __syncthreads();
        buf ^= 1;
    }
    #undef G_ISSUE

    #pragma unroll
    for (int mt = 0; mt < 4; mt++) {
        #pragma unroll
        for (int nt = 0; nt < 4; nt++) {
            int n_ = n0 + wn * 32 + nt * 8 + 2 * tig;
            #pragma unroll
            for (int h = 0; h < 2; h++) {
                int m = m0 + wm * 64 + mt * 16 + gid + h * 8;
                float v0 = acc[mt][nt][h * 2 + 0];
                float v1 = acc[mt][nt][h * 2 + 1];
                if (mode == 3) {
                    int mat = n_ >> 10, dcol = n_ & 1023;
                    const float* bp = mat == 0 ? b1 : (mat == 1 ? b2 : b3);
                    v0 += bp[dcol]; v1 += bp[dcol + 1];
                    int b_ = m >> 10, s_ = m & 1023;
                    int h_ = dcol >> 6, hd = dcol & 63;
                    __half* Ch = (__half*)C;
                    if (mat < 2) {
                        __half* base = Ch + (size_t)mat * 16777216ull;
                        *(unsigned*)(base + ((((size_t)(b_ * 16 + h_)) << 10) + s_) * 64 + hd)
                            = f2h2(v0, v1);
                    } else {
                        __half* vb = Ch + 33554432ull;
                        size_t bhh = (size_t)(b_ * 16 + h_) * 64;
                        vb[(bhh + hd)     * 1024 + s_] = __float2half(v0);
                        vb[(bhh + hd + 1) * 1024 + s_] = __float2half(v1);
                    }
                } else if (mode == 1) {
                    v0 = fmaxf(v0 + b1[n_], 0.f);
                    v1 = fmaxf(v1 + b1[n_ + 1], 0.f);
                    *(unsigned*)((__half*)C + (size_t)m * N + n_) = f2h2(v0, v1);
                } else {
                    v0 += b1[n_]     + resid[(size_t)m * N + n_];
                    v1 += b1[n_ + 1] + resid[(size_t)m * N + n_ + 1];
                    *(float2*)((float*)C + (size_t)m * N + n_) = make_float2(v0, v1);
                }
            }
        }
    }
}

// ---------------------------------------------------------------------------
// qrel[bh,q,r] = Q[bh,q,:] . rel_k[r,:]   (Q fp16)
// ---------------------------------------------------------------------------
__global__ __launch_bounds__(256)
void qrel_kernel(const __half* __restrict__ Q, const float* __restrict__ relk,
                 float* __restrict__ out)
{
    __shared__ float rk[NREL * 65];
    __shared__ float qs[64 * 65];
    const int tid = threadIdx.x;
    const int row0 = blockIdx.x * 64;

    for (int i = tid; i < NREL * HD; i += 256) {
        int r = i >> 6, d = i & 63;
        rk[r * 65 + d] = relk[i];
    }
    #pragma unroll
    for (int p = 0; p < 8; p++) {
        int f = tid + p * 256;          // 2048 half2 pairs
        int r = f >> 5, c = f & 31;
        __half2 h = ((const __half2*)Q)[(size_t)(row0 + r) * 32 + c];
        float2 fv = __half22float2(h);
        qs[r * 65 + c * 2]     = fv.x;
        qs[r * 65 + c * 2 + 1] = fv.y;
    }
    __syncthreads();

    for (int i = tid; i < 64 * NREL; i += 256) {
        int q = i / NREL, r = i - q * NREL;
        float s = 0.f;
        #pragma unroll
        for (int d = 0; d < HD; d++)
            s = fmaf(qs[q * 65 + d], rk[r * 65 + d], s);
        out[(size_t)(row0 + q) * NREL + r] = s;
    }
}

// ---------------------------------------------------------------------------
// FUSED flash attention, fp16 mma. Q,K [bh][s][hd] fp16; V transposed
// [bh][hd][s] fp16. P@V A-frags come straight from S fragments (no shuffles).
// grid (SS/128, BH), 256 thr; warp owns 16 q-rows. O fp16 [b][s][d].
// ---------------------------------------------------------------------------
#define TKF 64

__global__ __launch_bounds__(256, 2)
void flash_attn(const __half* __restrict__ Q, const __half* __restrict__ Kh,
                const __half* __restrict__ Vt, const float* __restrict__ qrel,
                const float* __restrict__ relv, __half* __restrict__ O)
{
    extern __shared__ __align__(16) unsigned fsm[];
    unsigned* Qs = fsm;                          // 128*36 pairs
    unsigned* Ks = Qs + 128 * FSTR;              // 64*36
    unsigned* Vs = Ks + TKF * FSTR;              // 64*36 (rows = hd)
    float* qr = (float*)(Vs + TKF * FSTR);       // 128*34
    float* bk = qr + 128 * 34;                   // 128*34

    const int tid = threadIdx.x, lane = tid & 31, warp = tid >> 5;
    const int gid = lane >> 2, tig = lane & 3;
    const int bh = blockIdx.y, q0 = blockIdx.x * 128;
    const __half* Qb = Q  + (size_t)bh * SS * HD;
    const __half* Kb = Kh + (size_t)bh * SS * HD;
    const __half* Vb = Vt + (size_t)bh * HD * SS;

    const int rl0 = warp * 16 + gid;
    const int qg0 = q0 + rl0;

    // Q tile: 128 rows x 128B (8 chunks)
    {
        unsigned dq = su32(Qs);
        int r = tid >> 3, c = tid & 7;
        #pragma unroll
        for (int p = 0; p < 4; p++) {
            int rr = r + p * 32;
            CP16(dq + (unsigned)((rr * FSTR + c * 4) * 4), Qb + (size_t)(q0 + rr) * HD + c * 8);
        }
        CPCOMMIT();
    }
    for (int i = tid; i < 128 * NREL; i += 256) {
        int r = i / NREL, c = i - r * NREL;
        qr[r * 34 + c] = qrel[((size_t)bh * SS + q0 + r) * NREL + c];
    }
    for (int i = tid; i < 128 * 34; i += 256) bk[i] = 0.f;

    float oacc[8][4];
    #pragma unroll
    for (int i = 0; i < 8; i++)
        #pragma unroll
        for (int t = 0; t < 4; t++) oacc[i][t] = 0.f;
    float m0 = -1e30f, m1 = -1e30f, l0 = 0.f, l1 = 0.f;

    for (int kt = 0; kt < SS / TKF; kt++) {
        const int k0 = kt * TKF;
        {
            unsigned dk = su32(Ks), dv = su32(Vs);
            int r = tid >> 3, c = tid & 7;
            #pragma unroll
            for (int p = 0; p < 2; p++) {
                int rr = r + p * 32;
                CP16(dk + (unsigned)((rr * FSTR + c * 4) * 4), Kb + (size_t)(k0 + rr) * HD + c * 8);
                CP16(dv + (unsigned)((rr * FSTR + c * 4) * 4), Vb + (size_t)rr * SS + k0 + c * 8);
            }
            CPCOMMIT(); CPWAIT(0);
        }
        __syncthreads();

        // --- S = Q @ K^T (16x64 per warp), 4 k16-steps ---
        float sacc[8][4];
        #pragma unroll
        for (int i = 0; i < 8; i++)
            #pragma unroll
            for (int t = 0; t < 4; t++) sacc[i][t] = 0.f;

        #pragma unroll
        for (int ks = 0; ks < 4; ks++) {
            const int pb = ks * 8;
            unsigned af[4];
            af[0] = Qs[rl0 * FSTR + pb + tig];
            af[1] = Qs[(rl0 + 8) * FSTR + pb + tig];
            af[2] = Qs[rl0 * FSTR + pb + tig + 4];
            af[3] = Qs[(rl0 + 8) * FSTR + pb + tig + 4];
            #pragma unroll
            for (int nt = 0; nt < 8; nt++) {
                unsigned bf[2];
                int br = (nt * 8 + gid) * FSTR + pb;
                bf[0] = Ks[br + tig];
                bf[1] = Ks[br + tig + 4];
                mmaf16(sacc[nt], af, bf);
            }
        }

        // --- bias + scale + row max ---
        float mx0 = -1e30f, mx1 = -1e30f;
        #pragma unroll
        for (int nt = 0; nt < 8; nt++) {
            int kc = k0 + nt * 8 + 2 * tig;
            int d00 = kc - qg0;           d00 = d00 < -16 ? -16 : (d00 > 16 ? 16 : d00);
            int d01 = kc + 1 - qg0;       d01 = d01 < -16 ? -16 : (d01 > 16 ? 16 : d01);
            int d10 = kc - qg0 - 8;       d10 = d10 < -16 ? -16 : (d10 > 16 ? 16 : d10);
            int d11 = kc + 1 - qg0 - 8;   d11 = d11 < -16 ? -16 : (d11 > 16 ? 16 : d11);
            sacc[nt][0] = (sacc[nt][0] + qr[rl0 * 34 + d00 + 16]) * 0.125f;
            sacc[nt][1] = (sacc[nt][1] + qr[rl0 * 34 + d01 + 16]) * 0.125f;
            sacc[nt][2] = (sacc[nt][2] + qr[(rl0 + 8) * 34 + d10 + 16]) * 0.125f;
            sacc[nt][3] = (sacc[nt][3] + qr[(rl0 + 8) * 34 + d11 + 16]) * 0.125f;
            mx0 = fmaxf(mx0, fmaxf(sacc[nt][0], sacc[nt][1]));
            mx1 = fmaxf(mx1, fmaxf(sacc[nt][2], sacc[nt][3]));
        }
        mx0 = fmaxf(mx0, __shfl_xor_sync(0xffffffffu, mx0, 1));
        mx0 = fmaxf(mx0, __shfl_xor_sync(0xffffffffu, mx0, 2));
        mx1 = fmaxf(mx1, __shfl_xor_sync(0xffffffffu, mx1, 1));
        mx1 = fmaxf(mx1, __shfl_xor_sync(0xffffffffu, mx1, 2));

        float m0n = fmaxf(m0, mx0), m1n = fmaxf(m1, mx1);
        float corr0 = __expf(m0 - m0n), corr1 = __expf(m1 - m1n);
        m0 = m0n; m1 = m1n;

        float sum0 = 0.f, sum1 = 0.f;
        #pragma unroll
        for (int nt = 0; nt < 8; nt++) {
            float p0 = __expf(sacc[nt][0] - m0);
            float p1 = __expf(sacc[nt][1] - m0);
            float p2 = __expf(sacc[nt][2] - m1);
            float p3 = __expf(sacc[nt][3] - m1);
            sacc[nt][0] = p0; sacc[nt][1] = p1; sacc[nt][2] = p2; sacc[nt][3] = p3;
            sum0 += p0 + p1; sum1 += p2 + p3;
            oacc[nt][0] *= corr0; oacc[nt][1] *= corr0;
            oacc[nt][2] *= corr1; oacc[nt][3] *= corr1;
        }
        sum0 += __shfl_xor_sync(0xffffffffu, sum0, 1);
        sum0 += __shfl_xor_sync(0xffffffffu, sum0, 2);
        sum1 += __shfl_xor_sync(0xffffffffu, sum1, 1);
        sum1 += __shfl_xor_sync(0xffffffffu, sum1, 2);
        l0 = l0 * corr0 + sum0;
        l1 = l1 * corr1 + sum1;

        // --- buckets: rescale then add ---
        {
            int st = tig * 9, en = st + 9 > NREL ? NREL : st + 9;
            float* b0p = &bk[rl0 * 34];
            float* b1p = &bk[(rl0 + 8) * 34];
            for (int d = st; d < en; d++) { b0p[d] *= corr0; b1p[d] *= corr1; }
        }
        __syncwarp();
        {
            float ba0r0 = 0.f, ba32r0 = 0.f, ba0r1 = 0.f, ba32r1 = 0.f;
            #pragma unroll
            for (int nt = 0; nt < 8; nt++) {
                int kc = k0 + nt * 8 + 2 * tig;
                int d0 = kc - qg0, d1 = kc + 1 - qg0;
                int e0 = kc - qg0 - 8, e1 = kc + 1 - qg0 - 8;
                if (d0 <= -16) ba0r0 += sacc[nt][0];
                else if (d0 >= 16) ba32r0 += sacc[nt][0];
                else bk[rl0 * 34 + d0 + 16] += sacc[nt][0];
                if (d1 <= -16) ba0r0 += sacc[nt][1];
                else if (d1 >= 16) ba32r0 += sacc[nt][1];
                else bk[rl0 * 34 + d1 + 16] += sacc[nt][1];
                if (e0 <= -16) ba0r1 += sacc[nt][2];
                else if (e0 >= 16) ba32r1 += sacc[nt][2];
                else bk[(rl0 + 8) * 34 + e0 + 16] += sacc[nt][2];
                if (e1 <= -16) ba0r1 += sacc[nt][3];
                else if (e1 >= 16) ba32r1 += sacc[nt][3];
                else bk[(rl0 + 8) * 34 + e1 + 16] += sacc[nt][3];
            }
            ba0r0  += __shfl_xor_sync(0xffffffffu, ba0r0, 1);
            ba0r0  += __shfl_xor_sync(0xffffffffu, ba0r0, 2);
            ba32r0 += __shfl_xor_sync(0xffffffffu, ba32r0, 1);
            ba32r0 += __shfl_xor_sync(0xffffffffu, ba32r0, 2);
            ba0r1  += __shfl_xor_sync(0xffffffffu, ba0r1, 1);
            ba0r1  += __shfl_xor_sync(0xffffffffu, ba0r1, 2);
            ba32r1 += __shfl_xor_sync(0xffffffffu, ba32r1, 1);
            ba32r1 += __shfl_xor_sync(0xffffffffu, ba32r1, 2);
            if (tig == 0) {
                bk[rl0 * 34 + 0]        += ba0r0;
                bk[rl0 * 34 + 32]       += ba32r0;
                bk[(rl0 + 8) * 34 + 0]  += ba0r1;
                bk[(rl0 + 8) * 34 + 32] += ba32r1;
            }
        }

        // --- P @ V: A-frags directly from S fragments (fp16 identity) ---
        #pragma unroll
        for (int j = 0; j < 4; j++) {
            const int pb = j * 8;
            unsigned a[4];
            a[0] = f2h2(sacc[2 * j][0],     sacc[2 * j][1]);
            a[1] = f2h2(sacc[2 * j][2],     sacc[2 * j][3]);
            a[2] = f2h2(sacc[2 * j + 1][0], sacc[2 * j + 1][1]);
            a[3] = f2h2(sacc[2 * j + 1][2], sacc[2 * j + 1][3]);
            #pragma unroll
            for (int nt = 0; nt < 8; nt++) {
                unsigned bf[2];
                int br = (nt * 8 + gid) * FSTR + pb;
                bf[0] = Vs[br + tig];
                bf[1] = Vs[br + tig + 4];
                mmaf16(oacc[nt], a, bf);
            }
        }
        __syncthreads();
    }

    // --- epilogue: + buckets @ rel_v, normalize, write fp16 ---
    float* rv = (float*)Ks;   // 33 x 64, stride 68 (9216B region fits 8976B)
    for (int i = tid; i < NREL * HD; i += 256) {
        int r = i >> 6, c = i & 63;
        rv[r * 68 + c] = relv[i];
    }
    __syncthreads();

    float inv0 = 1.f / l0, inv1 = 1.f / l1;

    #pragma unroll 1
    for (int r = 0; r < NREL; r++) {
        float br0 = bk[rl0 * 34 + r];
        float br1 = bk[(rl0 + 8) * 34 + r];
        #pragma unroll
        for (int nt = 0; nt < 8; nt++) {
            float r0 = rv[r * 68 + nt * 8 + 2 * tig];
            float r1 = rv[r * 68 + nt * 8 + 2 * tig + 1];
            oacc[nt][0] += br0 * r0; oacc[nt][1] += br0 * r1;
            oacc[nt][2] += br1 * r0; oacc[nt][3] += br1 * r1;
        }
    }

    const int b_ = bh >> 4, h_ = bh & 15;
    #pragma unroll
    for (int nt = 0; nt < 8; nt++) {
        int col = h_ * 64 + nt * 8 + 2 * tig;
        *(unsigned*)(O + ((size_t)b_ * SS + q0 + rl0) * DD + col)
            = f2h2(oacc[nt][0] * inv0, oacc[nt][1] * inv0);
        *(unsigned*)(O + ((size_t)b_ * SS + q0 + rl0 + 8) * DD + col)
            = f2h2(oacc[nt][2] * inv1, oacc[nt][3] * inv1);
    }
}

// ---------------------------------------------------------------------------
// LayerNorm; optionally writes fp16 copy
// ---------------------------------------------------------------------------
__global__ __launch_bounds__(256)
void ln_kernel(const float* __restrict__ X, const float* __restrict__ g,
               const float* __restrict__ bt, float* __restrict__ out,
               __half* __restrict__ outh)
{
    __shared__ float red[32];
    const int row = blockIdx.x;
    const int tid = threadIdx.x;
    const float* x = X + (size_t)row * DD;

    float4 v = *(const float4*)(x + tid * 4);
    float s  = v.x + v.y + v.z + v.w;
    float ss = v.x*v.x + v.y*v.y + v.z*v.z + v.w*v.w;
    s  = blockReduceSum256(s,  red);
    ss = blockReduceSum256(ss, red);
    const float mean = s * (1.f / DD);
    const float var  = ss * (1.f / DD) - mean * mean;
    const float rs   = rsqrtf(var + 1e-5f);

    float4 gg = *(const float4*)(g  + tid * 4);
    float4 bb = *(const float4*)(bt + tid * 4);
    float4 o;
    o.x = (v.x - mean) * rs * gg.x + bb.x;
    o.y = (v.y - mean) * rs * gg.y + bb.y;
    o.z = (v.z - mean) * rs * gg.z + bb.z;
    o.w = (v.w - mean) * rs * gg.w + bb.w;
    *(float4*)(out + (size_t)row * DD + tid * 4) = o;
    if (outh) {
        uint2 oh;
        oh.x = f2h2(o.x, o.y); oh.y = f2h2(o.z, o.w);
        *(uint2*)(outh + (size_t)row * DD + tid * 4) = oh;
    }
}

// ---------------------------------------------------------------------------
// kernel_launch
// ---------------------------------------------------------------------------
extern "C" void kernel_launch(void* const* d_in, const int* in_sizes, int n_in,
                              void* d_out, int out_size)
{
    const float* x     = (const float*)d_in[0];
    const float* wq    = (const float*)d_in[2];
    const float* bq    = (const float*)d_in[3];
    const float* wk    = (const float*)d_in[4];
    const float* bk_   = (const float*)d_in[5];
    const float* wv    = (const float*)d_in[6];
    const float* bv    = (const float*)d_in[7];
    const float* wo    = (const float*)d_in[8];
    const float* bo    = (const float*)d_in[9];
    const float* rel_k = (const float*)d_in[10];
    const float* rel_v = (const float*)d_in[11];
    const float* fc1_w = (const float*)d_in[12];
    const float* fc1_b = (const float*)d_in[13];
    const float* fc2_w = (const float*)d_in[14];
    const float* fc2_b = (const float*)d_in[15];
    const float* ln1_g = (const float*)d_in[16];
    const float* ln1_b = (const float*)d_in[17];
    const float* ln2_g = (const float*)d_in[18];
    const float* ln2_b = (const float*)d_in[19];

    float* scratch = nullptr;
    cudaGetSymbolAddress((void**)&scratch, g_scratch);
    __half* Qh   = (__half*)(scratch + OFF_Q);
    __half* Kh   = (__half*)(scratch + OFF_K);
    __half* Vth  = (__half*)(scratch + OFF_V);
    float*  qrel = scratch + OFF_QREL;
    __half* Oh   = (__half*)(scratch + OFF_O);
    float*  t1   = scratch + OFF_T1;
    float*  x1   = scratch + OFF_X1;
    __half* ffh  = (__half*)(scratch + OFF_FFH);
    float*  t2   = scratch + OFF_T2;
    __half* xth  = (__half*)(scratch + OFF_XT);
    __half* x1th = (__half*)(scratch + OFF_X1T);
    __half* wqkvt= (__half*)(scratch + OFF_WQT);  // [3072][1024]
    __half* woth = (__half*)(scratch + OFF_WOT);
    __half* f1t  = (__half*)(scratch + OFF_F1T);
    __half* f2t  = (__half*)(scratch + OFF_F2T);

    const int M = BB * SS;                 // 8192
    const int FLASH_SMEM = (128 * FSTR + TKF * FSTR + TKF * FSTR) * 4 + 128 * 34 * 4 * 2;

    cudaFuncSetAttribute(flash_attn, cudaFuncAttributeMaxDynamicSharedMemorySize, FLASH_SMEM);

    // operand prep
    cvt_h_kernel<<<(M * DD / 8 + 255) / 256, 256>>>(x, xth, M * DD);
    cvt_t_kernel<<<dim3(DD / 32, DD / 32), 256>>>(wq, wqkvt,                DD, DD);
    cvt_t_kernel<<<dim3(DD / 32, DD / 32), 256>>>(wk, wqkvt + 1048576,      DD, DD);
    cvt_t_kernel<<<dim3(DD / 32, DD / 32), 256>>>(wv, wqkvt + 2097152,      DD, DD);
    cvt_t_kernel<<<dim3(DD / 32, DD / 32), 256>>>(wo, woth,                 DD, DD);
    cvt_t_kernel<<<dim3(DFF / 32, DD / 32), 256>>>(fc1_w, f1t, DD, DFF);
    cvt_t_kernel<<<dim3(DD / 32, DFF / 32), 256>>>(fc2_w, f2t, DFF, DD);

    // fused QKV (N = 3072, scatter; V transposed)
    gemm_f16<<<dim3(3 * DD / 128, M / 128), 256>>>(
        xth, wqkvt, bq, bk_, bv, nullptr, Qh, M, 3 * DD, DD, 3);

    qrel_kernel<<<BH * SS / 64, 256>>>(Qh, rel_k, qrel);

    dim3 gFA(SS / 128, BH);
    flash_attn<<<gFA, 256, FLASH_SMEM>>>(Qh, Kh, Vth, qrel, rel_v, Oh);

    gemm_f16<<<dim3(DD / 128, M / 128), 256>>>(
        Oh, woth, bo, nullptr, nullptr, x, t1, M, DD, DD, 2);
    ln_kernel<<<M, 256>>>(t1, ln1_g, ln1_b, x1, x1th);

    gemm_f16<<<dim3(DFF / 128, M / 128), 256>>>(
        x1th, f1t, fc1_b, nullptr, nullptr, nullptr, ffh, M, DFF, DD, 1);

    gemm_f16<<<dim3(DD / 128, M / 128), 256>>>(
        ffh, f2t, fc2_b, nullptr, nullptr, x1, t2, M, DD, DFF, 2);
    ln_kernel<<<M, 256>>>(t2, ln2_g, ln2_b, (float*)d_out, nullptr);
}

// round 8
// speedup vs baseline: 2.5368x; 1.0224x over previous
#include <cuda_runtime.h>
#include <cuda_fp16.h>
#include <math.h>
#include <stdint.h>

// ---------------------------------------------------------------------------
// Problem constants
// ---------------------------------------------------------------------------
#define BB 8
#define SS 1024
#define DD 1024
#define HH 16
#define HD 64
#define DFF 4096
#define BH 128
#define NREL 33

// ---------------------------------------------------------------------------
// Scratch (float units; fp16 regions reinterpreted)
// ---------------------------------------------------------------------------
#define OFF_Q     0ull
#define OFF_K     8388608ull
#define OFF_V     16777216ull
#define OFF_QREL  25165824ull
#define OFF_O     29491200ull
#define OFF_T1    37879808ull
#define OFF_X1    46268416ull
#define OFF_FFH   54657024ull
#define OFF_T2    88211456ull
#define OFF_XT    96600064ull
#define OFF_X1T   104988672ull
#define OFF_WQT   113377280ull
#define OFF_WOT   116523008ull
#define OFF_F1T   117571584ull
#define OFF_F2T   121765888ull
#define SCRATCH_TOTAL 125960192ull

__device__ float g_scratch[SCRATCH_TOTAL];

// ---------------------------------------------------------------------------
// helpers
// ---------------------------------------------------------------------------
__device__ __forceinline__ unsigned f2h2(float a, float b) {
    __half2 h = __floats2half2_rn(a, b);
    return *(unsigned*)&h;
}

__device__ __forceinline__ void mmaf16(float* c, const unsigned* a, const unsigned* b) {
    asm volatile(
        "mma.sync.aligned.m16n8k16.row.col.f32.f16.f16.f32 "
        "{%0,%1,%2,%3}, {%4,%5,%6,%7}, {%8,%9}, {%0,%1,%2,%3};"
        : "+f"(c[0]), "+f"(c[1]), "+f"(c[2]), "+f"(c[3])
        : "r"(a[0]), "r"(a[1]), "r"(a[2]), "r"(a[3]), "r"(b[0]), "r"(b[1]));
}

__device__ __forceinline__ unsigned su32(const void* p) {
    return (unsigned)__cvta_generic_to_shared(p);
}
#define CP16(dst, src) \
    asm volatile("cp.async.cg.shared.global [%0], [%1], 16;" :: "r"(dst), "l"(src) : "memory")
#define CPCOMMIT() asm volatile("cp.async.commit_group;" ::: "memory")
#define CPWAIT(n)  asm volatile("cp.async.wait_group %0;" :: "n"(n) : "memory")

#define PADP 20   // gemm pair stride
#define FSTR 36   // flash pair stride
#define GSTG 2560 // gemm stage size (u32): 128*PADP
#define FSTG 2304 // flash K/V stage size (u32): 64*FSTR

// ---------------------------------------------------------------------------
// Block reductions
// ---------------------------------------------------------------------------
__device__ __forceinline__ float blockReduceSum256(float v, float* sh) {
    #pragma unroll
    for (int o = 16; o; o >>= 1) v += __shfl_xor_sync(0xffffffffu, v, o);
    int warp = threadIdx.x >> 5, lane = threadIdx.x & 31;
    if (lane == 0) sh[warp] = v;
    __syncthreads();
    if (warp == 0) {
        v = (lane < 8) ? sh[lane] : 0.f;
        #pragma unroll
        for (int o = 4; o; o >>= 1) v += __shfl_xor_sync(0xffffffffu, v, o);
        if (lane == 0) sh[0] = v;
    }
    __syncthreads();
    float r = sh[0];
    __syncthreads();
    return r;
}

// ---------------------------------------------------------------------------
// fp32 -> fp16 elementwise
// ---------------------------------------------------------------------------
__global__ __launch_bounds__(256)
void cvt_h_kernel(const float* __restrict__ in, __half* __restrict__ out, int n)
{
    int i = (blockIdx.x * 256 + threadIdx.x) * 8;
    if (i < n) {
        float4 a = *(const float4*)(in + i);
        float4 b = *(const float4*)(in + i + 4);
        uint4 o;
        o.x = f2h2(a.x, a.y); o.y = f2h2(a.z, a.w);
        o.z = f2h2(b.x, b.y); o.w = f2h2(b.z, b.w);
        *(uint4*)(out + i) = o;
    }
}

// ---------------------------------------------------------------------------
// Transpose + fp16: in [K,N] fp32 -> out [N,K] fp16
// ---------------------------------------------------------------------------
__global__ __launch_bounds__(256)
void cvt_t_kernel(const float* __restrict__ in, __half* __restrict__ out, int K, int N)
{
    __shared__ float t[32][33];
    const int lx = threadIdx.x & 31, ly = threadIdx.x >> 5;
    const int n = blockIdx.x * 32 + lx, k0 = blockIdx.y * 32;
    #pragma unroll
    for (int p = 0; p < 32; p += 8)
        t[ly + p][lx] = in[(size_t)(k0 + ly + p) * N + n];
    __syncthreads();
    const int k = k0 + lx, n2 = blockIdx.x * 32;
    #pragma unroll
    for (int p = 0; p < 32; p += 8)
        out[(size_t)(n2 + ly + p) * K + k] = __float2half(t[lx][ly + p]);
}

// ---------------------------------------------------------------------------
// fp16 GEMM: C = A[M,K] @ Bt[N,K]^T. 3-stage cp.async ring, 1 sync/step.
//   mode 1: relu -> fp16   mode 2: +bias+resid -> fp32   mode 3: QKV scatter
// Block 128x128, K-tile 32. 8 warps: 2(M) x 4(N).
// ---------------------------------------------------------------------------
#define GEMM_SMEM (6 * GSTG * 4)

__global__ __launch_bounds__(256, 2)
void gemm_f16(const __half* __restrict__ A, const __half* __restrict__ Bt,
              const float* __restrict__ b1, const float* __restrict__ b2,
              const float* __restrict__ b3, const float* __restrict__ resid,
              void* __restrict__ C, int M, int N, int K, int mode)
{
    extern __shared__ __align__(16) unsigned gsm[];
    unsigned* As = gsm;               // 3 stages x 2560
    unsigned* Bs = gsm + 3 * GSTG;    // 3 stages x 2560
    const int tid = threadIdx.x, lane = tid & 31, warp = tid >> 5;
    const int gid = lane >> 2, tig = lane & 3;
    const int m0 = blockIdx.y * 128, n0 = blockIdx.x * 128;
    const int wm = warp & 1, wn = warp >> 1;
    const int T = K >> 5;

    #define G_ISSUE(s, k0) do {                                                 \
        unsigned da = su32(As + (s) * GSTG);                                     \
        unsigned db = su32(Bs + (s) * GSTG);                                     \
        _Pragma("unroll")                                                        \
        for (int p_ = 0; p_ < 2; p_++) {                                         \
            int f_ = tid + p_ * 256;                                             \
            int r_ = f_ >> 2, c_ = f_ & 3;                                       \
            CP16(da + (unsigned)((r_ * PADP + c_ * 4) * 4),                      \
                 A + (size_t)(m0 + r_) * K + (k0) + c_ * 8);                     \
            CP16(db + (unsigned)((r_ * PADP + c_ * 4) * 4),                      \
                 Bt + (size_t)(n0 + r_) * K + (k0) + c_ * 8);                    \
        }                                                                        \
        CPCOMMIT();                                                              \
    } while (0)

    float acc[4][4][4];
    #pragma unroll
    for (int i = 0; i < 4; i++)
        #pragma unroll
        for (int j = 0; j < 4; j++)
            #pragma unroll
            for (int t = 0; t < 4; t++) acc[i][j][t] = 0.f;

    G_ISSUE(0, 0);
    G_ISSUE(1, 32);

    for (int i = 0; i < T; i++) {
        if (i + 1 < T) { CPWAIT(1); } else { CPWAIT(0); }
        __syncthreads();
        if (i + 2 < T) G_ISSUE((i + 2) % 3, (i + 2) * 32);

        const unsigned* Ac = As + (i % 3) * GSTG;
        const unsigned* Bc = Bs + (i % 3) * GSTG;
        #pragma unroll
        for (int ks = 0; ks < 2; ks++) {
            const int pb = ks * 8;
            unsigned af[4][4], bf[4][2];
            #pragma unroll
            for (int mt = 0; mt < 4; mt++) {
                int r = (wm * 64 + mt * 16 + gid) * PADP;
                af[mt][0] = Ac[r + pb + tig];
                af[mt][1] = Ac[r + 8 * PADP + pb + tig];
                af[mt][2] = Ac[r + pb + tig + 4];
                af[mt][3] = Ac[r + 8 * PADP + pb + tig + 4];
            }
            #pragma unroll
            for (int nt = 0; nt < 4; nt++) {
                int r = (wn * 32 + nt * 8 + gid) * PADP;
                bf[nt][0] = Bc[r + pb + tig];
                bf[nt][1] = Bc[r + pb + tig + 4];
            }
            #pragma unroll
            for (int mt = 0; mt < 4; mt++)
                #pragma unroll
                for (int nt = 0; nt < 4; nt++)
                    mmaf16(acc[mt][nt], af[mt], bf[nt]);
        }
    }
    #undef G_ISSUE

    #pragma unroll
    for (int mt = 0; mt < 4; mt++) {
        #pragma unroll
        for (int nt = 0; nt < 4; nt++) {
            int n_ = n0 + wn * 32 + nt * 8 + 2 * tig;
            #pragma unroll
            for (int h = 0; h < 2; h++) {
                int m = m0 + wm * 64 + mt * 16 + gid + h * 8;
                float v0 = acc[mt][nt][h * 2 + 0];
                float v1 = acc[mt][nt][h * 2 + 1];
                if (mode == 3) {
                    int mat = n_ >> 10, dcol = n_ & 1023;
                    const float* bp = mat == 0 ? b1 : (mat == 1 ? b2 : b3);
                    v0 += bp[dcol]; v1 += bp[dcol + 1];
                    int b_ = m >> 10, s_ = m & 1023;
                    int h_ = dcol >> 6, hd = dcol & 63;
                    __half* Ch = (__half*)C;
                    if (mat < 2) {
                        __half* base = Ch + (size_t)mat * 16777216ull;
                        *(unsigned*)(base + ((((size_t)(b_ * 16 + h_)) << 10) + s_) * 64 + hd)
                            = f2h2(v0, v1);
                    } else {
                        __half* vb = Ch + 33554432ull;
                        size_t bhh = (size_t)(b_ * 16 + h_) * 64;
                        vb[(bhh + hd)     * 1024 + s_] = __float2half(v0);
                        vb[(bhh + hd + 1) * 1024 + s_] = __float2half(v1);
                    }
                } else if (mode == 1) {
                    v0 = fmaxf(v0 + b1[n_], 0.f);
                    v1 = fmaxf(v1 + b1[n_ + 1], 0.f);
                    *(unsigned*)((__half*)C + (size_t)m * N + n_) = f2h2(v0, v1);
                } else {
                    v0 += b1[n_]     + resid[(size_t)m * N + n_];
                    v1 += b1[n_ + 1] + resid[(size_t)m * N + n_ + 1];
                    *(float2*)((float*)C + (size_t)m * N + n_) = make_float2(v0, v1);
                }
            }
        }
    }
}

// ---------------------------------------------------------------------------
// qrel[bh,q,r] = Q[bh,q,:] . rel_k[r,:]   (Q fp16)
// ---------------------------------------------------------------------------
__global__ __launch_bounds__(256)
void qrel_kernel(const __half* __restrict__ Q, const float* __restrict__ relk,
                 float* __restrict__ out)
{
    __shared__ float rk[NREL * 65];
    __shared__ float qs[64 * 65];
    const int tid = threadIdx.x;
    const int row0 = blockIdx.x * 64;

    for (int i = tid; i < NREL * HD; i += 256) {
        int r = i >> 6, d = i & 63;
        rk[r * 65 + d] = relk[i];
    }
    #pragma unroll
    for (int p = 0; p < 8; p++) {
        int f = tid + p * 256;
        int r = f >> 5, c = f & 31;
        __half2 h = ((const __half2*)Q)[(size_t)(row0 + r) * 32 + c];
        float2 fv = __half22float2(h);
        qs[r * 65 + c * 2]     = fv.x;
        qs[r * 65 + c * 2 + 1] = fv.y;
    }
    __syncthreads();

    for (int i = tid; i < 64 * NREL; i += 256) {
        int q = i / NREL, r = i - q * NREL;
        float s = 0.f;
        #pragma unroll
        for (int d = 0; d < HD; d++)
            s = fmaf(qs[q * 65 + d], rk[r * 65 + d], s);
        out[(size_t)(row0 + q) * NREL + r] = s;
    }
}

// ---------------------------------------------------------------------------
// FUSED flash attention, fp16 mma, 3-buffer K/V ring (1 sync/tile).
// Q,K [bh][s][hd] fp16; V transposed [bh][hd][s] fp16. O fp16 [b][s][d].
// ---------------------------------------------------------------------------
#define TKF 64
#define NKT (SS / TKF)   // 16

__global__ __launch_bounds__(256, 2)
void flash_attn(const __half* __restrict__ Q, const __half* __restrict__ Kh,
                const __half* __restrict__ Vt, const float* __restrict__ qrel,
                const float* __restrict__ relv, __half* __restrict__ O)
{
    extern __shared__ __align__(16) unsigned fsm[];
    unsigned* Qs = fsm;                          // 128*36
    unsigned* Ks = Qs + 128 * FSTR;              // 3 x 64*36
    unsigned* Vs = Ks + 3 * FSTG;                // 3 x 64*36
    float* qr = (float*)(Vs + 3 * FSTG);         // 128*34
    float* bk = qr + 128 * 34;                   // 128*34

    const int tid = threadIdx.x, lane = tid & 31, warp = tid >> 5;
    const int gid = lane >> 2, tig = lane & 3;
    const int bh = blockIdx.y, q0 = blockIdx.x * 128;
    const __half* Qb = Q  + (size_t)bh * SS * HD;
    const __half* Kb = Kh + (size_t)bh * SS * HD;
    const __half* Vb = Vt + (size_t)bh * HD * SS;

    const int rl0 = warp * 16 + gid;
    const int qg0 = q0 + rl0;

    #define KV_ISSUE(s, k0) do {                                                \
        unsigned dk = su32(Ks + (s) * FSTG), dv = su32(Vs + (s) * FSTG);         \
        int r_ = tid >> 3, c_ = tid & 7;                                         \
        _Pragma("unroll")                                                        \
        for (int p_ = 0; p_ < 2; p_++) {                                         \
            int rr_ = r_ + p_ * 32;                                              \
            CP16(dk + (unsigned)((rr_ * FSTR + c_ * 4) * 4),                     \
                 Kb + (size_t)((k0) + rr_) * HD + c_ * 8);                       \
            CP16(dv + (unsigned)((rr_ * FSTR + c_ * 4) * 4),                     \
                 Vb + (size_t)rr_ * SS + (k0) + c_ * 8);                         \
        }                                                                        \
    } while (0)

    // G0 = Q + KV0, G1 = KV1
    {
        unsigned dq = su32(Qs);
        int r = tid >> 3, c = tid & 7;
        #pragma unroll
        for (int p = 0; p < 4; p++) {
            int rr = r + p * 32;
            CP16(dq + (unsigned)((rr * FSTR + c * 4) * 4), Qb + (size_t)(q0 + rr) * HD + c * 8);
        }
        KV_ISSUE(0, 0);
        CPCOMMIT();
        KV_ISSUE(1, TKF);
        CPCOMMIT();
    }
    for (int i = tid; i < 128 * NREL; i += 256) {
        int r = i / NREL, c = i - r * NREL;
        qr[r * 34 + c] = qrel[((size_t)bh * SS + q0 + r) * NREL + c];
    }
    for (int i = tid; i < 128 * 34; i += 256) bk[i] = 0.f;

    float oacc[8][4];
    #pragma unroll
    for (int i = 0; i < 8; i++)
        #pragma unroll
        for (int t = 0; t < 4; t++) oacc[i][t] = 0.f;
    float m0 = -1e30f, m1 = -1e30f, l0 = 0.f, l1 = 0.f;

    for (int kt = 0; kt < NKT; kt++) {
        const int k0 = kt * TKF;
        if (kt + 1 < NKT) { CPWAIT(1); } else { CPWAIT(0); }
        __syncthreads();
        if (kt + 2 < NKT) { KV_ISSUE((kt + 2) % 3, (kt + 2) * TKF); CPCOMMIT(); }

        const unsigned* Kc = Ks + (kt % 3) * FSTG;
        const unsigned* Vc = Vs + (kt % 3) * FSTG;

        // --- S = Q @ K^T ---
        float sacc[8][4];
        #pragma unroll
        for (int i = 0; i < 8; i++)
            #pragma unroll
            for (int t = 0; t < 4; t++) sacc[i][t] = 0.f;

        #pragma unroll
        for (int ks = 0; ks < 4; ks++) {
            const int pb = ks * 8;
            unsigned af[4];
            af[0] = Qs[rl0 * FSTR + pb + tig];
            af[1] = Qs[(rl0 + 8) * FSTR + pb + tig];
            af[2] = Qs[rl0 * FSTR + pb + tig + 4];
            af[3] = Qs[(rl0 + 8) * FSTR + pb + tig + 4];
            #pragma unroll
            for (int nt = 0; nt < 8; nt++) {
                unsigned bf[2];
                int br = (nt * 8 + gid) * FSTR + pb;
                bf[0] = Kc[br + tig];
                bf[1] = Kc[br + tig + 4];
                mmaf16(sacc[nt], af, bf);
            }
        }

        // --- bias + scale + row max ---
        float mx0 = -1e30f, mx1 = -1e30f;
        #pragma unroll
        for (int nt = 0; nt < 8; nt++) {
            int kc = k0 + nt * 8 + 2 * tig;
            int d00 = kc - qg0;           d00 = d00 < -16 ? -16 : (d00 > 16 ? 16 : d00);
            int d01 = kc + 1 - qg0;       d01 = d01 < -16 ? -16 : (d01 > 16 ? 16 : d01);
            int d10 = kc - qg0 - 8;       d10 = d10 < -16 ? -16 : (d10 > 16 ? 16 : d10);
            int d11 = kc + 1 - qg0 - 8;   d11 = d11 < -16 ? -16 : (d11 > 16 ? 16 : d11);
            sacc[nt][0] = (sacc[nt][0] + qr[rl0 * 34 + d00 + 16]) * 0.125f;
            sacc[nt][1] = (sacc[nt][1] + qr[rl0 * 34 + d01 + 16]) * 0.125f;
            sacc[nt][2] = (sacc[nt][2] + qr[(rl0 + 8) * 34 + d10 + 16]) * 0.125f;
            sacc[nt][3] = (sacc[nt][3] + qr[(rl0 + 8) * 34 + d11 + 16]) * 0.125f;
            mx0 = fmaxf(mx0, fmaxf(sacc[nt][0], sacc[nt][1]));
            mx1 = fmaxf(mx1, fmaxf(sacc[nt][2], sacc[nt][3]));
        }
        mx0 = fmaxf(mx0, __shfl_xor_sync(0xffffffffu, mx0, 1));
        mx0 = fmaxf(mx0, __shfl_xor_sync(0xffffffffu, mx0, 2));
        mx1 = fmaxf(mx1, __shfl_xor_sync(0xffffffffu, mx1, 1));
        mx1 = fmaxf(mx1, __shfl_xor_sync(0xffffffffu, mx1, 2));

        float m0n = fmaxf(m0, mx0), m1n = fmaxf(m1, mx1);
        float corr0 = __expf(m0 - m0n), corr1 = __expf(m1 - m1n);
        m0 = m0n; m1 = m1n;

        float sum0 = 0.f, sum1 = 0.f;
        #pragma unroll
        for (int nt = 0; nt < 8; nt++) {
            float p0 = __expf(sacc[nt][0] - m0);
            float p1 = __expf(sacc[nt][1] - m0);
            float p2 = __expf(sacc[nt][2] - m1);
            float p3 = __expf(sacc[nt][3] - m1);
            sacc[nt][0] = p0; sacc[nt][1] = p1; sacc[nt][2] = p2; sacc[nt][3] = p3;
            sum0 += p0 + p1; sum1 += p2 + p3;
            oacc[nt][0] *= corr0; oacc[nt][1] *= corr0;
            oacc[nt][2] *= corr1; oacc[nt][3] *= corr1;
        }
        sum0 += __shfl_xor_sync(0xffffffffu, sum0, 1);
        sum0 += __shfl_xor_sync(0xffffffffu, sum0, 2);
        sum1 += __shfl_xor_sync(0xffffffffu, sum1, 1);
        sum1 += __shfl_xor_sync(0xffffffffu, sum1, 2);
        l0 = l0 * corr0 + sum0;
        l1 = l1 * corr1 + sum1;

        // --- buckets ---
        {
            int st = tig * 9, en = st + 9 > NREL ? NREL : st + 9;
            float* b0p = &bk[rl0 * 34];
            float* b1p = &bk[(rl0 + 8) * 34];
            for (int d = st; d < en; d++) { b0p[d] *= corr0; b1p[d] *= corr1; }
        }
        __syncwarp();
        {
            float ba0r0 = 0.f, ba32r0 = 0.f, ba0r1 = 0.f, ba32r1 = 0.f;
            #pragma unroll
            for (int nt = 0; nt < 8; nt++) {
                int kc = k0 + nt * 8 + 2 * tig;
                int d0 = kc - qg0, d1 = kc + 1 - qg0;
                int e0 = kc - qg0 - 8, e1 = kc + 1 - qg0 - 8;
                if (d0 <= -16) ba0r0 += sacc[nt][0];
                else if (d0 >= 16) ba32r0 += sacc[nt][0];
                else bk[rl0 * 34 + d0 + 16] += sacc[nt][0];
                if (d1 <= -16) ba0r0 += sacc[nt][1];
                else if (d1 >= 16) ba32r0 += sacc[nt][1];
                else bk[rl0 * 34 + d1 + 16] += sacc[nt][1];
                if (e0 <= -16) ba0r1 += sacc[nt][2];
                else if (e0 >= 16) ba32r1 += sacc[nt][2];
                else bk[(rl0 + 8) * 34 + e0 + 16] += sacc[nt][2];
                if (e1 <= -16) ba0r1 += sacc[nt][3];
                else if (e1 >= 16) ba32r1 += sacc[nt][3];
                else bk[(rl0 + 8) * 34 + e1 + 16] += sacc[nt][3];
            }
            ba0r0  += __shfl_xor_sync(0xffffffffu, ba0r0, 1);
            ba0r0  += __shfl_xor_sync(0xffffffffu, ba0r0, 2);
            ba32r0 += __shfl_xor_sync(0xffffffffu, ba32r0, 1);
            ba32r0 += __shfl_xor_sync(0xffffffffu, ba32r0, 2);
            ba0r1  += __shfl_xor_sync(0xffffffffu, ba0r1, 1);
            ba0r1  += __shfl_xor_sync(0xffffffffu, ba0r1, 2);
            ba32r1 += __shfl_xor_sync(0xffffffffu, ba32r1, 1);
            ba32r1 += __shfl_xor_sync(0xffffffffu, ba32r1, 2);
            if (tig == 0) {
                bk[rl0 * 34 + 0]        += ba0r0;
                bk[rl0 * 34 + 32]       += ba32r0;
                bk[(rl0 + 8) * 34 + 0]  += ba0r1;
                bk[(rl0 + 8) * 34 + 32] += ba32r1;
            }
        }

        // --- P @ V ---
        #pragma unroll
        for (int j = 0; j < 4; j++) {
            const int pb = j * 8;
            unsigned a[4];
            a[0] = f2h2(sacc[2 * j][0],     sacc[2 * j][1]);
            a[1] = f2h2(sacc[2 * j][2],     sacc[2 * j][3]);
            a[2] = f2h2(sacc[2 * j + 1][0], sacc[2 * j + 1][1]);
            a[3] = f2h2(sacc[2 * j + 1][2], sacc[2 * j + 1][3]);
            #pragma unroll
            for (int nt = 0; nt < 8; nt++) {
                unsigned bf[2];
                int br = (nt * 8 + gid) * FSTR + pb;
                bf[0] = Vc[br + tig];
                bf[1] = Vc[br + tig + 4];
                mmaf16(oacc[nt], a, bf);
            }
        }
    }
    #undef KV_ISSUE
    __syncthreads();

    // --- epilogue: + buckets @ rel_v, normalize, write fp16 ---
    float* rv = (float*)Ks;
    for (int i = tid; i < NREL * HD; i += 256) {
        int r = i >> 6, c = i & 63;
        rv[r * 68 + c] = relv[i];
    }
    __syncthreads();

    float inv0 = 1.f / l0, inv1 = 1.f / l1;

    #pragma unroll 1
    for (int r = 0; r < NREL; r++) {
        float br0 = bk[rl0 * 34 + r];
        float br1 = bk[(rl0 + 8) * 34 + r];
        #pragma unroll
        for (int nt = 0; nt < 8; nt++) {
            float r0 = rv[r * 68 + nt * 8 + 2 * tig];
            float r1 = rv[r * 68 + nt * 8 + 2 * tig + 1];
            oacc[nt][0] += br0 * r0; oacc[nt][1] += br0 * r1;
            oacc[nt][2] += br1 * r0; oacc[nt][3] += br1 * r1;
        }
    }

    const int b_ = bh >> 4, h_ = bh & 15;
    #pragma unroll
    for (int nt = 0; nt < 8; nt++) {
        int col = h_ * 64 + nt * 8 + 2 * tig;
        *(unsigned*)(O + ((size_t)b_ * SS + q0 + rl0) * DD + col)
            = f2h2(oacc[nt][0] * inv0, oacc[nt][1] * inv0);
        *(unsigned*)(O + ((size_t)b_ * SS + q0 + rl0 + 8) * DD + col)
            = f2h2(oacc[nt][2] * inv1, oacc[nt][3] * inv1);
    }
}

// ---------------------------------------------------------------------------
// LayerNorm; optionally writes fp16 copy
// ---------------------------------------------------------------------------
__global__ __launch_bounds__(256)
void ln_kernel(const float* __restrict__ X, const float* __restrict__ g,
               const float* __restrict__ bt, float* __restrict__ out,
               __half* __restrict__ outh)
{
    __shared__ float red[32];
    const int row = blockIdx.x;
    const int tid = threadIdx.x;
    const float* x = X + (size_t)row * DD;

    float4 v = *(const float4*)(x + tid * 4);
    float s  = v.x + v.y + v.z + v.w;
    float ss = v.x*v.x + v.y*v.y + v.z*v.z + v.w*v.w;
    s  = blockReduceSum256(s,  red);
    ss = blockReduceSum256(ss, red);
    const float mean = s * (1.f / DD);
    const float var  = ss * (1.f / DD) - mean * mean;
    const float rs   = rsqrtf(var + 1e-5f);

    float4 gg = *(const float4*)(g  + tid * 4);
    float4 bb = *(const float4*)(bt + tid * 4);
    float4 o;
    o.x = (v.x - mean) * rs * gg.x + bb.x;
    o.y = (v.y - mean) * rs * gg.y + bb.y;
    o.z = (v.z - mean) * rs * gg.z + bb.z;
    o.w = (v.w - mean) * rs * gg.w + bb.w;
    *(float4*)(out + (size_t)row * DD + tid * 4) = o;
    if (outh) {
        uint2 oh;
        oh.x = f2h2(o.x, o.y); oh.y = f2h2(o.z, o.w);
        *(uint2*)(outh + (size_t)row * DD + tid * 4) = oh;
    }
}

// ---------------------------------------------------------------------------
// kernel_launch
// ---------------------------------------------------------------------------
extern "C" void kernel_launch(void* const* d_in, const int* in_sizes, int n_in,
                              void* d_out, int out_size)
{
    const float* x     = (const float*)d_in[0];
    const float* wq    = (const float*)d_in[2];
    const float* bq    = (const float*)d_in[3];
    const float* wk    = (const float*)d_in[4];
    const float* bk_   = (const float*)d_in[5];
    const float* wv    = (const float*)d_in[6];
    const float* bv    = (const float*)d_in[7];
    const float* wo    = (const float*)d_in[8];
    const float* bo    = (const float*)d_in[9];
    const float* rel_k = (const float*)d_in[10];
    const float* rel_v = (const float*)d_in[11];
    const float* fc1_w = (const float*)d_in[12];
    const float* fc1_b = (const float*)d_in[13];
    const float* fc2_w = (const float*)d_in[14];
    const float* fc2_b = (const float*)d_in[15];
    const float* ln1_g = (const float*)d_in[16];
    const float* ln1_b = (const float*)d_in[17];
    const float* ln2_g = (const float*)d_in[18];
    const float* ln2_b = (const float*)d_in[19];

    float* scratch = nullptr;
    cudaGetSymbolAddress((void**)&scratch, g_scratch);
    __half* Qh   = (__half*)(scratch + OFF_Q);
    __half* Kh   = (__half*)(scratch + OFF_K);
    __half* Vth  = (__half*)(scratch + OFF_V);
    float*  qrel = scratch + OFF_QREL;
    __half* Oh   = (__half*)(scratch + OFF_O);
    float*  t1   = scratch + OFF_T1;
    float*  x1   = scratch + OFF_X1;
    __half* ffh  = (__half*)(scratch + OFF_FFH);
    float*  t2   = scratch + OFF_T2;
    __half* xth  = (__half*)(scratch + OFF_XT);
    __half* x1th = (__half*)(scratch + OFF_X1T);
    __half* wqkvt= (__half*)(scratch + OFF_WQT);
    __half* woth = (__half*)(scratch + OFF_WOT);
    __half* f1t  = (__half*)(scratch + OFF_F1T);
    __half* f2t  = (__half*)(scratch + OFF_F2T);

    const int M = BB * SS;
    const int FLASH_SMEM = (128 * FSTR + 6 * FSTG) * 4 + 128 * 34 * 4 * 2;

    cudaFuncSetAttribute(flash_attn, cudaFuncAttributeMaxDynamicSharedMemorySize, FLASH_SMEM);
    cudaFuncSetAttribute(gemm_f16, cudaFuncAttributeMaxDynamicSharedMemorySize, GEMM_SMEM);

    // operand prep
    cvt_h_kernel<<<(M * DD / 8 + 255) / 256, 256>>>(x, xth, M * DD);
    cvt_t_kernel<<<dim3(DD / 32, DD / 32), 256>>>(wq, wqkvt,           DD, DD);
    cvt_t_kernel<<<dim3(DD / 32, DD / 32), 256>>>(wk, wqkvt + 1048576, DD, DD);
    cvt_t_kernel<<<dim3(DD / 32, DD / 32), 256>>>(wv, wqkvt + 2097152, DD, DD);
    cvt_t_kernel<<<dim3(DD / 32, DD / 32), 256>>>(wo, woth,            DD, DD);
    cvt_t_kernel<<<dim3(DFF / 32, DD / 32), 256>>>(fc1_w, f1t, DD, DFF);
    cvt_t_kernel<<<dim3(DD / 32, DFF / 32), 256>>>(fc2_w, f2t, DFF, DD);

    // fused QKV (N = 3072, scatter; V transposed)
    gemm_f16<<<dim3(3 * DD / 128, M / 128), 256, GEMM_SMEM>>>(
        xth, wqkvt, bq, bk_, bv, nullptr, Qh, M, 3 * DD, DD, 3);

    qrel_kernel<<<BH * SS / 64, 256>>>(Qh, rel_k, qrel);

    dim3 gFA(SS / 128, BH);
    flash_attn<<<gFA, 256, FLASH_SMEM>>>(Qh, Kh, Vth, qrel, rel_v, Oh);

    gemm_f16<<<dim3(DD / 128, M / 128), 256, GEMM_SMEM>>>(
        Oh, woth, bo, nullptr, nullptr, x, t1, M, DD, DD, 2);
    ln_kernel<<<M, 256>>>(t1, ln1_g, ln1_b, x1, x1th);

    gemm_f16<<<dim3(DFF / 128, M / 128), 256, GEMM_SMEM>>>(
        x1th, f1t, fc1_b, nullptr, nullptr, nullptr, ffh, M, DFF, DD, 1);

    gemm_f16<<<dim3(DD / 128, M / 128), 256, GEMM_SMEM>>>(
        ffh, f2t, fc2_b, nullptr, nullptr, x1, t2, M, DD, DFF, 2);
    ln_kernel<<<M, 256>>>(t2, ln2_g, ln2_b, (float*)d_out, nullptr);
}

// round 9
// speedup vs baseline: 2.6619x; 1.0493x over previous
#include <cuda_runtime.h>
#include <cuda_fp16.h>
#include <math.h>
#include <stdint.h>

// ---------------------------------------------------------------------------
// Problem constants
// ---------------------------------------------------------------------------
#define BB 8
#define SS 1024
#define DD 1024
#define HH 16
#define HD 64
#define DFF 4096
#define BH 128
#define NREL 33

// ---------------------------------------------------------------------------
// Scratch (float units; fp16 regions reinterpreted)
// ---------------------------------------------------------------------------
#define OFF_Q     0ull
#define OFF_K     8388608ull
#define OFF_V     16777216ull
#define OFF_QREL  25165824ull
#define OFF_O     29491200ull
#define OFF_T1    37879808ull
#define OFF_X1    46268416ull
#define OFF_FFH   54657024ull
#define OFF_T2    88211456ull
#define OFF_XT    96600064ull
#define OFF_X1T   104988672ull
#define OFF_WQT   113377280ull
#define OFF_WOT   116523008ull
#define OFF_F1T   117571584ull
#define OFF_F2T   121765888ull
#define SCRATCH_TOTAL 125960192ull

__device__ float g_scratch[SCRATCH_TOTAL];

// ---------------------------------------------------------------------------
// helpers
// ---------------------------------------------------------------------------
__device__ __forceinline__ unsigned f2h2(float a, float b) {
    __half2 h = __floats2half2_rn(a, b);
    return *(unsigned*)&h;
}

__device__ __forceinline__ void mmaf16(float* c, const unsigned* a, const unsigned* b) {
    asm volatile(
        "mma.sync.aligned.m16n8k16.row.col.f32.f16.f16.f32 "
        "{%0,%1,%2,%3}, {%4,%5,%6,%7}, {%8,%9}, {%0,%1,%2,%3};"
        : "+f"(c[0]), "+f"(c[1]), "+f"(c[2]), "+f"(c[3])
        : "r"(a[0]), "r"(a[1]), "r"(a[2]), "r"(a[3]), "r"(b[0]), "r"(b[1]));
}

__device__ __forceinline__ unsigned su32(const void* p) {
    return (unsigned)__cvta_generic_to_shared(p);
}
#define CP16(dst, src) \
    asm volatile("cp.async.cg.shared.global [%0], [%1], 16;" :: "r"(dst), "l"(src) : "memory")
#define CPCOMMIT() asm volatile("cp.async.commit_group;" ::: "memory")
#define CPWAIT(n)  asm volatile("cp.async.wait_group %0;" :: "n"(n) : "memory")

#define PADP 20   // gemm pair stride
#define FSTR 36   // flash pair stride
#define GSTG 2560 // gemm stage size (u32): 128*PADP
#define FSTG 2304 // flash K/V stage size (u32): 64*FSTR

// ---------------------------------------------------------------------------
// Block reductions
// ---------------------------------------------------------------------------
__device__ __forceinline__ float blockReduceSum256(float v, float* sh) {
    #pragma unroll
    for (int o = 16; o; o >>= 1) v += __shfl_xor_sync(0xffffffffu, v, o);
    int warp = threadIdx.x >> 5, lane = threadIdx.x & 31;
    if (lane == 0) sh[warp] = v;
    __syncthreads();
    if (warp == 0) {
        v = (lane < 8) ? sh[lane] : 0.f;
        #pragma unroll
        for (int o = 4; o; o >>= 1) v += __shfl_xor_sync(0xffffffffu, v, o);
        if (lane == 0) sh[0] = v;
    }
    __syncthreads();
    float r = sh[0];
    __syncthreads();
    return r;
}

// ---------------------------------------------------------------------------
// fp32 -> fp16 elementwise
// ---------------------------------------------------------------------------
__global__ __launch_bounds__(256)
void cvt_h_kernel(const float* __restrict__ in, __half* __restrict__ out, int n)
{
    int i = (blockIdx.x * 256 + threadIdx.x) * 8;
    if (i < n) {
        float4 a = *(const float4*)(in + i);
        float4 b = *(const float4*)(in + i + 4);
        uint4 o;
        o.x = f2h2(a.x, a.y); o.y = f2h2(a.z, a.w);
        o.z = f2h2(b.x, b.y); o.w = f2h2(b.z, b.w);
        *(uint4*)(out + i) = o;
    }
}

// ---------------------------------------------------------------------------
// Transpose + fp16: in [K,N] fp32 -> out [N,K] fp16
// ---------------------------------------------------------------------------
__global__ __launch_bounds__(256)
void cvt_t_kernel(const float* __restrict__ in, __half* __restrict__ out, int K, int N)
{
    __shared__ float t[32][33];
    const int lx = threadIdx.x & 31, ly = threadIdx.x >> 5;
    const int n = blockIdx.x * 32 + lx, k0 = blockIdx.y * 32;
    #pragma unroll
    for (int p = 0; p < 32; p += 8)
        t[ly + p][lx] = in[(size_t)(k0 + ly + p) * N + n];
    __syncthreads();
    const int k = k0 + lx, n2 = blockIdx.x * 32;
    #pragma unroll
    for (int p = 0; p < 32; p += 8)
        out[(size_t)(n2 + ly + p) * K + k] = __float2half(t[lx][ly + p]);
}

// ---------------------------------------------------------------------------
// fp16 GEMM: C = A[M,K] @ Bt[N,K]^T. 3-stage cp.async ring, 1 sync/step.
// 128 threads, 4 warps in 2(M) x 2(N); warp tile 64x64 (max register reuse:
// fragment smem traffic 0.0625 B/MAC -> tensor-bound).
//   mode 1: relu -> fp16   mode 2: +bias+resid -> fp32   mode 3: QKV scatter
// ---------------------------------------------------------------------------
#define GEMM_SMEM (6 * GSTG * 4)

__global__ __launch_bounds__(128, 2)
void gemm_f16(const __half* __restrict__ A, const __half* __restrict__ Bt,
              const float* __restrict__ b1, const float* __restrict__ b2,
              const float* __restrict__ b3, const float* __restrict__ resid,
              void* __restrict__ C, int M, int N, int K, int mode)
{
    extern __shared__ __align__(16) unsigned gsm[];
    unsigned* As = gsm;               // 3 stages x 2560
    unsigned* Bs = gsm + 3 * GSTG;    // 3 stages x 2560
    const int tid = threadIdx.x, lane = tid & 31, warp = tid >> 5;
    const int gid = lane >> 2, tig = lane & 3;
    const int m0 = blockIdx.y * 128, n0 = blockIdx.x * 128;
    const int wm = warp & 1, wn = warp >> 1;
    const int T = K >> 5;

    #define G_ISSUE(s, k0) do {                                                 \
        unsigned da = su32(As + (s) * GSTG);                                     \
        unsigned db = su32(Bs + (s) * GSTG);                                     \
        _Pragma("unroll")                                                        \
        for (int p_ = 0; p_ < 4; p_++) {                                         \
            int f_ = tid + p_ * 128;                                             \
            int r_ = f_ >> 2, c_ = f_ & 3;                                       \
            CP16(da + (unsigned)((r_ * PADP + c_ * 4) * 4),                      \
                 A + (size_t)(m0 + r_) * K + (k0) + c_ * 8);                     \
            CP16(db + (unsigned)((r_ * PADP + c_ * 4) * 4),                      \
                 Bt + (size_t)(n0 + r_) * K + (k0) + c_ * 8);                    \
        }                                                                        \
        CPCOMMIT();                                                              \
    } while (0)

    float acc[4][8][4];
    #pragma unroll
    for (int i = 0; i < 4; i++)
        #pragma unroll
        for (int j = 0; j < 8; j++)
            #pragma unroll
            for (int t = 0; t < 4; t++) acc[i][j][t] = 0.f;

    G_ISSUE(0, 0);
    G_ISSUE(1, 32);

    for (int i = 0; i < T; i++) {
        if (i + 1 < T) { CPWAIT(1); } else { CPWAIT(0); }
        __syncthreads();
        if (i + 2 < T) G_ISSUE((i + 2) % 3, (i + 2) * 32);

        const unsigned* Ac = As + (i % 3) * GSTG;
        const unsigned* Bc = Bs + (i % 3) * GSTG;
        #pragma unroll
        for (int ks = 0; ks < 2; ks++) {
            const int pb = ks * 8;
            unsigned af[4][4], bf[8][2];
            #pragma unroll
            for (int mt = 0; mt < 4; mt++) {
                int r = (wm * 64 + mt * 16 + gid) * PADP;
                af[mt][0] = Ac[r + pb + tig];
                af[mt][1] = Ac[r + 8 * PADP + pb + tig];
                af[mt][2] = Ac[r + pb + tig + 4];
                af[mt][3] = Ac[r + 8 * PADP + pb + tig + 4];
            }
            #pragma unroll
            for (int nt = 0; nt < 8; nt++) {
                int r = (wn * 64 + nt * 8 + gid) * PADP;
                bf[nt][0] = Bc[r + pb + tig];
                bf[nt][1] = Bc[r + pb + tig + 4];
            }
            #pragma unroll
            for (int mt = 0; mt < 4; mt++)
                #pragma unroll
                for (int nt = 0; nt < 8; nt++)
                    mmaf16(acc[mt][nt], af[mt], bf[nt]);
        }
    }
    #undef G_ISSUE

    #pragma unroll
    for (int mt = 0; mt < 4; mt++) {
        #pragma unroll
        for (int nt = 0; nt < 8; nt++) {
            int n_ = n0 + wn * 64 + nt * 8 + 2 * tig;
            #pragma unroll
            for (int h = 0; h < 2; h++) {
                int m = m0 + wm * 64 + mt * 16 + gid + h * 8;
                float v0 = acc[mt][nt][h * 2 + 0];
                float v1 = acc[mt][nt][h * 2 + 1];
                if (mode == 3) {
                    int mat = n_ >> 10, dcol = n_ & 1023;
                    const float* bp = mat == 0 ? b1 : (mat == 1 ? b2 : b3);
                    v0 += bp[dcol]; v1 += bp[dcol + 1];
                    int b_ = m >> 10, s_ = m & 1023;
                    int h_ = dcol >> 6, hd = dcol & 63;
                    __half* Ch = (__half*)C;
                    if (mat < 2) {
                        __half* base = Ch + (size_t)mat * 16777216ull;
                        *(unsigned*)(base + ((((size_t)(b_ * 16 + h_)) << 10) + s_) * 64 + hd)
                            = f2h2(v0, v1);
                    } else {
                        __half* vb = Ch + 33554432ull;
                        size_t bhh = (size_t)(b_ * 16 + h_) * 64;
                        vb[(bhh + hd)     * 1024 + s_] = __float2half(v0);
                        vb[(bhh + hd + 1) * 1024 + s_] = __float2half(v1);
                    }
                } else if (mode == 1) {
                    v0 = fmaxf(v0 + b1[n_], 0.f);
                    v1 = fmaxf(v1 + b1[n_ + 1], 0.f);
                    *(unsigned*)((__half*)C + (size_t)m * N + n_) = f2h2(v0, v1);
                } else {
                    v0 += b1[n_]     + resid[(size_t)m * N + n_];
                    v1 += b1[n_ + 1] + resid[(size_t)m * N + n_ + 1];
                    *(float2*)((float*)C + (size_t)m * N + n_) = make_float2(v0, v1);
                }
            }
        }
    }
}

// ---------------------------------------------------------------------------
// qrel[bh,q,r] = Q[bh,q,:] . rel_k[r,:]   (Q fp16)
// ---------------------------------------------------------------------------
__global__ __launch_bounds__(256)
void qrel_kernel(const __half* __restrict__ Q, const float* __restrict__ relk,
                 float* __restrict__ out)
{
    __shared__ float rk[NREL * 65];
    __shared__ float qs[64 * 65];
    const int tid = threadIdx.x;
    const int row0 = blockIdx.x * 64;

    for (int i = tid; i < NREL * HD; i += 256) {
        int r = i >> 6, d = i & 63;
        rk[r * 65 + d] = relk[i];
    }
    #pragma unroll
    for (int p = 0; p < 8; p++) {
        int f = tid + p * 256;
        int r = f >> 5, c = f & 31;
        __half2 h = ((const __half2*)Q)[(size_t)(row0 + r) * 32 + c];
        float2 fv = __half22float2(h);
        qs[r * 65 + c * 2]     = fv.x;
        qs[r * 65 + c * 2 + 1] = fv.y;
    }
    __syncthreads();

    for (int i = tid; i < 64 * NREL; i += 256) {
        int q = i / NREL, r = i - q * NREL;
        float s = 0.f;
        #pragma unroll
        for (int d = 0; d < HD; d++)
            s = fmaf(qs[q * 65 + d], rk[r * 65 + d], s);
        out[(size_t)(row0 + q) * NREL + r] = s;
    }
}

// ---------------------------------------------------------------------------
// FUSED flash attention, fp16 mma, 3-buffer K/V ring (1 sync/tile).
// Q,K [bh][s][hd] fp16; V transposed [bh][hd][s] fp16. O fp16 [b][s][d].
// ---------------------------------------------------------------------------
#define TKF 64
#define NKT (SS / TKF)   // 16

__global__ __launch_bounds__(256, 2)
void flash_attn(const __half* __restrict__ Q, const __half* __restrict__ Kh,
                const __half* __restrict__ Vt, const float* __restrict__ qrel,
                const float* __restrict__ relv, __half* __restrict__ O)
{
    extern __shared__ __align__(16) unsigned fsm[];
    unsigned* Qs = fsm;                          // 128*36
    unsigned* Ks = Qs + 128 * FSTR;              // 3 x 64*36
    unsigned* Vs = Ks + 3 * FSTG;                // 3 x 64*36
    float* qr = (float*)(Vs + 3 * FSTG);         // 128*34
    float* bk = qr + 128 * 34;                   // 128*34

    const int tid = threadIdx.x, lane = tid & 31, warp = tid >> 5;
    const int gid = lane >> 2, tig = lane & 3;
    const int bh = blockIdx.y, q0 = blockIdx.x * 128;
    const __half* Qb = Q  + (size_t)bh * SS * HD;
    const __half* Kb = Kh + (size_t)bh * SS * HD;
    const __half* Vb = Vt + (size_t)bh * HD * SS;

    const int rl0 = warp * 16 + gid;
    const int qg0 = q0 + rl0;

    #define KV_ISSUE(s, k0) do {                                                \
        unsigned dk = su32(Ks + (s) * FSTG), dv = su32(Vs + (s) * FSTG);         \
        int r_ = tid >> 3, c_ = tid & 7;                                         \
        _Pragma("unroll")                                                        \
        for (int p_ = 0; p_ < 2; p_++) {                                         \
            int rr_ = r_ + p_ * 32;                                              \
            CP16(dk + (unsigned)((rr_ * FSTR + c_ * 4) * 4),                     \
                 Kb + (size_t)((k0) + rr_) * HD + c_ * 8);                       \
            CP16(dv + (unsigned)((rr_ * FSTR + c_ * 4) * 4),                     \
                 Vb + (size_t)rr_ * SS + (k0) + c_ * 8);                         \
        }                                                                        \
    } while (0)

    {
        unsigned dq = su32(Qs);
        int r = tid >> 3, c = tid & 7;
        #pragma unroll
        for (int p = 0; p < 4; p++) {
            int rr = r + p * 32;
            CP16(dq + (unsigned)((rr * FSTR + c * 4) * 4), Qb + (size_t)(q0 + rr) * HD + c * 8);
        }
        KV_ISSUE(0, 0);
        CPCOMMIT();
        KV_ISSUE(1, TKF);
        CPCOMMIT();
    }
    for (int i = tid; i < 128 * NREL; i += 256) {
        int r = i / NREL, c = i - r * NREL;
        qr[r * 34 + c] = qrel[((size_t)bh * SS + q0 + r) * NREL + c];
    }
    for (int i = tid; i < 128 * 34; i += 256) bk[i] = 0.f;

    float oacc[8][4];
    #pragma unroll
    for (int i = 0; i < 8; i++)
        #pragma unroll
        for (int t = 0; t < 4; t++) oacc[i][t] = 0.f;
    float m0 = -1e30f, m1 = -1e30f, l0 = 0.f, l1 = 0.f;

    for (int kt = 0; kt < NKT; kt++) {
        const int k0 = kt * TKF;
        if (kt + 1 < NKT) { CPWAIT(1); } else { CPWAIT(0); }
        __syncthreads();
        if (kt + 2 < NKT) { KV_ISSUE((kt + 2) % 3, (kt + 2) * TKF); CPCOMMIT(); }

        const unsigned* Kc = Ks + (kt % 3) * FSTG;
        const unsigned* Vc = Vs + (kt % 3) * FSTG;

        // --- S = Q @ K^T ---
        float sacc[8][4];
        #pragma unroll
        for (int i = 0; i < 8; i++)
            #pragma unroll
            for (int t = 0; t < 4; t++) sacc[i][t] = 0.f;

        #pragma unroll
        for (int ks = 0; ks < 4; ks++) {
            const int pb = ks * 8;
            unsigned af[4];
            af[0] = Qs[rl0 * FSTR + pb + tig];
            af[1] = Qs[(rl0 + 8) * FSTR + pb + tig];
            af[2] = Qs[rl0 * FSTR + pb + tig + 4];
            af[3] = Qs[(rl0 + 8) * FSTR + pb + tig + 4];
            #pragma unroll
            for (int nt = 0; nt < 8; nt++) {
                unsigned bf[2];
                int br = (nt * 8 + gid) * FSTR + pb;
                bf[0] = Kc[br + tig];
                bf[1] = Kc[br + tig + 4];
                mmaf16(sacc[nt], af, bf);
            }
        }

        // --- bias + scale + row max ---
        float mx0 = -1e30f, mx1 = -1e30f;
        #pragma unroll
        for (int nt = 0; nt < 8; nt++) {
            int kc = k0 + nt * 8 + 2 * tig;
            int d00 = kc - qg0;           d00 = d00 < -16 ? -16 : (d00 > 16 ? 16 : d00);
            int d01 = kc + 1 - qg0;       d01 = d01 < -16 ? -16 : (d01 > 16 ? 16 : d01);
            int d10 = kc - qg0 - 8;       d10 = d10 < -16 ? -16 : (d10 > 16 ? 16 : d10);
            int d11 = kc + 1 - qg0 - 8;   d11 = d11 < -16 ? -16 : (d11 > 16 ? 16 : d11);
            sacc[nt][0] = (sacc[nt][0] + qr[rl0 * 34 + d00 + 16]) * 0.125f;
            sacc[nt][1] = (sacc[nt][1] + qr[rl0 * 34 + d01 + 16]) * 0.125f;
            sacc[nt][2] = (sacc[nt][2] + qr[(rl0 + 8) * 34 + d10 + 16]) * 0.125f;
            sacc[nt][3] = (sacc[nt][3] + qr[(rl0 + 8) * 34 + d11 + 16]) * 0.125f;
            mx0 = fmaxf(mx0, fmaxf(sacc[nt][0], sacc[nt][1]));
            mx1 = fmaxf(mx1, fmaxf(sacc[nt][2], sacc[nt][3]));
        }
        mx0 = fmaxf(mx0, __shfl_xor_sync(0xffffffffu, mx0, 1));
        mx0 = fmaxf(mx0, __shfl_xor_sync(0xffffffffu, mx0, 2));
        mx1 = fmaxf(mx1, __shfl_xor_sync(0xffffffffu, mx1, 1));
        mx1 = fmaxf(mx1, __shfl_xor_sync(0xffffffffu, mx1, 2));

        float m0n = fmaxf(m0, mx0), m1n = fmaxf(m1, mx1);
        float corr0 = __expf(m0 - m0n), corr1 = __expf(m1 - m1n);
        m0 = m0n; m1 = m1n;

        float sum0 = 0.f, sum1 = 0.f;
        #pragma unroll
        for (int nt = 0; nt < 8; nt++) {
            float p0 = __expf(sacc[nt][0] - m0);
            float p1 = __expf(sacc[nt][1] - m0);
            float p2 = __expf(sacc[nt][2] - m1);
            float p3 = __expf(sacc[nt][3] - m1);
            sacc[nt][0] = p0; sacc[nt][1] = p1; sacc[nt][2] = p2; sacc[nt][3] = p3;
            sum0 += p0 + p1; sum1 += p2 + p3;
            oacc[nt][0] *= corr0; oacc[nt][1] *= corr0;
            oacc[nt][2] *= corr1; oacc[nt][3] *= corr1;
        }
        sum0 += __shfl_xor_sync(0xffffffffu, sum0, 1);
        sum0 += __shfl_xor_sync(0xffffffffu, sum0, 2);
        sum1 += __shfl_xor_sync(0xffffffffu, sum1, 1);
        sum1 += __shfl_xor_sync(0xffffffffu, sum1, 2);
        l0 = l0 * corr0 + sum0;
        l1 = l1 * corr1 + sum1;

        // --- buckets ---
        {
            int st = tig * 9, en = st + 9 > NREL ? NREL : st + 9;
            float* b0p = &bk[rl0 * 34];
            float* b1p = &bk[(rl0 + 8) * 34];
            for (int d = st; d < en; d++) { b0p[d] *= corr0; b1p[d] *= corr1; }
        }
        __syncwarp();
        {
            float ba0r0 = 0.f, ba32r0 = 0.f, ba0r1 = 0.f, ba32r1 = 0.f;
            #pragma unroll
            for (int nt = 0; nt < 8; nt++) {
                int kc = k0 + nt * 8 + 2 * tig;
                int d0 = kc - qg0, d1 = kc + 1 - qg0;
                int e0 = kc - qg0 - 8, e1 = kc + 1 - qg0 - 8;
                if (d0 <= -16) ba0r0 += sacc[nt][0];
                else if (d0 >= 16) ba32r0 += sacc[nt][0];
                else bk[rl0 * 34 + d0 + 16] += sacc[nt][0];
                if (d1 <= -16) ba0r0 += sacc[nt][1];
                else if (d1 >= 16) ba32r0 += sacc[nt][1];
                else bk[rl0 * 34 + d1 + 16] += sacc[nt][1];
                if (e0 <= -16) ba0r1 += sacc[nt][2];
                else if (e0 >= 16) ba32r1 += sacc[nt][2];
                else bk[(rl0 + 8) * 34 + e0 + 16] += sacc[nt][2];
                if (e1 <= -16) ba0r1 += sacc[nt][3];
                else if (e1 >= 16) ba32r1 += sacc[nt][3];
                else bk[(rl0 + 8) * 34 + e1 + 16] += sacc[nt][3];
            }
            ba0r0  += __shfl_xor_sync(0xffffffffu, ba0r0, 1);
            ba0r0  += __shfl_xor_sync(0xffffffffu, ba0r0, 2);
            ba32r0 += __shfl_xor_sync(0xffffffffu, ba32r0, 1);
            ba32r0 += __shfl_xor_sync(0xffffffffu, ba32r0, 2);
            ba0r1  += __shfl_xor_sync(0xffffffffu, ba0r1, 1);
            ba0r1  += __shfl_xor_sync(0xffffffffu, ba0r1, 2);
            ba32r1 += __shfl_xor_sync(0xffffffffu, ba32r1, 1);
            ba32r1 += __shfl_xor_sync(0xffffffffu, ba32r1, 2);
            if (tig == 0) {
                bk[rl0 * 34 + 0]        += ba0r0;
                bk[rl0 * 34 + 32]       += ba32r0;
                bk[(rl0 + 8) * 34 + 0]  += ba0r1;
                bk[(rl0 + 8) * 34 + 32] += ba32r1;
            }
        }

        // --- P @ V ---
        #pragma unroll
        for (int j = 0; j < 4; j++) {
            const int pb = j * 8;
            unsigned a[4];
            a[0] = f2h2(sacc[2 * j][0],     sacc[2 * j][1]);
            a[1] = f2h2(sacc[2 * j][2],     sacc[2 * j][3]);
            a[2] = f2h2(sacc[2 * j + 1][0], sacc[2 * j + 1][1]);
            a[3] = f2h2(sacc[2 * j + 1][2], sacc[2 * j + 1][3]);
            #pragma unroll
            for (int nt = 0; nt < 8; nt++) {
                unsigned bf[2];
                int br = (nt * 8 + gid) * FSTR + pb;
                bf[0] = Vc[br + tig];
                bf[1] = Vc[br + tig + 4];
                mmaf16(oacc[nt], a, bf);
            }
        }
    }
    #undef KV_ISSUE
    __syncthreads();

    // --- epilogue: + buckets @ rel_v, normalize, write fp16 ---
    float* rv = (float*)Ks;
    for (int i = tid; i < NREL * HD; i += 256) {
        int r = i >> 6, c = i & 63;
        rv[r * 68 + c] = relv[i];
    }
    __syncthreads();

    float inv0 = 1.f / l0, inv1 = 1.f / l1;

    #pragma unroll 1
    for (int r = 0; r < NREL; r++) {
        float br0 = bk[rl0 * 34 + r];
        float br1 = bk[(rl0 + 8) * 34 + r];
        #pragma unroll
        for (int nt = 0; nt < 8; nt++) {
            float r0 = rv[r * 68 + nt * 8 + 2 * tig];
            float r1 = rv[r * 68 + nt * 8 + 2 * tig + 1];
            oacc[nt][0] += br0 * r0; oacc[nt][1] += br0 * r1;
            oacc[nt][2] += br1 * r0; oacc[nt][3] += br1 * r1;
        }
    }

    const int b_ = bh >> 4, h_ = bh & 15;
    #pragma unroll
    for (int nt = 0; nt < 8; nt++) {
        int col = h_ * 64 + nt * 8 + 2 * tig;
        *(unsigned*)(O + ((size_t)b_ * SS + q0 + rl0) * DD + col)
            = f2h2(oacc[nt][0] * inv0, oacc[nt][1] * inv0);
        *(unsigned*)(O + ((size_t)b_ * SS + q0 + rl0 + 8) * DD + col)
            = f2h2(oacc[nt][2] * inv1, oacc[nt][3] * inv1);
    }
}

// ---------------------------------------------------------------------------
// LayerNorm; optionally writes fp16 copy
// ---------------------------------------------------------------------------
__global__ __launch_bounds__(256)
void ln_kernel(const float* __restrict__ X, const float* __restrict__ g,
               const float* __restrict__ bt, float* __restrict__ out,
               __half* __restrict__ outh)
{
    __shared__ float red[32];
    const int row = blockIdx.x;
    const int tid = threadIdx.x;
    const float* x = X + (size_t)row * DD;

    float4 v = *(const float4*)(x + tid * 4);
    float s  = v.x + v.y + v.z + v.w;
    float ss = v.x*v.x + v.y*v.y + v.z*v.z + v.w*v.w;
    s  = blockReduceSum256(s,  red);
    ss = blockReduceSum256(ss, red);
    const float mean = s * (1.f / DD);
    const float var  = ss * (1.f / DD) - mean * mean;
    const float rs   = rsqrtf(var + 1e-5f);

    float4 gg = *(const float4*)(g  + tid * 4);
    float4 bb = *(const float4*)(bt + tid * 4);
    float4 o;
    o.x = (v.x - mean) * rs * gg.x + bb.x;
    o.y = (v.y - mean) * rs * gg.y + bb.y;
    o.z = (v.z - mean) * rs * gg.z + bb.z;
    o.w = (v.w - mean) * rs * gg.w + bb.w;
    *(float4*)(out + (size_t)row * DD + tid * 4) = o;
    if (outh) {
        uint2 oh;
        oh.x = f2h2(o.x, o.y); oh.y = f2h2(o.z, o.w);
        *(uint2*)(outh + (size_t)row * DD + tid * 4) = oh;
    }
}

// ---------------------------------------------------------------------------
// kernel_launch
// ---------------------------------------------------------------------------
extern "C" void kernel_launch(void* const* d_in, const int* in_sizes, int n_in,
                              void* d_out, int out_size)
{
    const float* x     = (const float*)d_in[0];
    const float* wq    = (const float*)d_in[2];
    const float* bq    = (const float*)d_in[3];
    const float* wk    = (const float*)d_in[4];
    const float* bk_   = (const float*)d_in[5];
    const float* wv    = (const float*)d_in[6];
    const float* bv    = (const float*)d_in[7];
    const float* wo    = (const float*)d_in[8];
    const float* bo    = (const float*)d_in[9];
    const float* rel_k = (const float*)d_in[10];
    const float* rel_v = (const float*)d_in[11];
    const float* fc1_w = (const float*)d_in[12];
    const float* fc1_b = (const float*)d_in[13];
    const float* fc2_w = (const float*)d_in[14];
    const float* fc2_b = (const float*)d_in[15];
    const float* ln1_g = (const float*)d_in[16];
    const float* ln1_b = (const float*)d_in[17];
    const float* ln2_g = (const float*)d_in[18];
    const float* ln2_b = (const float*)d_in[19];

    float* scratch = nullptr;
    cudaGetSymbolAddress((void**)&scratch, g_scratch);
    __half* Qh   = (__half*)(scratch + OFF_Q);
    __half* Kh   = (__half*)(scratch + OFF_K);
    __half* Vth  = (__half*)(scratch + OFF_V);
    float*  qrel = scratch + OFF_QREL;
    __half* Oh   = (__half*)(scratch + OFF_O);
    float*  t1   = scratch + OFF_T1;
    float*  x1   = scratch + OFF_X1;
    __half* ffh  = (__half*)(scratch + OFF_FFH);
    float*  t2   = scratch + OFF_T2;
    __half* xth  = (__half*)(scratch + OFF_XT);
    __half* x1th = (__half*)(scratch + OFF_X1T);
    __half* wqkvt= (__half*)(scratch + OFF_WQT);
    __half* woth = (__half*)(scratch + OFF_WOT);
    __half* f1t  = (__half*)(scratch + OFF_F1T);
    __half* f2t  = (__half*)(scratch + OFF_F2T);

    const int M = BB * SS;
    const int FLASH_SMEM = (128 * FSTR + 6 * FSTG) * 4 + 128 * 34 * 4 * 2;

    cudaFuncSetAttribute(flash_attn, cudaFuncAttributeMaxDynamicSharedMemorySize, FLASH_SMEM);
    cudaFuncSetAttribute(gemm_f16, cudaFuncAttributeMaxDynamicSharedMemorySize, GEMM_SMEM);

    // operand prep
    cvt_h_kernel<<<(M * DD / 8 + 255) / 256, 256>>>(x, xth, M * DD);
    cvt_t_kernel<<<dim3(DD / 32, DD / 32), 256>>>(wq, wqkvt,           DD, DD);
    cvt_t_kernel<<<dim3(DD / 32, DD / 32), 256>>>(wk, wqkvt + 1048576, DD, DD);
    cvt_t_kernel<<<dim3(DD / 32, DD / 32), 256>>>(wv, wqkvt + 2097152, DD, DD);
    cvt_t_kernel<<<dim3(DD / 32, DD / 32), 256>>>(wo, woth,            DD, DD);
    cvt_t_kernel<<<dim3(DFF / 32, DD / 32), 256>>>(fc1_w, f1t, DD, DFF);
    cvt_t_kernel<<<dim3(DD / 32, DFF / 32), 256>>>(fc2_w, f2t, DFF, DD);

    // fused QKV (N = 3072, scatter; V transposed)
    gemm_f16<<<dim3(3 * DD / 128, M / 128), 128, GEMM_SMEM>>>(
        xth, wqkvt, bq, bk_, bv, nullptr, Qh, M, 3 * DD, DD, 3);

    qrel_kernel<<<BH * SS / 64, 256>>>(Qh, rel_k, qrel);

    dim3 gFA(SS / 128, BH);
    flash_attn<<<gFA, 256, FLASH_SMEM>>>(Qh, Kh, Vth, qrel, rel_v, Oh);

    gemm_f16<<<dim3(DD / 128, M / 128), 128, GEMM_SMEM>>>(
        Oh, woth, bo, nullptr, nullptr, x, t1, M, DD, DD, 2);
    ln_kernel<<<M, 256>>>(t1, ln1_g, ln1_b, x1, x1th);

    gemm_f16<<<dim3(DFF / 128, M / 128), 128, GEMM_SMEM>>>(
        x1th, f1t, fc1_b, nullptr, nullptr, nullptr, ffh, M, DFF, DD, 1);

    gemm_f16<<<dim3(DD / 128, M / 128), 128, GEMM_SMEM>>>(
        ffh, f2t, fc2_b, nullptr, nullptr, x1, t2, M, DD, DFF, 2);
    ln_kernel<<<M, 256>>>(t2, ln2_g, ln2_b, (float*)d_out, nullptr);
}

// round 10
// speedup vs baseline: 3.1487x; 1.1829x over previous
#include <cuda_runtime.h>
#include <cuda_fp16.h>
#include <math.h>
#include <stdint.h>

// ---------------------------------------------------------------------------
// Problem constants
// ---------------------------------------------------------------------------
#define BB 8
#define SS 1024
#define DD 1024
#define HH 16
#define HD 64
#define DFF 4096
#define BH 128
#define NREL 33

// ---------------------------------------------------------------------------
// Scratch (float units; fp16 regions reinterpreted)
// ---------------------------------------------------------------------------
#define OFF_Q     0ull
#define OFF_K     8388608ull
#define OFF_V     16777216ull
#define OFF_QREL  25165824ull
#define OFF_O     29491200ull
#define OFF_T1    37879808ull
#define OFF_X1    46268416ull
#define OFF_FFH   54657024ull
#define OFF_T2    88211456ull
#define OFF_XT    96600064ull
#define OFF_X1T   104988672ull
#define OFF_WQT   113377280ull
#define OFF_WOT   116523008ull
#define OFF_F1T   117571584ull
#define OFF_F2T   121765888ull
#define SCRATCH_TOTAL 125960192ull

__device__ float g_scratch[SCRATCH_TOTAL];

// ---------------------------------------------------------------------------
// helpers
// ---------------------------------------------------------------------------
__device__ __forceinline__ unsigned f2h2(float a, float b) {
    __half2 h = __floats2half2_rn(a, b);
    return *(unsigned*)&h;
}

__device__ __forceinline__ void mmaf16(float* c, const unsigned* a, const unsigned* b) {
    asm volatile(
        "mma.sync.aligned.m16n8k16.row.col.f32.f16.f16.f32 "
        "{%0,%1,%2,%3}, {%4,%5,%6,%7}, {%8,%9}, {%0,%1,%2,%3};"
        : "+f"(c[0]), "+f"(c[1]), "+f"(c[2]), "+f"(c[3])
        : "r"(a[0]), "r"(a[1]), "r"(a[2]), "r"(a[3]), "r"(b[0]), "r"(b[1]));
}

__device__ __forceinline__ void ldm_x4(unsigned* r, unsigned addr) {
    asm volatile("ldmatrix.sync.aligned.m8n8.x4.shared.b16 {%0,%1,%2,%3}, [%4];"
        : "=r"(r[0]), "=r"(r[1]), "=r"(r[2]), "=r"(r[3]) : "r"(addr));
}
__device__ __forceinline__ void ldm_x2(unsigned* r, unsigned addr) {
    asm volatile("ldmatrix.sync.aligned.m8n8.x2.shared.b16 {%0,%1}, [%2];"
        : "=r"(r[0]), "=r"(r[1]) : "r"(addr));
}

__device__ __forceinline__ unsigned su32(const void* p) {
    return (unsigned)__cvta_generic_to_shared(p);
}
#define CP16(dst, src) \
    asm volatile("cp.async.cg.shared.global [%0], [%1], 16;" :: "r"(dst), "l"(src) : "memory")
#define CPCOMMIT() asm volatile("cp.async.commit_group;" ::: "memory")
#define CPWAIT(n)  asm volatile("cp.async.wait_group %0;" :: "n"(n) : "memory")

#define PADP 20   // gemm pair stride
#define FSTR 36   // flash pair stride
#define GSTG 2560 // gemm stage size (u32): 128*PADP
#define FSTG 2304 // flash K/V stage size (u32): 64*FSTR

// ---------------------------------------------------------------------------
// Block reductions
// ---------------------------------------------------------------------------
__device__ __forceinline__ float blockReduceSum256(float v, float* sh) {
    #pragma unroll
    for (int o = 16; o; o >>= 1) v += __shfl_xor_sync(0xffffffffu, v, o);
    int warp = threadIdx.x >> 5, lane = threadIdx.x & 31;
    if (lane == 0) sh[warp] = v;
    __syncthreads();
    if (warp == 0) {
        v = (lane < 8) ? sh[lane] : 0.f;
        #pragma unroll
        for (int o = 4; o; o >>= 1) v += __shfl_xor_sync(0xffffffffu, v, o);
        if (lane == 0) sh[0] = v;
    }
    __syncthreads();
    float r = sh[0];
    __syncthreads();
    return r;
}

// ---------------------------------------------------------------------------
// fp32 -> fp16 elementwise
// ---------------------------------------------------------------------------
__global__ __launch_bounds__(256)
void cvt_h_kernel(const float* __restrict__ in, __half* __restrict__ out, int n)
{
    int i = (blockIdx.x * 256 + threadIdx.x) * 8;
    if (i < n) {
        float4 a = *(const float4*)(in + i);
        float4 b = *(const float4*)(in + i + 4);
        uint4 o;
        o.x = f2h2(a.x, a.y); o.y = f2h2(a.z, a.w);
        o.z = f2h2(b.x, b.y); o.w = f2h2(b.z, b.w);
        *(uint4*)(out + i) = o;
    }
}

// ---------------------------------------------------------------------------
// Transpose + fp16: in [K,N] fp32 -> out [N,K] fp16
// ---------------------------------------------------------------------------
__global__ __launch_bounds__(256)
void cvt_t_kernel(const float* __restrict__ in, __half* __restrict__ out, int K, int N)
{
    __shared__ float t[32][33];
    const int lx = threadIdx.x & 31, ly = threadIdx.x >> 5;
    const int n = blockIdx.x * 32 + lx, k0 = blockIdx.y * 32;
    #pragma unroll
    for (int p = 0; p < 32; p += 8)
        t[ly + p][lx] = in[(size_t)(k0 + ly + p) * N + n];
    __syncthreads();
    const int k = k0 + lx, n2 = blockIdx.x * 32;
    #pragma unroll
    for (int p = 0; p < 32; p += 8)
        out[(size_t)(n2 + ly + p) * K + k] = __float2half(t[lx][ly + p]);
}

// ---------------------------------------------------------------------------
// fp16 GEMM: C = A[M,K] @ Bt[N,K]^T. 3-stage cp.async ring, ldmatrix frags.
// 128 threads, 4 warps 2(M) x 2(N); warp tile 64x64.
//   mode 1: relu -> fp16   mode 2: +bias+resid -> fp32   mode 3: QKV scatter
// ---------------------------------------------------------------------------
#define GEMM_SMEM (6 * GSTG * 4)

__global__ __launch_bounds__(128, 2)
void gemm_f16(const __half* __restrict__ A, const __half* __restrict__ Bt,
              const float* __restrict__ b1, const float* __restrict__ b2,
              const float* __restrict__ b3, const float* __restrict__ resid,
              void* __restrict__ C, int M, int N, int K, int mode)
{
    extern __shared__ __align__(16) unsigned gsm[];
    unsigned* As = gsm;               // 3 stages x 2560
    unsigned* Bs = gsm + 3 * GSTG;    // 3 stages x 2560
    const int tid = threadIdx.x, lane = tid & 31, warp = tid >> 5;
    const int gid = lane >> 2, tig = lane & 3;
    const int l7 = lane & 7, l8 = (lane >> 3) & 1, l16 = (lane >> 4) & 1;
    const int m0 = blockIdx.y * 128, n0 = blockIdx.x * 128;
    const int wm = warp & 1, wn = warp >> 1;
    const int T = K >> 5;

    // lane-invariant ldmatrix offsets (u32 units)
    const int aoff = (wm * 64 + l7 + l8 * 8) * PADP + l16 * 4;
    const int boff = (wn * 64 + l7 + l16 * 8) * PADP + l8 * 4;

    #define G_ISSUE(s, k0) do {                                                 \
        unsigned da = su32(As + (s) * GSTG);                                     \
        unsigned db = su32(Bs + (s) * GSTG);                                     \
        _Pragma("unroll")                                                        \
        for (int p_ = 0; p_ < 4; p_++) {                                         \
            int f_ = tid + p_ * 128;                                             \
            int r_ = f_ >> 2, c_ = f_ & 3;                                       \
            CP16(da + (unsigned)((r_ * PADP + c_ * 4) * 4),                      \
                 A + (size_t)(m0 + r_) * K + (k0) + c_ * 8);                     \
            CP16(db + (unsigned)((r_ * PADP + c_ * 4) * 4),                      \
                 Bt + (size_t)(n0 + r_) * K + (k0) + c_ * 8);                    \
        }                                                                        \
        CPCOMMIT();                                                              \
    } while (0)

    float acc[4][8][4];
    #pragma unroll
    for (int i = 0; i < 4; i++)
        #pragma unroll
        for (int j = 0; j < 8; j++)
            #pragma unroll
            for (int t = 0; t < 4; t++) acc[i][j][t] = 0.f;

    G_ISSUE(0, 0);
    G_ISSUE(1, 32);

    for (int i = 0; i < T; i++) {
        if (i + 1 < T) { CPWAIT(1); } else { CPWAIT(0); }
        __syncthreads();
        if (i + 2 < T) G_ISSUE((i + 2) % 3, (i + 2) * 32);

        const unsigned abase = su32(As + (i % 3) * GSTG) + (unsigned)(aoff * 4);
        const unsigned bbase = su32(Bs + (i % 3) * GSTG) + (unsigned)(boff * 4);
        #pragma unroll
        for (int ks = 0; ks < 2; ks++) {
            const int pb = ks * 8;
            unsigned af[4][4], bfr[16];
            #pragma unroll
            for (int mt = 0; mt < 4; mt++)
                ldm_x4(af[mt], abase + (unsigned)((mt * 16 * PADP + pb) * 4));
            #pragma unroll
            for (int np = 0; np < 4; np++)
                ldm_x4(&bfr[np * 4], bbase + (unsigned)((np * 16 * PADP + pb) * 4));
            #pragma unroll
            for (int mt = 0; mt < 4; mt++)
                #pragma unroll
                for (int nt = 0; nt < 8; nt++)
                    mmaf16(acc[mt][nt], af[mt], &bfr[nt * 2]);
        }
    }
    #undef G_ISSUE

    #pragma unroll
    for (int mt = 0; mt < 4; mt++) {
        #pragma unroll
        for (int nt = 0; nt < 8; nt++) {
            int n_ = n0 + wn * 64 + nt * 8 + 2 * tig;
            #pragma unroll
            for (int h = 0; h < 2; h++) {
                int m = m0 + wm * 64 + mt * 16 + gid + h * 8;
                float v0 = acc[mt][nt][h * 2 + 0];
                float v1 = acc[mt][nt][h * 2 + 1];
                if (mode == 3) {
                    int mat = n_ >> 10, dcol = n_ & 1023;
                    const float* bp = mat == 0 ? b1 : (mat == 1 ? b2 : b3);
                    v0 += bp[dcol]; v1 += bp[dcol + 1];
                    int b_ = m >> 10, s_ = m & 1023;
                    int h_ = dcol >> 6, hd = dcol & 63;
                    __half* Ch = (__half*)C;
                    if (mat < 2) {
                        __half* base = Ch + (size_t)mat * 16777216ull;
                        *(unsigned*)(base + ((((size_t)(b_ * 16 + h_)) << 10) + s_) * 64 + hd)
                            = f2h2(v0, v1);
                    } else {
                        __half* vb = Ch + 33554432ull;
                        size_t bhh = (size_t)(b_ * 16 + h_) * 64;
                        vb[(bhh + hd)     * 1024 + s_] = __float2half(v0);
                        vb[(bhh + hd + 1) * 1024 + s_] = __float2half(v1);
                    }
                } else if (mode == 1) {
                    v0 = fmaxf(v0 + b1[n_], 0.f);
                    v1 = fmaxf(v1 + b1[n_ + 1], 0.f);
                    *(unsigned*)((__half*)C + (size_t)m * N + n_) = f2h2(v0, v1);
                } else {
                    v0 += b1[n_]     + resid[(size_t)m * N + n_];
                    v1 += b1[n_ + 1] + resid[(size_t)m * N + n_ + 1];
                    *(float2*)((float*)C + (size_t)m * N + n_) = make_float2(v0, v1);
                }
            }
        }
    }
}

// ---------------------------------------------------------------------------
// qrel[bh,q,r] = Q[bh,q,:] . rel_k[r,:]   (Q fp16)
// ---------------------------------------------------------------------------
__global__ __launch_bounds__(256)
void qrel_kernel(const __half* __restrict__ Q, const float* __restrict__ relk,
                 float* __restrict__ out)
{
    __shared__ float rk[NREL * 65];
    __shared__ float qs[64 * 65];
    const int tid = threadIdx.x;
    const int row0 = blockIdx.x * 64;

    for (int i = tid; i < NREL * HD; i += 256) {
        int r = i >> 6, d = i & 63;
        rk[r * 65 + d] = relk[i];
    }
    #pragma unroll
    for (int p = 0; p < 8; p++) {
        int f = tid + p * 256;
        int r = f >> 5, c = f & 31;
        __half2 h = ((const __half2*)Q)[(size_t)(row0 + r) * 32 + c];
        float2 fv = __half22float2(h);
        qs[r * 65 + c * 2]     = fv.x;
        qs[r * 65 + c * 2 + 1] = fv.y;
    }
    __syncthreads();

    for (int i = tid; i < 64 * NREL; i += 256) {
        int q = i / NREL, r = i - q * NREL;
        float s = 0.f;
        #pragma unroll
        for (int d = 0; d < HD; d++)
            s = fmaf(qs[q * 65 + d], rk[r * 65 + d], s);
        out[(size_t)(row0 + q) * NREL + r] = s;
    }
}

// ---------------------------------------------------------------------------
// FUSED flash attention, fp16 mma, 3-buffer K/V ring, ldmatrix frags,
// off-diagonal bucket fast path. O fp16 [b][s][d].
// ---------------------------------------------------------------------------
#define TKF 64
#define NKT (SS / TKF)   // 16

__global__ __launch_bounds__(256, 2)
void flash_attn(const __half* __restrict__ Q, const __half* __restrict__ Kh,
                const __half* __restrict__ Vt, const float* __restrict__ qrel,
                const float* __restrict__ relv, __half* __restrict__ O)
{
    extern __shared__ __align__(16) unsigned fsm[];
    unsigned* Qs = fsm;                          // 128*36
    unsigned* Ks = Qs + 128 * FSTR;              // 3 x 64*36
    unsigned* Vs = Ks + 3 * FSTG;                // 3 x 64*36
    float* qr = (float*)(Vs + 3 * FSTG);         // 128*34
    float* bk = qr + 128 * 34;                   // 128*34

    const int tid = threadIdx.x, lane = tid & 31, warp = tid >> 5;
    const int gid = lane >> 2, tig = lane & 3;
    const int l7 = lane & 7, l8 = (lane >> 3) & 1, l16 = (lane >> 4) & 1;
    const int bh = blockIdx.y, q0 = blockIdx.x * 128;
    const __half* Qb = Q  + (size_t)bh * SS * HD;
    const __half* Kb = Kh + (size_t)bh * SS * HD;
    const __half* Vb = Vt + (size_t)bh * HD * SS;

    const int rl0 = warp * 16 + gid;
    const int qg0 = q0 + rl0;

    // lane-invariant ldmatrix offsets (u32)
    const unsigned qoff = (unsigned)(((warp * 16 + l7 + l8 * 8) * FSTR + l16 * 4) * 4);
    const unsigned kvoff = (unsigned)((l7 * FSTR + l8 * 4) * 4);

    #define KV_ISSUE(s, k0) do {                                                \
        unsigned dk = su32(Ks + (s) * FSTG), dv = su32(Vs + (s) * FSTG);         \
        int r_ = tid >> 3, c_ = tid & 7;                                         \
        _Pragma("unroll")                                                        \
        for (int p_ = 0; p_ < 2; p_++) {                                         \
            int rr_ = r_ + p_ * 32;                                              \
            CP16(dk + (unsigned)((rr_ * FSTR + c_ * 4) * 4),                     \
                 Kb + (size_t)((k0) + rr_) * HD + c_ * 8);                       \
            CP16(dv + (unsigned)((rr_ * FSTR + c_ * 4) * 4),                     \
                 Vb + (size_t)rr_ * SS + (k0) + c_ * 8);                         \
        }                                                                        \
    } while (0)

    {
        unsigned dq = su32(Qs);
        int r = tid >> 3, c = tid & 7;
        #pragma unroll
        for (int p = 0; p < 4; p++) {
            int rr = r + p * 32;
            CP16(dq + (unsigned)((rr * FSTR + c * 4) * 4), Qb + (size_t)(q0 + rr) * HD + c * 8);
        }
        KV_ISSUE(0, 0);
        CPCOMMIT();
        KV_ISSUE(1, TKF);
        CPCOMMIT();
    }
    for (int i = tid; i < 128 * NREL; i += 256) {
        int r = i / NREL, c = i - r * NREL;
        qr[r * 34 + c] = qrel[((size_t)bh * SS + q0 + r) * NREL + c];
    }
    for (int i = tid; i < 128 * 34; i += 256) bk[i] = 0.f;

    float oacc[8][4];
    #pragma unroll
    for (int i = 0; i < 8; i++)
        #pragma unroll
        for (int t = 0; t < 4; t++) oacc[i][t] = 0.f;
    float m0 = -1e30f, m1 = -1e30f, l0 = 0.f, l1 = 0.f;

    for (int kt = 0; kt < NKT; kt++) {
        const int k0 = kt * TKF;
        if (kt + 1 < NKT) { CPWAIT(1); } else { CPWAIT(0); }
        __syncthreads();
        if (kt + 2 < NKT) { KV_ISSUE((kt + 2) % 3, (kt + 2) * TKF); CPCOMMIT(); }

        const unsigned kbase = su32(Ks + (kt % 3) * FSTG) + kvoff;
        const unsigned vbase = su32(Vs + (kt % 3) * FSTG) + kvoff;
        const unsigned qbase = su32(Qs) + qoff;

        // --- S = Q @ K^T ---
        float sacc[8][4];
        #pragma unroll
        for (int i = 0; i < 8; i++)
            #pragma unroll
            for (int t = 0; t < 4; t++) sacc[i][t] = 0.f;

        #pragma unroll
        for (int ks = 0; ks < 4; ks++) {
            const int pb = ks * 8;
            unsigned af[4];
            ldm_x4(af, qbase + (unsigned)(pb * 4));
            #pragma unroll
            for (int nt = 0; nt < 8; nt++) {
                unsigned bf[2];
                ldm_x2(bf, kbase + (unsigned)((nt * 8 * FSTR + pb) * 4));
                mmaf16(sacc[nt], af, bf);
            }
        }

        // --- bias + scale + row max ---
        float mx0 = -1e30f, mx1 = -1e30f;
        #pragma unroll
        for (int nt = 0; nt < 8; nt++) {
            int kc = k0 + nt * 8 + 2 * tig;
            int d00 = kc - qg0;           d00 = d00 < -16 ? -16 : (d00 > 16 ? 16 : d00);
            int d01 = kc + 1 - qg0;       d01 = d01 < -16 ? -16 : (d01 > 16 ? 16 : d01);
            int d10 = kc - qg0 - 8;       d10 = d10 < -16 ? -16 : (d10 > 16 ? 16 : d10);
            int d11 = kc + 1 - qg0 - 8;   d11 = d11 < -16 ? -16 : (d11 > 16 ? 16 : d11);
            sacc[nt][0] = (sacc[nt][0] + qr[rl0 * 34 + d00 + 16]) * 0.125f;
            sacc[nt][1] = (sacc[nt][1] + qr[rl0 * 34 + d01 + 16]) * 0.125f;
            sacc[nt][2] = (sacc[nt][2] + qr[(rl0 + 8) * 34 + d10 + 16]) * 0.125f;
            sacc[nt][3] = (sacc[nt][3] + qr[(rl0 + 8) * 34 + d11 + 16]) * 0.125f;
            mx0 = fmaxf(mx0, fmaxf(sacc[nt][0], sacc[nt][1]));
            mx1 = fmaxf(mx1, fmaxf(sacc[nt][2], sacc[nt][3]));
        }
        mx0 = fmaxf(mx0, __shfl_xor_sync(0xffffffffu, mx0, 1));
        mx0 = fmaxf(mx0, __shfl_xor_sync(0xffffffffu, mx0, 2));
        mx1 = fmaxf(mx1, __shfl_xor_sync(0xffffffffu, mx1, 1));
        mx1 = fmaxf(mx1, __shfl_xor_sync(0xffffffffu, mx1, 2));

        float m0n = fmaxf(m0, mx0), m1n = fmaxf(m1, mx1);
        float corr0 = __expf(m0 - m0n), corr1 = __expf(m1 - m1n);
        m0 = m0n; m1 = m1n;

        float sum0 = 0.f, sum1 = 0.f;
        #pragma unroll
        for (int nt = 0; nt < 8; nt++) {
            float p0 = __expf(sacc[nt][0] - m0);
            float p1 = __expf(sacc[nt][1] - m0);
            float p2 = __expf(sacc[nt][2] - m1);
            float p3 = __expf(sacc[nt][3] - m1);
            sacc[nt][0] = p0; sacc[nt][1] = p1; sacc[nt][2] = p2; sacc[nt][3] = p3;
            sum0 += p0 + p1; sum1 += p2 + p3;
            oacc[nt][0] *= corr0; oacc[nt][1] *= corr0;
            oacc[nt][2] *= corr1; oacc[nt][3] *= corr1;
        }
        sum0 += __shfl_xor_sync(0xffffffffu, sum0, 1);
        sum0 += __shfl_xor_sync(0xffffffffu, sum0, 2);
        sum1 += __shfl_xor_sync(0xffffffffu, sum1, 1);
        sum1 += __shfl_xor_sync(0xffffffffu, sum1, 2);
        l0 = l0 * corr0 + sum0;
        l1 = l1 * corr1 + sum1;

        // --- buckets: rescale (skip if corr==1), then fast/slow path add ---
        if (corr0 != 1.f || corr1 != 1.f) {
            int st = tig * 9, en = st + 9 > NREL ? NREL : st + 9;
            float* b0p = &bk[rl0 * 34];
            float* b1p = &bk[(rl0 + 8) * 34];
            for (int d = st; d < en; d++) { b0p[d] *= corr0; b1p[d] *= corr1; }
        }
        __syncwarp();
        if (k0 <= qg0 - 79) {
            // entire tile left of band for both rows
            if (tig == 0) {
                bk[rl0 * 34 + 0]       += sum0;
                bk[(rl0 + 8) * 34 + 0] += sum1;
            }
        } else if (k0 >= qg0 + 24) {
            // entire tile right of band for both rows
            if (tig == 0) {
                bk[rl0 * 34 + 32]       += sum0;
                bk[(rl0 + 8) * 34 + 32] += sum1;
            }
        } else {
            float ba0r0 = 0.f, ba32r0 = 0.f, ba0r1 = 0.f, ba32r1 = 0.f;
            #pragma unroll
            for (int nt = 0; nt < 8; nt++) {
                int kc = k0 + nt * 8 + 2 * tig;
                int d0 = kc - qg0, d1 = kc + 1 - qg0;
                int e0 = kc - qg0 - 8, e1 = kc + 1 - qg0 - 8;
                if (d0 <= -16) ba0r0 += sacc[nt][0];
                else if (d0 >= 16) ba32r0 += sacc[nt][0];
                else bk[rl0 * 34 + d0 + 16] += sacc[nt][0];
                if (d1 <= -16) ba0r0 += sacc[nt][1];
                else if (d1 >= 16) ba32r0 += sacc[nt][1];
                else bk[rl0 * 34 + d1 + 16] += sacc[nt][1];
                if (e0 <= -16) ba0r1 += sacc[nt][2];
                else if (e0 >= 16) ba32r1 += sacc[nt][2];
                else bk[(rl0 + 8) * 34 + e0 + 16] += sacc[nt][2];
                if (e1 <= -16) ba0r1 += sacc[nt][3];
                else if (e1 >= 16) ba32r1 += sacc[nt][3];
                else bk[(rl0 + 8) * 34 + e1 + 16] += sacc[nt][3];
            }
            ba0r0  += __shfl_xor_sync(0xffffffffu, ba0r0, 1);
            ba0r0  += __shfl_xor_sync(0xffffffffu, ba0r0, 2);
            ba32r0 += __shfl_xor_sync(0xffffffffu, ba32r0, 1);
            ba32r0 += __shfl_xor_sync(0xffffffffu, ba32r0, 2);
            ba0r1  += __shfl_xor_sync(0xffffffffu, ba0r1, 1);
            ba0r1  += __shfl_xor_sync(0xffffffffu, ba0r1, 2);
            ba32r1 += __shfl_xor_sync(0xffffffffu, ba32r1, 1);
            ba32r1 += __shfl_xor_sync(0xffffffffu, ba32r1, 2);
            if (tig == 0) {
                bk[rl0 * 34 + 0]        += ba0r0;
                bk[rl0 * 34 + 32]       += ba32r0;
                bk[(rl0 + 8) * 34 + 0]  += ba0r1;
                bk[(rl0 + 8) * 34 + 32] += ba32r1;
            }
        }

        // --- P @ V ---
        #pragma unroll
        for (int j = 0; j < 4; j++) {
            const int pb = j * 8;
            unsigned a[4];
            a[0] = f2h2(sacc[2 * j][0],     sacc[2 * j][1]);
            a[1] = f2h2(sacc[2 * j][2],     sacc[2 * j][3]);
            a[2] = f2h2(sacc[2 * j + 1][0], sacc[2 * j + 1][1]);
            a[3] = f2h2(sacc[2 * j + 1][2], sacc[2 * j + 1][3]);
            #pragma unroll
            for (int nt = 0; nt < 8; nt++) {
                unsigned bf[2];
                ldm_x2(bf, vbase + (unsigned)((nt * 8 * FSTR + pb) * 4));
                mmaf16(oacc[nt], a, bf);
            }
        }
    }
    #undef KV_ISSUE
    __syncthreads();

    // --- epilogue: + buckets @ rel_v, normalize, write fp16 ---
    float* rv = (float*)Ks;
    for (int i = tid; i < NREL * HD; i += 256) {
        int r = i >> 6, c = i & 63;
        rv[r * 68 + c] = relv[i];
    }
    __syncthreads();

    float inv0 = 1.f / l0, inv1 = 1.f / l1;

    #pragma unroll 1
    for (int r = 0; r < NREL; r++) {
        float br0 = bk[rl0 * 34 + r];
        float br1 = bk[(rl0 + 8) * 34 + r];
        #pragma unroll
        for (int nt = 0; nt < 8; nt++) {
            float r0 = rv[r * 68 + nt * 8 + 2 * tig];
            float r1 = rv[r * 68 + nt * 8 + 2 * tig + 1];
            oacc[nt][0] += br0 * r0; oacc[nt][1] += br0 * r1;
            oacc[nt][2] += br1 * r0; oacc[nt][3] += br1 * r1;
        }
    }

    const int b_ = bh >> 4, h_ = bh & 15;
    #pragma unroll
    for (int nt = 0; nt < 8; nt++) {
        int col = h_ * 64 + nt * 8 + 2 * tig;
        *(unsigned*)(O + ((size_t)b_ * SS + q0 + rl0) * DD + col)
            = f2h2(oacc[nt][0] * inv0, oacc[nt][1] * inv0);
        *(unsigned*)(O + ((size_t)b_ * SS + q0 + rl0 + 8) * DD + col)
            = f2h2(oacc[nt][2] * inv1, oacc[nt][3] * inv1);
    }
}

// ---------------------------------------------------------------------------
// LayerNorm; optionally writes fp16 copy
// ---------------------------------------------------------------------------
__global__ __launch_bounds__(256)
void ln_kernel(const float* __restrict__ X, const float* __restrict__ g,
               const float* __restrict__ bt, float* __restrict__ out,
               __half* __restrict__ outh)
{
    __shared__ float red[32];
    const int row = blockIdx.x;
    const int tid = threadIdx.x;
    const float* x = X + (size_t)row * DD;

    float4 v = *(const float4*)(x + tid * 4);
    float s  = v.x + v.y + v.z + v.w;
    float ss = v.x*v.x + v.y*v.y + v.z*v.z + v.w*v.w;
    s  = blockReduceSum256(s,  red);
    ss = blockReduceSum256(ss, red);
    const float mean = s * (1.f / DD);
    const float var  = ss * (1.f / DD) - mean * mean;
    const float rs   = rsqrtf(var + 1e-5f);

    float4 gg = *(const float4*)(g  + tid * 4);
    float4 bb = *(const float4*)(bt + tid * 4);
    float4 o;
    o.x = (v.x - mean) * rs * gg.x + bb.x;
    o.y = (v.y - mean) * rs * gg.y + bb.y;
    o.z = (v.z - mean) * rs * gg.z + bb.z;
    o.w = (v.w - mean) * rs * gg.w + bb.w;
    *(float4*)(out + (size_t)row * DD + tid * 4) = o;
    if (outh) {
        uint2 oh;
        oh.x = f2h2(o.x, o.y); oh.y = f2h2(o.z, o.w);
        *(uint2*)(outh + (size_t)row * DD + tid * 4) = oh;
    }
}

// ---------------------------------------------------------------------------
// kernel_launch
// ---------------------------------------------------------------------------
extern "C" void kernel_launch(void* const* d_in, const int* in_sizes, int n_in,
                              void* d_out, int out_size)
{
    const float* x     = (const float*)d_in[0];
    const float* wq    = (const float*)d_in[2];
    const float* bq    = (const float*)d_in[3];
    const float* wk    = (const float*)d_in[4];
    const float* bk_   = (const float*)d_in[5];
    const float* wv    = (const float*)d_in[6];
    const float* bv    = (const float*)d_in[7];
    const float* wo    = (const float*)d_in[8];
    const float* bo    = (const float*)d_in[9];
    const float* rel_k = (const float*)d_in[10];
    const float* rel_v = (const float*)d_in[11];
    const float* fc1_w = (const float*)d_in[12];
    const float* fc1_b = (const float*)d_in[13];
    const float* fc2_w = (const float*)d_in[14];
    const float* fc2_b = (const float*)d_in[15];
    const float* ln1_g = (const float*)d_in[16];
    const float* ln1_b = (const float*)d_in[17];
    const float* ln2_g = (const float*)d_in[18];
    const float* ln2_b = (const float*)d_in[19];

    float* scratch = nullptr;
    cudaGetSymbolAddress((void**)&scratch, g_scratch);
    __half* Qh   = (__half*)(scratch + OFF_Q);
    __half* Kh   = (__half*)(scratch + OFF_K);
    __half* Vth  = (__half*)(scratch + OFF_V);
    float*  qrel = scratch + OFF_QREL;
    __half* Oh   = (__half*)(scratch + OFF_O);
    float*  t1   = scratch + OFF_T1;
    float*  x1   = scratch + OFF_X1;
    __half* ffh  = (__half*)(scratch + OFF_FFH);
    float*  t2   = scratch + OFF_T2;
    __half* xth  = (__half*)(scratch + OFF_XT);
    __half* x1th = (__half*)(scratch + OFF_X1T);
    __half* wqkvt= (__half*)(scratch + OFF_WQT);
    __half* woth = (__half*)(scratch + OFF_WOT);
    __half* f1t  = (__half*)(scratch + OFF_F1T);
    __half* f2t  = (__half*)(scratch + OFF_F2T);

    const int M = BB * SS;
    const int FLASH_SMEM = (128 * FSTR + 6 * FSTG) * 4 + 128 * 34 * 4 * 2;

    cudaFuncSetAttribute(flash_attn, cudaFuncAttributeMaxDynamicSharedMemorySize, FLASH_SMEM);
    cudaFuncSetAttribute(gemm_f16, cudaFuncAttributeMaxDynamicSharedMemorySize, GEMM_SMEM);

    // operand prep
    cvt_h_kernel<<<(M * DD / 8 + 255) / 256, 256>>>(x, xth, M * DD);
    cvt_t_kernel<<<dim3(DD / 32, DD / 32), 256>>>(wq, wqkvt,           DD, DD);
    cvt_t_kernel<<<dim3(DD / 32, DD / 32), 256>>>(wk, wqkvt + 1048576, DD, DD);
    cvt_t_kernel<<<dim3(DD / 32, DD / 32), 256>>>(wv, wqkvt + 2097152, DD, DD);
    cvt_t_kernel<<<dim3(DD / 32, DD / 32), 256>>>(wo, woth,            DD, DD);
    cvt_t_kernel<<<dim3(DFF / 32, DD / 32), 256>>>(fc1_w, f1t, DD, DFF);
    cvt_t_kernel<<<dim3(DD / 32, DFF / 32), 256>>>(fc2_w, f2t, DFF, DD);

    // fused QKV (N = 3072, scatter; V transposed)
    gemm_f16<<<dim3(3 * DD / 128, M / 128), 128, GEMM_SMEM>>>(
        xth, wqkvt, bq, bk_, bv, nullptr, Qh, M, 3 * DD, DD, 3);

    qrel_kernel<<<BH * SS / 64, 256>>>(Qh, rel_k, qrel);

    dim3 gFA(SS / 128, BH);
    flash_attn<<<gFA, 256, FLASH_SMEM>>>(Qh, Kh, Vth, qrel, rel_v, Oh);

    gemm_f16<<<dim3(DD / 128, M / 128), 128, GEMM_SMEM>>>(
        Oh, woth, bo, nullptr, nullptr, x, t1, M, DD, DD, 2);
    ln_kernel<<<M, 256>>>(t1, ln1_g, ln1_b, x1, x1th);

    gemm_f16<<<dim3(DFF / 128, M / 128), 128, GEMM_SMEM>>>(
        x1th, f1t, fc1_b, nullptr, nullptr, nullptr, ffh, M, DFF, DD, 1);

    gemm_f16<<<dim3(DD / 128, M / 128), 128, GEMM_SMEM>>>(
        ffh, f2t, fc2_b, nullptr, nullptr, x1, t2, M, DD, DFF, 2);
    ln_kernel<<<M, 256>>>(t2, ln2_g, ln2_b, (float*)d_out, nullptr);
}